// round 1
// baseline (speedup 1.0000x reference)
#include <cuda_runtime.h>
#include <cuda_bf16.h>

// Problem constants
#define BATCH 2
#define SEQ   2048
#define DMODEL 768
#define NHEAD 12
#define DHEAD 64
#define HID   1536
#define ROWS  (BATCH * SEQ)          // 4096
#define QKVN  (3 * DMODEL)           // 2304
#define EPS   1e-6f

// ---------------- scratch (no allocs allowed; __device__ globals) ----------------
__device__ float g_h  [ROWS * DMODEL];   // rmsnorm output (reused)
__device__ float g_qkv[ROWS * QKVN];     // qkv
__device__ float g_ctx[ROWS * DMODEL];   // attention context
__device__ float g_x1 [ROWS * DMODEL];   // post-attention residual
__device__ float g_fc1[ROWS * HID];      // relu(fc1)

// ---------------- RMSNorm: one block per row, D=768, 256 threads ----------------
__global__ __launch_bounds__(256) void rmsnorm_kernel(
    const float* __restrict__ x, const float* __restrict__ w, float* __restrict__ out)
{
    const int row = blockIdx.x;
    const int tid = threadIdx.x;
    const float* xr = x + (size_t)row * DMODEL;
    float v0 = xr[tid], v1 = xr[tid + 256], v2 = xr[tid + 512];
    float s = v0 * v0 + v1 * v1 + v2 * v2;

    // warp reduce
    #pragma unroll
    for (int o = 16; o > 0; o >>= 1) s += __shfl_xor_sync(0xFFFFFFFF, s, o);
    __shared__ float wsum[8];
    if ((tid & 31) == 0) wsum[tid >> 5] = s;
    __syncthreads();
    if (tid < 8) {
        float t = wsum[tid];
        #pragma unroll
        for (int o = 4; o > 0; o >>= 1) t += __shfl_xor_sync(0xFF, t, o);
        if (tid == 0) wsum[0] = t;
    }
    __syncthreads();
    const float scale = rsqrtf(wsum[0] * (1.0f / DMODEL) + EPS);

    float* orow = out + (size_t)row * DMODEL;
    orow[tid]       = v0 * scale * w[tid];
    orow[tid + 256] = v1 * scale * w[tid + 256];
    orow[tid + 512] = v2 * scale * w[tid + 512];
}

// ---------------- GEMM: C[M,N] = A[M,K] @ W[K,N] + bias (+relu) (+resid) ----------
// BM=BN=64, BK=32, 16x16 threads, 4x4 micro-tile. All dims divide evenly here.
__global__ __launch_bounds__(256) void gemm64_kernel(
    const float* __restrict__ A, const float* __restrict__ W,
    const float* __restrict__ bias, const float* __restrict__ resid,
    float* __restrict__ C, int M, int N, int K, int do_relu)
{
    __shared__ float As[64][33];   // [m][k], padded to kill 2-way conflicts
    __shared__ float Bs[32][64];   // [k][n]

    const int tx = threadIdx.x, ty = threadIdx.y;
    const int tid = ty * 16 + tx;
    const int m0 = blockIdx.y * 64, n0 = blockIdx.x * 64;

    float acc[4][4] = {};

    for (int k0 = 0; k0 < K; k0 += 32) {
        // load A tile 64x32 (coalesced over k)
        #pragma unroll
        for (int i = 0; i < 8; i++) {
            int idx = tid + i * 256;
            int m = idx >> 5, k = idx & 31;
            As[m][k] = A[(size_t)(m0 + m) * K + k0 + k];
        }
        // load B tile 32x64 (coalesced over n)
        #pragma unroll
        for (int i = 0; i < 8; i++) {
            int idx = tid + i * 256;
            int k = idx >> 6, n = idx & 63;
            Bs[k][n] = W[(size_t)(k0 + k) * N + n0 + n];
        }
        __syncthreads();
        #pragma unroll
        for (int k = 0; k < 32; k++) {
            float a[4], b[4];
            #pragma unroll
            for (int i = 0; i < 4; i++) a[i] = As[ty * 4 + i][k];
            float4 bv = *(const float4*)&Bs[k][tx * 4];
            b[0] = bv.x; b[1] = bv.y; b[2] = bv.z; b[3] = bv.w;
            #pragma unroll
            for (int i = 0; i < 4; i++)
                #pragma unroll
                for (int j = 0; j < 4; j++)
                    acc[i][j] = fmaf(a[i], b[j], acc[i][j]);
        }
        __syncthreads();
    }

    #pragma unroll
    for (int i = 0; i < 4; i++) {
        int m = m0 + ty * 4 + i;
        #pragma unroll
        for (int j = 0; j < 4; j++) {
            int n = n0 + tx * 4 + j;
            float v = acc[i][j] + bias[n];
            if (do_relu) v = fmaxf(v, 0.0f);
            if (resid) v += resid[(size_t)m * N + n];
            C[(size_t)m * N + n] = v;
        }
    }
}

// ---------------- Fused squared-ReLU attention ----------------
// ctx[b,q,h,:] = sum_k relu(q·k / 8)^2 * v[k]   (no softmax -> pure streaming)
// Block: 64 queries of one (b,h). Loop over keys in chunks of 32.
__global__ __launch_bounds__(256) void attn_kernel(
    const float* __restrict__ qkv, float* __restrict__ ctx)
{
    __shared__ float Qs[64][65];
    __shared__ float Ks[32][65];
    __shared__ float Vs[32][65];
    __shared__ float Ss[64][33];

    const int tx = threadIdx.x, ty = threadIdx.y;
    const int tid = ty * 16 + tx;
    const int bh = blockIdx.y;
    const int b = bh / NHEAD, h = bh % NHEAD;
    const int q0 = blockIdx.x * 64;

    const float* base = qkv + (size_t)b * SEQ * QKVN;
    const int hcol = h * DHEAD;

    // load Q tile [64 x 64]
    #pragma unroll
    for (int i = 0; i < 16; i++) {
        int idx = tid + i * 256;
        int m = idx >> 6, d = idx & 63;
        Qs[m][d] = base[(size_t)(q0 + m) * QKVN + hcol + d];
    }

    float acc[4][4] = {};

    for (int k0 = 0; k0 < SEQ; k0 += 32) {
        __syncthreads();   // protect Ks/Vs/Ss reuse (also orders Q load on iter 0)
        #pragma unroll
        for (int i = 0; i < 8; i++) {
            int idx = tid + i * 256;
            int r = idx >> 6, d = idx & 63;
            size_t rowoff = (size_t)(k0 + r) * QKVN + hcol + d;
            Ks[r][d] = base[rowoff + DMODEL];
            Vs[r][d] = base[rowoff + 2 * DMODEL];
        }
        __syncthreads();

        // scores: each thread does 4 q-rows x 2 k-cols
        float s[4][2] = {};
        #pragma unroll
        for (int d = 0; d < 64; d++) {
            float qv[4], kv[2];
            #pragma unroll
            for (int i = 0; i < 4; i++) qv[i] = Qs[ty * 4 + i][d];
            #pragma unroll
            for (int j = 0; j < 2; j++) kv[j] = Ks[tx * 2 + j][d];
            #pragma unroll
            for (int i = 0; i < 4; i++)
                #pragma unroll
                for (int j = 0; j < 2; j++)
                    s[i][j] = fmaf(qv[i], kv[j], s[i][j]);
        }
        #pragma unroll
        for (int i = 0; i < 4; i++)
            #pragma unroll
            for (int j = 0; j < 2; j++) {
                float p = fmaxf(s[i][j] * 0.125f, 0.0f);
                Ss[ty * 4 + i][tx * 2 + j] = p * p;
            }
        __syncthreads();

        // acc += Ss[64x32] @ Vs[32x64]; thread does 4 q-rows x 4 dh-cols
        #pragma unroll
        for (int kk = 0; kk < 32; kk++) {
            float sv[4], vv[4];
            #pragma unroll
            for (int i = 0; i < 4; i++) sv[i] = Ss[ty * 4 + i][kk];
            #pragma unroll
            for (int j = 0; j < 4; j++) vv[j] = Vs[kk][tx * 4 + j];
            #pragma unroll
            for (int i = 0; i < 4; i++)
                #pragma unroll
                for (int j = 0; j < 4; j++)
                    acc[i][j] = fmaf(sv[i], vv[j], acc[i][j]);
        }
    }

    // write ctx in [b, s, h, dh] layout == [b, s, d]
    #pragma unroll
    for (int i = 0; i < 4; i++) {
        int q = q0 + ty * 4 + i;
        #pragma unroll
        for (int j = 0; j < 4; j++) {
            ctx[((size_t)b * SEQ + q) * DMODEL + hcol + tx * 4 + j] = acc[i][j];
        }
    }
}

// ---------------- launch ----------------
extern "C" void kernel_launch(void* const* d_in, const int* in_sizes, int n_in,
                              void* d_out, int out_size)
{
    const float* x      = (const float*)d_in[0];
    const float* ln1_w  = (const float*)d_in[1];
    const float* W_attn = (const float*)d_in[2];
    const float* b_attn = (const float*)d_in[3];
    const float* W_proj = (const float*)d_in[4];
    const float* b_proj = (const float*)d_in[5];
    const float* ln2_w  = (const float*)d_in[6];
    const float* W_fc1  = (const float*)d_in[7];
    const float* b_fc1  = (const float*)d_in[8];
    const float* W_fc2  = (const float*)d_in[9];
    const float* b_fc2  = (const float*)d_in[10];
    float* out = (float*)d_out;

    float *h, *qkv, *ctx, *x1, *fc1;
    cudaGetSymbolAddress((void**)&h,   g_h);
    cudaGetSymbolAddress((void**)&qkv, g_qkv);
    cudaGetSymbolAddress((void**)&ctx, g_ctx);
    cudaGetSymbolAddress((void**)&x1,  g_x1);
    cudaGetSymbolAddress((void**)&fc1, g_fc1);

    dim3 tb(16, 16);

    // h = rmsnorm(x, ln1_w)
    rmsnorm_kernel<<<ROWS, 256>>>(x, ln1_w, h);
    // qkv = h @ W_attn + b_attn
    gemm64_kernel<<<dim3(QKVN / 64, ROWS / 64), tb>>>(h, W_attn, b_attn, nullptr, qkv,
                                                      ROWS, QKVN, DMODEL, 0);
    // ctx = squared-relu attention
    attn_kernel<<<dim3(SEQ / 64, BATCH * NHEAD), tb>>>(qkv, ctx);
    // x1 = x + ctx @ W_proj + b_proj
    gemm64_kernel<<<dim3(DMODEL / 64, ROWS / 64), tb>>>(ctx, W_proj, b_proj, x, x1,
                                                        ROWS, DMODEL, DMODEL, 0);
    // h = rmsnorm(x1, ln2_w)
    rmsnorm_kernel<<<ROWS, 256>>>(x1, ln2_w, h);
    // fc1 = relu(h @ W_fc1 + b_fc1)
    gemm64_kernel<<<dim3(HID / 64, ROWS / 64), tb>>>(h, W_fc1, b_fc1, nullptr, fc1,
                                                     ROWS, HID, DMODEL, 1);
    // out = x1 + fc1 @ W_fc2 + b_fc2
    gemm64_kernel<<<dim3(DMODEL / 64, ROWS / 64), tb>>>(fc1, W_fc2, b_fc2, x1, out,
                                                        ROWS, DMODEL, HID, 0);
}

// round 4
// speedup vs baseline: 1.3882x; 1.3882x over previous
#include <cuda_runtime.h>
#include <cuda_bf16.h>
#include <cstdint>

// Problem constants
#define BATCH 2
#define SEQ   2048
#define DMODEL 768
#define NHEAD 12
#define DHEAD 64
#define HID   1536
#define ROWS  (BATCH * SEQ)          // 4096
#define QKVN  (3 * DMODEL)           // 2304
#define EPS   1e-6f

// ---------------- scratch (__device__ globals; no allocs allowed) ----------------
__device__ float g_h  [ROWS * DMODEL];
__device__ float g_qkv[ROWS * QKVN];
__device__ float g_ctx[ROWS * DMODEL];
__device__ float g_x1 [ROWS * DMODEL];
__device__ float g_fc1[ROWS * HID];

// ================= warp-MMA helpers (sm_100, no 'a' features) =================
__device__ __forceinline__ uint32_t sptr(const void* p) {
    return (uint32_t)__cvta_generic_to_shared(p);
}
__device__ __forceinline__ void ldsm_x4(uint32_t addr, uint32_t* r) {
    asm volatile("ldmatrix.sync.aligned.m8n8.x4.shared.b16 {%0,%1,%2,%3}, [%4];"
                 : "=r"(r[0]), "=r"(r[1]), "=r"(r[2]), "=r"(r[3]) : "r"(addr));
}
__device__ __forceinline__ void ldsm_x2t(uint32_t addr, uint32_t* r) {
    asm volatile("ldmatrix.sync.aligned.m8n8.x2.trans.shared.b16 {%0,%1}, [%2];"
                 : "=r"(r[0]), "=r"(r[1]) : "r"(addr));
}
__device__ __forceinline__ void mma_bf16(float* c, const uint32_t* a, const uint32_t* b) {
    asm volatile(
        "mma.sync.aligned.m16n8k16.row.col.f32.bf16.bf16.f32 "
        "{%0,%1,%2,%3}, {%4,%5,%6,%7}, {%8,%9}, {%0,%1,%2,%3};"
        : "+f"(c[0]), "+f"(c[1]), "+f"(c[2]), "+f"(c[3])
        : "r"(a[0]), "r"(a[1]), "r"(a[2]), "r"(a[3]), "r"(b[0]), "r"(b[1]));
}
__device__ __forceinline__ uint32_t pack_bf2(__nv_bfloat16 a, __nv_bfloat16 b) {
    return ((uint32_t)__bfloat16_as_ushort(b) << 16) | (uint32_t)__bfloat16_as_ushort(a);
}
// split float4 into hi/lo bf16 packs
__device__ __forceinline__ void split4(float4 v, uint2& h, uint2& l) {
    __nv_bfloat16 hx = __float2bfloat16_rn(v.x), hy = __float2bfloat16_rn(v.y);
    __nv_bfloat16 hz = __float2bfloat16_rn(v.z), hw = __float2bfloat16_rn(v.w);
    __nv_bfloat16 lx = __float2bfloat16_rn(v.x - __bfloat162float(hx));
    __nv_bfloat16 ly = __float2bfloat16_rn(v.y - __bfloat162float(hy));
    __nv_bfloat16 lz = __float2bfloat16_rn(v.z - __bfloat162float(hz));
    __nv_bfloat16 lw = __float2bfloat16_rn(v.w - __bfloat162float(hw));
    h = make_uint2(pack_bf2(hx, hy), pack_bf2(hz, hw));
    l = make_uint2(pack_bf2(lx, ly), pack_bf2(lz, lw));
}

// ================= RMSNorm =================
__global__ __launch_bounds__(256) void rmsnorm_kernel(
    const float* __restrict__ x, const float* __restrict__ w, float* __restrict__ out)
{
    const int row = blockIdx.x;
    const int tid = threadIdx.x;
    const float* xr = x + (size_t)row * DMODEL;
    float v0 = xr[tid], v1 = xr[tid + 256], v2 = xr[tid + 512];
    float s = v0 * v0 + v1 * v1 + v2 * v2;
    #pragma unroll
    for (int o = 16; o > 0; o >>= 1) s += __shfl_xor_sync(0xFFFFFFFF, s, o);
    __shared__ float wsum[8];
    if ((tid & 31) == 0) wsum[tid >> 5] = s;
    __syncthreads();
    if (tid < 8) {
        float t = wsum[tid];
        #pragma unroll
        for (int o = 4; o > 0; o >>= 1) t += __shfl_xor_sync(0xFF, t, o);
        if (tid == 0) wsum[0] = t;
    }
    __syncthreads();
    const float scale = rsqrtf(wsum[0] * (1.0f / DMODEL) + EPS);
    float* orow = out + (size_t)row * DMODEL;
    orow[tid]       = v0 * scale * w[tid];
    orow[tid + 256] = v1 * scale * w[tid + 256];
    orow[tid + 512] = v2 * scale * w[tid + 512];
}

// ================= tensor-core GEMM (mma.sync bf16 hi/lo) =================
// C[M,N] = A[M,K] @ W[K,N] + bias (+relu) (+resid)
// CTA 128x128, BK=32, 8 warps (2x4), warp tile 64x32.
#define BM 128
#define BN 128
#define BK 32
#define STA 40    // A smem row stride (bf16 elems): conflict-free ldmatrix phases
#define STB 136   // B smem row stride

__global__ __launch_bounds__(256) void gemm_mma_kernel(
    const float* __restrict__ A, const float* __restrict__ W,
    const float* __restrict__ bias, const float* __restrict__ resid,
    float* __restrict__ C, int M, int N, int K, int do_relu)
{
    __shared__ __nv_bfloat16 Ah[BM * STA];
    __shared__ __nv_bfloat16 Al[BM * STA];
    __shared__ __nv_bfloat16 Bh[BK * STB];
    __shared__ __nv_bfloat16 Bl[BK * STB];

    const int tid = threadIdx.x, wid = tid >> 5, lane = tid & 31;
    const int warp_m = wid >> 2, warp_n = wid & 3;   // 2 x 4
    const int m0 = blockIdx.y * BM, n0 = blockIdx.x * BN;

    float acc[4][4][4];
    #pragma unroll
    for (int i = 0; i < 4; i++)
        #pragma unroll
        for (int j = 0; j < 4; j++)
            #pragma unroll
            for (int r = 0; r < 4; r++) acc[i][j][r] = 0.f;

    // per-thread load slots: 4 float4 for A tile, 4 for B tile
    float4 av[4], bv[4];

    const int ntiles = K / BK;

    // prefetch tile 0
    {
        const int k0 = 0;
        #pragma unroll
        for (int i = 0; i < 4; i++) {
            int idx = tid + i * 256;                 // [0,1024)
            int m = idx >> 3, kq = idx & 7;
            av[i] = *(const float4*)(A + (size_t)(m0 + m) * K + k0 + kq * 4);
        }
        #pragma unroll
        for (int i = 0; i < 4; i++) {
            int idx = tid + i * 256;
            int kk = idx >> 5, nq = idx & 31;
            bv[i] = *(const float4*)(W + (size_t)(k0 + kk) * N + n0 + nq * 4);
        }
    }

    for (int t = 0; t < ntiles; t++) {
        __syncthreads();   // previous iteration's MMAs done with smem
        // store + convert current regs -> smem
        #pragma unroll
        for (int i = 0; i < 4; i++) {
            int idx = tid + i * 256;
            int m = idx >> 3, kq = idx & 7;
            uint2 h, l; split4(av[i], h, l);
            *(uint2*)(Ah + m * STA + kq * 4) = h;
            *(uint2*)(Al + m * STA + kq * 4) = l;
        }
        #pragma unroll
        for (int i = 0; i < 4; i++) {
            int idx = tid + i * 256;
            int kk = idx >> 5, nq = idx & 31;
            uint2 h, l; split4(bv[i], h, l);
            *(uint2*)(Bh + kk * STB + nq * 4) = h;
            *(uint2*)(Bl + kk * STB + nq * 4) = l;
        }
        __syncthreads();

        // prefetch next tile (LDGs overlap the MMAs below)
        if (t + 1 < ntiles) {
            const int k0 = (t + 1) * BK;
            #pragma unroll
            for (int i = 0; i < 4; i++) {
                int idx = tid + i * 256;
                int m = idx >> 3, kq = idx & 7;
                av[i] = *(const float4*)(A + (size_t)(m0 + m) * K + k0 + kq * 4);
            }
            #pragma unroll
            for (int i = 0; i < 4; i++) {
                int idx = tid + i * 256;
                int kk = idx >> 5, nq = idx & 31;
                bv[i] = *(const float4*)(W + (size_t)(k0 + kk) * N + n0 + nq * 4);
            }
        }

        // MMA over the k-tile: two k16 sub-steps
        #pragma unroll
        for (int ks = 0; ks < 2; ks++) {
            const int kof = ks * 16;
            uint32_t ah[4][4], al[4][4], bh[4][2], bl[4][2];
            #pragma unroll
            for (int mt = 0; mt < 4; mt++) {
                int row = warp_m * 64 + mt * 16 + (lane & 15);
                int col = kof + ((lane >> 4) << 3);
                uint32_t off = (uint32_t)(row * STA + col) * 2;
                ldsm_x4(sptr(Ah) + off, ah[mt]);
                ldsm_x4(sptr(Al) + off, al[mt]);
            }
            #pragma unroll
            for (int nt = 0; nt < 4; nt++) {
                int krow = kof + (lane & 15);
                int col = warp_n * 32 + nt * 8;
                uint32_t off = (uint32_t)(krow * STB + col) * 2;
                ldsm_x2t(sptr(Bh) + off, bh[nt]);
                ldsm_x2t(sptr(Bl) + off, bl[nt]);
            }
            #pragma unroll
            for (int mt = 0; mt < 4; mt++)
                #pragma unroll
                for (int nt = 0; nt < 4; nt++) {
                    mma_bf16(acc[mt][nt], ah[mt], bh[nt]);
                    mma_bf16(acc[mt][nt], ah[mt], bl[nt]);
                    mma_bf16(acc[mt][nt], al[mt], bh[nt]);
                }
        }
    }

    // ---- epilogue: c fragment rows l/4 (+8), cols (l%4)*2 (+1) ----
    #pragma unroll
    for (int mt = 0; mt < 4; mt++) {
        int r0 = m0 + warp_m * 64 + mt * 16 + (lane >> 2);
        #pragma unroll
        for (int nt = 0; nt < 4; nt++) {
            int c0 = n0 + warp_n * 32 + nt * 8 + (lane & 3) * 2;
            float b0 = bias[c0], b1 = bias[c0 + 1];
            float v0 = acc[mt][nt][0] + b0, v1 = acc[mt][nt][1] + b1;
            float v2 = acc[mt][nt][2] + b0, v3 = acc[mt][nt][3] + b1;
            if (do_relu) {
                v0 = fmaxf(v0, 0.f); v1 = fmaxf(v1, 0.f);
                v2 = fmaxf(v2, 0.f); v3 = fmaxf(v3, 0.f);
            }
            if (resid) {
                const float* rr0 = resid + (size_t)r0 * N + c0;
                const float* rr1 = resid + (size_t)(r0 + 8) * N + c0;
                v0 += rr0[0]; v1 += rr0[1];
                v2 += rr1[0]; v3 += rr1[1];
            }
            *(float2*)(C + (size_t)r0 * N + c0)       = make_float2(v0, v1);
            *(float2*)(C + (size_t)(r0 + 8) * N + c0) = make_float2(v2, v3);
        }
    }
}

// ================= Fused squared-ReLU attention (unchanged) =================
__global__ __launch_bounds__(256) void attn_kernel(
    const float* __restrict__ qkv, float* __restrict__ ctx)
{
    __shared__ float Qs[64][65];
    __shared__ float Ks[32][65];
    __shared__ float Vs[32][65];
    __shared__ float Ss[64][33];

    const int tx = threadIdx.x, ty = threadIdx.y;
    const int tid = ty * 16 + tx;
    const int bh = blockIdx.y;
    const int b = bh / NHEAD, h = bh % NHEAD;
    const int q0 = blockIdx.x * 64;

    const float* base = qkv + (size_t)b * SEQ * QKVN;
    const int hcol = h * DHEAD;

    #pragma unroll
    for (int i = 0; i < 16; i++) {
        int idx = tid + i * 256;
        int m = idx >> 6, d = idx & 63;
        Qs[m][d] = base[(size_t)(q0 + m) * QKVN + hcol + d];
    }

    float acc[4][4] = {};

    for (int k0 = 0; k0 < SEQ; k0 += 32) {
        __syncthreads();
        #pragma unroll
        for (int i = 0; i < 8; i++) {
            int idx = tid + i * 256;
            int r = idx >> 6, d = idx & 63;
            size_t rowoff = (size_t)(k0 + r) * QKVN + hcol + d;
            Ks[r][d] = base[rowoff + DMODEL];
            Vs[r][d] = base[rowoff + 2 * DMODEL];
        }
        __syncthreads();

        float s[4][2] = {};
        #pragma unroll
        for (int d = 0; d < 64; d++) {
            float qv[4], kv[2];
            #pragma unroll
            for (int i = 0; i < 4; i++) qv[i] = Qs[ty * 4 + i][d];
            #pragma unroll
            for (int j = 0; j < 2; j++) kv[j] = Ks[tx * 2 + j][d];
            #pragma unroll
            for (int i = 0; i < 4; i++)
                #pragma unroll
                for (int j = 0; j < 2; j++)
                    s[i][j] = fmaf(qv[i], kv[j], s[i][j]);
        }
        #pragma unroll
        for (int i = 0; i < 4; i++)
            #pragma unroll
            for (int j = 0; j < 2; j++) {
                float p = fmaxf(s[i][j] * 0.125f, 0.0f);
                Ss[ty * 4 + i][tx * 2 + j] = p * p;
            }
        __syncthreads();

        #pragma unroll
        for (int kk = 0; kk < 32; kk++) {
            float sv[4], vv[4];
            #pragma unroll
            for (int i = 0; i < 4; i++) sv[i] = Ss[ty * 4 + i][kk];
            #pragma unroll
            for (int j = 0; j < 4; j++) vv[j] = Vs[kk][tx * 4 + j];
            #pragma unroll
            for (int i = 0; i < 4; i++)
                #pragma unroll
                for (int j = 0; j < 4; j++)
                    acc[i][j] = fmaf(sv[i], vv[j], acc[i][j]);
        }
    }

    #pragma unroll
    for (int i = 0; i < 4; i++) {
        int q = q0 + ty * 4 + i;
        #pragma unroll
        for (int j = 0; j < 4; j++) {
            ctx[((size_t)b * SEQ + q) * DMODEL + hcol + tx * 4 + j] = acc[i][j];
        }
    }
}

// ================= launch =================
extern "C" void kernel_launch(void* const* d_in, const int* in_sizes, int n_in,
                              void* d_out, int out_size)
{
    const float* x      = (const float*)d_in[0];
    const float* ln1_w  = (const float*)d_in[1];
    const float* W_attn = (const float*)d_in[2];
    const float* b_attn = (const float*)d_in[3];
    const float* W_proj = (const float*)d_in[4];
    const float* b_proj = (const float*)d_in[5];
    const float* ln2_w  = (const float*)d_in[6];
    const float* W_fc1  = (const float*)d_in[7];
    const float* b_fc1  = (const float*)d_in[8];
    const float* W_fc2  = (const float*)d_in[9];
    const float* b_fc2  = (const float*)d_in[10];
    float* out = (float*)d_out;

    float *h, *qkv, *ctx, *x1, *fc1;
    cudaGetSymbolAddress((void**)&h,   g_h);
    cudaGetSymbolAddress((void**)&qkv, g_qkv);
    cudaGetSymbolAddress((void**)&ctx, g_ctx);
    cudaGetSymbolAddress((void**)&x1,  g_x1);
    cudaGetSymbolAddress((void**)&fc1, g_fc1);

    // h = rmsnorm(x, ln1_w)
    rmsnorm_kernel<<<ROWS, 256>>>(x, ln1_w, h);
    // qkv = h @ W_attn + b_attn
    gemm_mma_kernel<<<dim3(QKVN / BN, ROWS / BM), 256>>>(
        h, W_attn, b_attn, nullptr, qkv, ROWS, QKVN, DMODEL, 0);
    // ctx = squared-relu attention
    attn_kernel<<<dim3(SEQ / 64, BATCH * NHEAD), dim3(16, 16)>>>(qkv, ctx);
    // x1 = x + ctx @ W_proj + b_proj
    gemm_mma_kernel<<<dim3(DMODEL / BN, ROWS / BM), 256>>>(
        ctx, W_proj, b_proj, x, x1, ROWS, DMODEL, DMODEL, 0);
    // h = rmsnorm(x1, ln2_w)
    rmsnorm_kernel<<<ROWS, 256>>>(x1, ln2_w, h);
    // fc1 = relu(h @ W_fc1 + b_fc1)
    gemm_mma_kernel<<<dim3(HID / BN, ROWS / BM), 256>>>(
        h, W_fc1, b_fc1, nullptr, fc1, ROWS, HID, DMODEL, 1);
    // out = x1 + fc1 @ W_fc2 + b_fc2
    gemm_mma_kernel<<<dim3(DMODEL / BN, ROWS / BM), 256>>>(
        fc1, W_fc2, b_fc2, x1, out, ROWS, DMODEL, HID, 0);
}

// round 5
// speedup vs baseline: 2.3638x; 1.7028x over previous
#include <cuda_runtime.h>
#include <cuda_bf16.h>
#include <cstdint>

// Problem constants
#define BATCH 2
#define SEQ   2048
#define DMODEL 768
#define NHEAD 12
#define DHEAD 64
#define HID   1536
#define ROWS  (BATCH * SEQ)          // 4096
#define QKVN  (3 * DMODEL)           // 2304
#define EPS   1e-6f

// ---------------- scratch (__device__ globals; no allocs allowed) ----------------
__device__ float g_h  [ROWS * DMODEL];
__device__ float g_qkv[ROWS * QKVN];
__device__ float g_ctx[ROWS * DMODEL];
__device__ float g_x1 [ROWS * DMODEL];
__device__ float g_fc1[ROWS * HID];

// ================= warp-MMA helpers (sm_100, no 'a' features) =================
__device__ __forceinline__ uint32_t sptr(const void* p) {
    return (uint32_t)__cvta_generic_to_shared(p);
}
__device__ __forceinline__ void ldsm_x4(uint32_t addr, uint32_t* r) {
    asm volatile("ldmatrix.sync.aligned.m8n8.x4.shared.b16 {%0,%1,%2,%3}, [%4];"
                 : "=r"(r[0]), "=r"(r[1]), "=r"(r[2]), "=r"(r[3]) : "r"(addr));
}
__device__ __forceinline__ void ldsm_x4t(uint32_t addr, uint32_t* r) {
    asm volatile("ldmatrix.sync.aligned.m8n8.x4.trans.shared.b16 {%0,%1,%2,%3}, [%4];"
                 : "=r"(r[0]), "=r"(r[1]), "=r"(r[2]), "=r"(r[3]) : "r"(addr));
}
__device__ __forceinline__ void ldsm_x2t(uint32_t addr, uint32_t* r) {
    asm volatile("ldmatrix.sync.aligned.m8n8.x2.trans.shared.b16 {%0,%1}, [%2];"
                 : "=r"(r[0]), "=r"(r[1]) : "r"(addr));
}
__device__ __forceinline__ void mma_bf16(float* c, const uint32_t* a, const uint32_t* b) {
    asm volatile(
        "mma.sync.aligned.m16n8k16.row.col.f32.bf16.bf16.f32 "
        "{%0,%1,%2,%3}, {%4,%5,%6,%7}, {%8,%9}, {%0,%1,%2,%3};"
        : "+f"(c[0]), "+f"(c[1]), "+f"(c[2]), "+f"(c[3])
        : "r"(a[0]), "r"(a[1]), "r"(a[2]), "r"(a[3]), "r"(b[0]), "r"(b[1]));
}
__device__ __forceinline__ uint32_t pack_bf2(__nv_bfloat16 a, __nv_bfloat16 b) {
    return ((uint32_t)__bfloat16_as_ushort(b) << 16) | (uint32_t)__bfloat16_as_ushort(a);
}
__device__ __forceinline__ void split4(float4 v, uint2& h, uint2& l) {
    __nv_bfloat16 hx = __float2bfloat16_rn(v.x), hy = __float2bfloat16_rn(v.y);
    __nv_bfloat16 hz = __float2bfloat16_rn(v.z), hw = __float2bfloat16_rn(v.w);
    __nv_bfloat16 lx = __float2bfloat16_rn(v.x - __bfloat162float(hx));
    __nv_bfloat16 ly = __float2bfloat16_rn(v.y - __bfloat162float(hy));
    __nv_bfloat16 lz = __float2bfloat16_rn(v.z - __bfloat162float(hz));
    __nv_bfloat16 lw = __float2bfloat16_rn(v.w - __bfloat162float(hw));
    h = make_uint2(pack_bf2(hx, hy), pack_bf2(hz, hw));
    l = make_uint2(pack_bf2(lx, ly), pack_bf2(lz, lw));
}
// split a single fp32 into hi/lo bf16
__device__ __forceinline__ void split1(float v, __nv_bfloat16& h, __nv_bfloat16& l) {
    h = __float2bfloat16_rn(v);
    l = __float2bfloat16_rn(v - __bfloat162float(h));
}

// ================= RMSNorm =================
__global__ __launch_bounds__(256) void rmsnorm_kernel(
    const float* __restrict__ x, const float* __restrict__ w, float* __restrict__ out)
{
    const int row = blockIdx.x;
    const int tid = threadIdx.x;
    const float* xr = x + (size_t)row * DMODEL;
    float v0 = xr[tid], v1 = xr[tid + 256], v2 = xr[tid + 512];
    float s = v0 * v0 + v1 * v1 + v2 * v2;
    #pragma unroll
    for (int o = 16; o > 0; o >>= 1) s += __shfl_xor_sync(0xFFFFFFFF, s, o);
    __shared__ float wsum[8];
    if ((tid & 31) == 0) wsum[tid >> 5] = s;
    __syncthreads();
    if (tid < 8) {
        float t = wsum[tid];
        #pragma unroll
        for (int o = 4; o > 0; o >>= 1) t += __shfl_xor_sync(0xFF, t, o);
        if (tid == 0) wsum[0] = t;
    }
    __syncthreads();
    const float scale = rsqrtf(wsum[0] * (1.0f / DMODEL) + EPS);
    float* orow = out + (size_t)row * DMODEL;
    orow[tid]       = v0 * scale * w[tid];
    orow[tid + 256] = v1 * scale * w[tid + 256];
    orow[tid + 512] = v2 * scale * w[tid + 512];
}

// ================= tensor-core GEMM (mma.sync bf16 hi/lo) =================
#define BM 128
#define BN 128
#define BK 32
#define STA 40
#define STB 136

__global__ __launch_bounds__(256) void gemm_mma_kernel(
    const float* __restrict__ A, const float* __restrict__ W,
    const float* __restrict__ bias, const float* __restrict__ resid,
    float* __restrict__ C, int M, int N, int K, int do_relu)
{
    __shared__ __nv_bfloat16 Ah[BM * STA];
    __shared__ __nv_bfloat16 Al[BM * STA];
    __shared__ __nv_bfloat16 Bh[BK * STB];
    __shared__ __nv_bfloat16 Bl[BK * STB];

    const int tid = threadIdx.x, wid = tid >> 5, lane = tid & 31;
    const int warp_m = wid >> 2, warp_n = wid & 3;
    const int m0 = blockIdx.y * BM, n0 = blockIdx.x * BN;

    float acc[4][4][4];
    #pragma unroll
    for (int i = 0; i < 4; i++)
        #pragma unroll
        for (int j = 0; j < 4; j++)
            #pragma unroll
            for (int r = 0; r < 4; r++) acc[i][j][r] = 0.f;

    float4 av[4], bv[4];
    const int ntiles = K / BK;

    {
        #pragma unroll
        for (int i = 0; i < 4; i++) {
            int idx = tid + i * 256;
            int m = idx >> 3, kq = idx & 7;
            av[i] = *(const float4*)(A + (size_t)(m0 + m) * K + kq * 4);
        }
        #pragma unroll
        for (int i = 0; i < 4; i++) {
            int idx = tid + i * 256;
            int kk = idx >> 5, nq = idx & 31;
            bv[i] = *(const float4*)(W + (size_t)kk * N + n0 + nq * 4);
        }
    }

    for (int t = 0; t < ntiles; t++) {
        __syncthreads();
        #pragma unroll
        for (int i = 0; i < 4; i++) {
            int idx = tid + i * 256;
            int m = idx >> 3, kq = idx & 7;
            uint2 h, l; split4(av[i], h, l);
            *(uint2*)(Ah + m * STA + kq * 4) = h;
            *(uint2*)(Al + m * STA + kq * 4) = l;
        }
        #pragma unroll
        for (int i = 0; i < 4; i++) {
            int idx = tid + i * 256;
            int kk = idx >> 5, nq = idx & 31;
            uint2 h, l; split4(bv[i], h, l);
            *(uint2*)(Bh + kk * STB + nq * 4) = h;
            *(uint2*)(Bl + kk * STB + nq * 4) = l;
        }
        __syncthreads();

        if (t + 1 < ntiles) {
            const int k0 = (t + 1) * BK;
            #pragma unroll
            for (int i = 0; i < 4; i++) {
                int idx = tid + i * 256;
                int m = idx >> 3, kq = idx & 7;
                av[i] = *(const float4*)(A + (size_t)(m0 + m) * K + k0 + kq * 4);
            }
            #pragma unroll
            for (int i = 0; i < 4; i++) {
                int idx = tid + i * 256;
                int kk = idx >> 5, nq = idx & 31;
                bv[i] = *(const float4*)(W + (size_t)(k0 + kk) * N + n0 + nq * 4);
            }
        }

        #pragma unroll
        for (int ks = 0; ks < 2; ks++) {
            const int kof = ks * 16;
            uint32_t ah[4][4], al[4][4], bh[4][2], bl[4][2];
            #pragma unroll
            for (int mt = 0; mt < 4; mt++) {
                int row = warp_m * 64 + mt * 16 + (lane & 15);
                int col = kof + ((lane >> 4) << 3);
                uint32_t off = (uint32_t)(row * STA + col) * 2;
                ldsm_x4(sptr(Ah) + off, ah[mt]);
                ldsm_x4(sptr(Al) + off, al[mt]);
            }
            #pragma unroll
            for (int nt = 0; nt < 4; nt++) {
                int krow = kof + (lane & 15);
                int col = warp_n * 32 + nt * 8;
                uint32_t off = (uint32_t)(krow * STB + col) * 2;
                ldsm_x2t(sptr(Bh) + off, bh[nt]);
                ldsm_x2t(sptr(Bl) + off, bl[nt]);
            }
            #pragma unroll
            for (int mt = 0; mt < 4; mt++)
                #pragma unroll
                for (int nt = 0; nt < 4; nt++) {
                    mma_bf16(acc[mt][nt], ah[mt], bh[nt]);
                    mma_bf16(acc[mt][nt], ah[mt], bl[nt]);
                    mma_bf16(acc[mt][nt], al[mt], bh[nt]);
                }
        }
    }

    #pragma unroll
    for (int mt = 0; mt < 4; mt++) {
        int r0 = m0 + warp_m * 64 + mt * 16 + (lane >> 2);
        #pragma unroll
        for (int nt = 0; nt < 4; nt++) {
            int c0 = n0 + warp_n * 32 + nt * 8 + (lane & 3) * 2;
            float b0 = bias[c0], b1 = bias[c0 + 1];
            float v0 = acc[mt][nt][0] + b0, v1 = acc[mt][nt][1] + b1;
            float v2 = acc[mt][nt][2] + b0, v3 = acc[mt][nt][3] + b1;
            if (do_relu) {
                v0 = fmaxf(v0, 0.f); v1 = fmaxf(v1, 0.f);
                v2 = fmaxf(v2, 0.f); v3 = fmaxf(v3, 0.f);
            }
            if (resid) {
                const float* rr0 = resid + (size_t)r0 * N + c0;
                const float* rr1 = resid + (size_t)(r0 + 8) * N + c0;
                v0 += rr0[0]; v1 += rr0[1];
                v2 += rr1[0]; v3 += rr1[1];
            }
            *(float2*)(C + (size_t)r0 * N + c0)       = make_float2(v0, v1);
            *(float2*)(C + (size_t)(r0 + 8) * N + c0) = make_float2(v2, v3);
        }
    }
}

// ================= tensor-core squared-ReLU attention =================
// Block: 128 queries x one (b,h). 8 warps, each owns 16 q-rows.
// K tile = 64 keys. Q (hi/lo) resident in smem; K/V (hi/lo) streamed per tile.
// S = Q K^T via mma (3 hi/lo passes); P = relu(S)^2/64 in fp32, repacked in
// registers into A-fragments; ctx += P V via mma (3 passes).
#define AQ  128
#define AKT 64
#define AST 72    // smem row stride in bf16 (144B rows -> conflict-free ldmatrix)

// dynamic smem offsets (bytes)
#define AO_QH 0
#define AO_QL (AO_QH + AQ * AST * 2)      // 18432
#define AO_KH (AO_QL + AQ * AST * 2)      // 36864
#define AO_KL (AO_KH + AKT * AST * 2)     // 46080
#define AO_VH (AO_KL + AKT * AST * 2)     // 55296
#define AO_VL (AO_VH + AKT * AST * 2)     // 64512
#define ATTN_SMEM (AO_VL + AKT * AST * 2) // 73728

__global__ __launch_bounds__(256) void attn_mma_kernel(
    const float* __restrict__ qkv, float* __restrict__ ctx)
{
    extern __shared__ char asm_buf[];
    __nv_bfloat16* Qh = (__nv_bfloat16*)(asm_buf + AO_QH);
    __nv_bfloat16* Ql = (__nv_bfloat16*)(asm_buf + AO_QL);
    __nv_bfloat16* Kh = (__nv_bfloat16*)(asm_buf + AO_KH);
    __nv_bfloat16* Kl = (__nv_bfloat16*)(asm_buf + AO_KL);
    __nv_bfloat16* Vh = (__nv_bfloat16*)(asm_buf + AO_VH);
    __nv_bfloat16* Vl = (__nv_bfloat16*)(asm_buf + AO_VL);

    const int tid = threadIdx.x, wid = tid >> 5, lane = tid & 31;
    const int bh = blockIdx.y;
    const int b = bh / NHEAD, h = bh % NHEAD;
    const int q0 = blockIdx.x * AQ;
    const float* base = qkv + (size_t)b * SEQ * QKVN;
    const int hcol = h * DHEAD;

    // ---- load Q tile [128 x 64] hi/lo ----
    #pragma unroll
    for (int i = 0; i < 8; i++) {
        int idx = tid + i * 256;             // 2048 float4 slots
        int m = idx >> 4, dq = idx & 15;
        float4 v = *(const float4*)(base + (size_t)(q0 + m) * QKVN + hcol + dq * 4);
        uint2 hh, ll; split4(v, hh, ll);
        *(uint2*)(Qh + m * AST + dq * 4) = hh;
        *(uint2*)(Ql + m * AST + dq * 4) = ll;
    }

    float out_acc[8][4];
    #pragma unroll
    for (int nt = 0; nt < 8; nt++)
        #pragma unroll
        for (int r = 0; r < 4; r++) out_acc[nt][r] = 0.f;

    const uint32_t qh_b = sptr(Qh), ql_b = sptr(Ql);
    const uint32_t kh_b = sptr(Kh), kl_b = sptr(Kl);
    const uint32_t vh_b = sptr(Vh), vl_b = sptr(Vl);

    for (int k0 = 0; k0 < SEQ; k0 += AKT) {
        __syncthreads();
        // ---- load K,V tile [64 x 64] hi/lo ----
        #pragma unroll
        for (int i = 0; i < 4; i++) {
            int idx = tid + i * 256;         // 1024 slots for K
            int r = idx >> 4, dq = idx & 15;
            float4 v = *(const float4*)(base + (size_t)(k0 + r) * QKVN + DMODEL + hcol + dq * 4);
            uint2 hh, ll; split4(v, hh, ll);
            *(uint2*)(Kh + r * AST + dq * 4) = hh;
            *(uint2*)(Kl + r * AST + dq * 4) = ll;
        }
        #pragma unroll
        for (int i = 0; i < 4; i++) {
            int idx = tid + i * 256;         // 1024 slots for V
            int r = idx >> 4, dq = idx & 15;
            float4 v = *(const float4*)(base + (size_t)(k0 + r) * QKVN + 2 * DMODEL + hcol + dq * 4);
            uint2 hh, ll; split4(v, hh, ll);
            *(uint2*)(Vh + r * AST + dq * 4) = hh;
            *(uint2*)(Vl + r * AST + dq * 4) = ll;
        }
        __syncthreads();

        // ---- scores: S[16 x 64] per warp ----
        float s_acc[8][4];
        #pragma unroll
        for (int nt = 0; nt < 8; nt++)
            #pragma unroll
            for (int r = 0; r < 4; r++) s_acc[nt][r] = 0.f;

        #pragma unroll
        for (int ks = 0; ks < 4; ks++) {     // d = 64 -> 4 k16 steps
            const int kof = ks * 16;
            uint32_t ah[4], al[4];
            {
                int row = wid * 16 + (lane & 15);
                int col = kof + ((lane >> 4) << 3);
                uint32_t off = (uint32_t)(row * AST + col) * 2;
                ldsm_x4(qh_b + off, ah);
                ldsm_x4(ql_b + off, al);
            }
            #pragma unroll
            for (int ntp = 0; ntp < 4; ntp++) {   // 16 key-rows per x4
                int n = ntp * 16 + (lane & 15);
                int col = kof + ((lane >> 4) << 3);
                uint32_t off = (uint32_t)(n * AST + col) * 2;
                uint32_t kb_h[4], kb_l[4];
                ldsm_x4(kh_b + off, kb_h);        // r0,r1: n0-7/n8-15 @ k0-7; r2,r3: @ k8-15
                ldsm_x4(kl_b + off, kb_l);
                uint32_t b0h[2] = {kb_h[0], kb_h[2]}, b1h[2] = {kb_h[1], kb_h[3]};
                uint32_t b0l[2] = {kb_l[0], kb_l[2]}, b1l[2] = {kb_l[1], kb_l[3]};
                mma_bf16(s_acc[2 * ntp],     ah, b0h);
                mma_bf16(s_acc[2 * ntp],     ah, b0l);
                mma_bf16(s_acc[2 * ntp],     al, b0h);
                mma_bf16(s_acc[2 * ntp + 1], ah, b1h);
                mma_bf16(s_acc[2 * ntp + 1], ah, b1l);
                mma_bf16(s_acc[2 * ntp + 1], al, b1h);
            }
        }

        // ---- P = relu(s)^2 / 64, repack in registers into A-fragments ----
        // a-frag[kt2]: a0=pack(c0,c1) tile(2kt2), a1=pack(c2,c3) tile(2kt2),
        //              a2=pack(c0,c1) tile(2kt2+1), a3=pack(c2,c3) tile(2kt2+1)
        uint32_t pa_h[4][4], pa_l[4][4];
        #pragma unroll
        for (int nt = 0; nt < 8; nt++) {
            float p[4];
            #pragma unroll
            for (int r = 0; r < 4; r++) {
                float t = fmaxf(s_acc[nt][r], 0.f);
                p[r] = t * t * 0.015625f;     // (t/8)^2
            }
            __nv_bfloat16 h0, l0, h1, l1, h2, l2, h3, l3;
            split1(p[0], h0, l0); split1(p[1], h1, l1);
            split1(p[2], h2, l2); split1(p[3], h3, l3);
            int kt2 = nt >> 1;
            int base_r = (nt & 1) ? 2 : 0;
            pa_h[kt2][base_r]     = pack_bf2(h0, h1);
            pa_h[kt2][base_r + 1] = pack_bf2(h2, h3);
            pa_l[kt2][base_r]     = pack_bf2(l0, l1);
            pa_l[kt2][base_r + 1] = pack_bf2(l2, l3);
        }

        // ---- ctx += P V ----
        #pragma unroll
        for (int kt2 = 0; kt2 < 4; kt2++) {   // kpos 16 each
            #pragma unroll
            for (int nb = 0; nb < 2; nb++) {  // dh: two x4t loads cover 32 cols each
                int krow = kt2 * 16 + (lane & 15);
                int col = nb * 32 + ((lane >> 4) << 4);  // lanes 16-31 -> col+16? no: +8
                // x4t: lanes 0-15 col base, lanes 16-31 col base+8
                col = nb * 32 + ((lane >> 4) << 3);
                uint32_t off = (uint32_t)(krow * AST + col) * 2;
                uint32_t vb_h[4], vb_l[4];
                ldsm_x4t(vh_b + off, vb_h);   // r0,r1 -> tile col base; r2,r3 -> +8
                ldsm_x4t(vl_b + off, vb_l);
                int nt = nb * 4;              // tiles of 8 cols: nb*32/8
                uint32_t b0h[2] = {vb_h[0], vb_h[1]}, b1h[2] = {vb_h[2], vb_h[3]};
                uint32_t b0l[2] = {vb_l[0], vb_l[1]}, b1l[2] = {vb_l[2], vb_l[3]};
                mma_bf16(out_acc[nt],     pa_h[kt2], b0h);
                mma_bf16(out_acc[nt],     pa_h[kt2], b0l);
                mma_bf16(out_acc[nt],     pa_l[kt2], b0h);
                mma_bf16(out_acc[nt + 1], pa_h[kt2], b1h);
                mma_bf16(out_acc[nt + 1], pa_h[kt2], b1l);
                mma_bf16(out_acc[nt + 1], pa_l[kt2], b1h);
            }
            // second 32-col half handled by nb loop? nb covers 2*32 = 64? No:
            // nb in {0,1} covers cols 0-31? Each x4t covers 16 cols (two tiles).
        }
        // cover remaining dh tiles 2,3,6,7 (cols 16-31 and 48-63)
        #pragma unroll
        for (int kt2 = 0; kt2 < 4; kt2++) {
            #pragma unroll
            for (int nb = 0; nb < 2; nb++) {
                int krow = kt2 * 16 + (lane & 15);
                int col = nb * 32 + 16 + ((lane >> 4) << 3);
                uint32_t off = (uint32_t)(krow * AST + col) * 2;
                uint32_t vb_h[4], vb_l[4];
                ldsm_x4t(vh_b + off, vb_h);
                ldsm_x4t(vl_b + off, vb_l);
                int nt = nb * 4 + 2;
                uint32_t b0h[2] = {vb_h[0], vb_h[1]}, b1h[2] = {vb_h[2], vb_h[3]};
                uint32_t b0l[2] = {vb_l[0], vb_l[1]}, b1l[2] = {vb_l[2], vb_l[3]};
                mma_bf16(out_acc[nt],     pa_h[kt2], b0h);
                mma_bf16(out_acc[nt],     pa_h[kt2], b0l);
                mma_bf16(out_acc[nt],     pa_l[kt2], b0h);
                mma_bf16(out_acc[nt + 1], pa_h[kt2], b1h);
                mma_bf16(out_acc[nt + 1], pa_h[kt2], b1l);
                mma_bf16(out_acc[nt + 1], pa_l[kt2], b1h);
            }
        }
    }

    // ---- epilogue: ctx [b, q, hcol + dh] ----
    #pragma unroll
    for (int nt = 0; nt < 8; nt++) {
        int q = q0 + wid * 16 + (lane >> 2);
        int c = hcol + nt * 8 + (lane & 3) * 2;
        *(float2*)(ctx + ((size_t)b * SEQ + q) * DMODEL + c) =
            make_float2(out_acc[nt][0], out_acc[nt][1]);
        *(float2*)(ctx + ((size_t)b * SEQ + q + 8) * DMODEL + c) =
            make_float2(out_acc[nt][2], out_acc[nt][3]);
    }
}

// ================= launch =================
extern "C" void kernel_launch(void* const* d_in, const int* in_sizes, int n_in,
                              void* d_out, int out_size)
{
    const float* x      = (const float*)d_in[0];
    const float* ln1_w  = (const float*)d_in[1];
    const float* W_attn = (const float*)d_in[2];
    const float* b_attn = (const float*)d_in[3];
    const float* W_proj = (const float*)d_in[4];
    const float* b_proj = (const float*)d_in[5];
    const float* ln2_w  = (const float*)d_in[6];
    const float* W_fc1  = (const float*)d_in[7];
    const float* b_fc1  = (const float*)d_in[8];
    const float* W_fc2  = (const float*)d_in[9];
    const float* b_fc2  = (const float*)d_in[10];
    float* out = (float*)d_out;

    float *h, *qkv, *ctx, *x1, *fc1;
    cudaGetSymbolAddress((void**)&h,   g_h);
    cudaGetSymbolAddress((void**)&qkv, g_qkv);
    cudaGetSymbolAddress((void**)&ctx, g_ctx);
    cudaGetSymbolAddress((void**)&x1,  g_x1);
    cudaGetSymbolAddress((void**)&fc1, g_fc1);

    cudaFuncSetAttribute(attn_mma_kernel, cudaFuncAttributeMaxDynamicSharedMemorySize, ATTN_SMEM);

    rmsnorm_kernel<<<ROWS, 256>>>(x, ln1_w, h);
    gemm_mma_kernel<<<dim3(QKVN / BN, ROWS / BM), 256>>>(
        h, W_attn, b_attn, nullptr, qkv, ROWS, QKVN, DMODEL, 0);
    attn_mma_kernel<<<dim3(SEQ / AQ, BATCH * NHEAD), 256, ATTN_SMEM>>>(qkv, ctx);
    gemm_mma_kernel<<<dim3(DMODEL / BN, ROWS / BM), 256>>>(
        ctx, W_proj, b_proj, x, x1, ROWS, DMODEL, DMODEL, 0);
    rmsnorm_kernel<<<ROWS, 256>>>(x1, ln2_w, h);
    gemm_mma_kernel<<<dim3(HID / BN, ROWS / BM), 256>>>(
        h, W_fc1, b_fc1, nullptr, fc1, ROWS, HID, DMODEL, 1);
    gemm_mma_kernel<<<dim3(DMODEL / BN, ROWS / BM), 256>>>(
        fc1, W_fc2, b_fc2, x1, out, ROWS, DMODEL, HID, 0);
}

// round 7
// speedup vs baseline: 2.4724x; 1.0459x over previous
#include <cuda_runtime.h>
#include <cuda_bf16.h>
#include <cstdint>

// Problem constants
#define BATCH 2
#define SEQ   2048
#define DMODEL 768
#define NHEAD 12
#define DHEAD 64
#define HID   1536
#define ROWS  (BATCH * SEQ)          // 4096
#define QKVN  (3 * DMODEL)           // 2304
#define EPS   1e-6f

// ---------------- scratch (__device__ globals; no allocs allowed) ----------------
__device__ float g_h  [ROWS * DMODEL];
__device__ float g_qkv[ROWS * QKVN];
__device__ float g_ctx[ROWS * DMODEL];
__device__ float g_x1 [ROWS * DMODEL];
__device__ float g_fc1[ROWS * HID];

// ================= warp-MMA helpers =================
__device__ __forceinline__ uint32_t sptr(const void* p) {
    return (uint32_t)__cvta_generic_to_shared(p);
}
__device__ __forceinline__ void ldsm_x4(uint32_t addr, uint32_t* r) {
    asm volatile("ldmatrix.sync.aligned.m8n8.x4.shared.b16 {%0,%1,%2,%3}, [%4];"
                 : "=r"(r[0]), "=r"(r[1]), "=r"(r[2]), "=r"(r[3]) : "r"(addr));
}
__device__ __forceinline__ void ldsm_x4t(uint32_t addr, uint32_t* r) {
    asm volatile("ldmatrix.sync.aligned.m8n8.x4.trans.shared.b16 {%0,%1,%2,%3}, [%4];"
                 : "=r"(r[0]), "=r"(r[1]), "=r"(r[2]), "=r"(r[3]) : "r"(addr));
}
__device__ __forceinline__ void ldsm_x2t(uint32_t addr, uint32_t* r) {
    asm volatile("ldmatrix.sync.aligned.m8n8.x2.trans.shared.b16 {%0,%1}, [%2];"
                 : "=r"(r[0]), "=r"(r[1]) : "r"(addr));
}
__device__ __forceinline__ void mma_bf16(float* c, const uint32_t* a, const uint32_t* b) {
    asm volatile(
        "mma.sync.aligned.m16n8k16.row.col.f32.bf16.bf16.f32 "
        "{%0,%1,%2,%3}, {%4,%5,%6,%7}, {%8,%9}, {%0,%1,%2,%3};"
        : "+f"(c[0]), "+f"(c[1]), "+f"(c[2]), "+f"(c[3])
        : "r"(a[0]), "r"(a[1]), "r"(a[2]), "r"(a[3]), "r"(b[0]), "r"(b[1]));
}
__device__ __forceinline__ uint32_t pack_bf2(__nv_bfloat16 a, __nv_bfloat16 b) {
    return ((uint32_t)__bfloat16_as_ushort(b) << 16) | (uint32_t)__bfloat16_as_ushort(a);
}
__device__ __forceinline__ void split4(float4 v, uint2& h, uint2& l) {
    __nv_bfloat16 hx = __float2bfloat16_rn(v.x), hy = __float2bfloat16_rn(v.y);
    __nv_bfloat16 hz = __float2bfloat16_rn(v.z), hw = __float2bfloat16_rn(v.w);
    __nv_bfloat16 lx = __float2bfloat16_rn(v.x - __bfloat162float(hx));
    __nv_bfloat16 ly = __float2bfloat16_rn(v.y - __bfloat162float(hy));
    __nv_bfloat16 lz = __float2bfloat16_rn(v.z - __bfloat162float(hz));
    __nv_bfloat16 lw = __float2bfloat16_rn(v.w - __bfloat162float(hw));
    h = make_uint2(pack_bf2(hx, hy), pack_bf2(hz, hw));
    l = make_uint2(pack_bf2(lx, ly), pack_bf2(lz, lw));
}
__device__ __forceinline__ void split1(float v, __nv_bfloat16& h, __nv_bfloat16& l) {
    h = __float2bfloat16_rn(v);
    l = __float2bfloat16_rn(v - __bfloat162float(h));
}

// ================= RMSNorm =================
__global__ __launch_bounds__(256) void rmsnorm_kernel(
    const float* __restrict__ x, const float* __restrict__ w, float* __restrict__ out)
{
    const int row = blockIdx.x;
    const int tid = threadIdx.x;
    const float* xr = x + (size_t)row * DMODEL;
    float v0 = xr[tid], v1 = xr[tid + 256], v2 = xr[tid + 512];
    float s = v0 * v0 + v1 * v1 + v2 * v2;
    #pragma unroll
    for (int o = 16; o > 0; o >>= 1) s += __shfl_xor_sync(0xFFFFFFFF, s, o);
    __shared__ float wsum[8];
    if ((tid & 31) == 0) wsum[tid >> 5] = s;
    __syncthreads();
    if (tid < 8) {
        float t = wsum[tid];
        #pragma unroll
        for (int o = 4; o > 0; o >>= 1) t += __shfl_xor_sync(0xFF, t, o);
        if (tid == 0) wsum[0] = t;
    }
    __syncthreads();
    const float scale = rsqrtf(wsum[0] * (1.0f / DMODEL) + EPS);
    float* orow = out + (size_t)row * DMODEL;
    orow[tid]       = v0 * scale * w[tid];
    orow[tid + 256] = v1 * scale * w[tid + 256];
    orow[tid + 512] = v2 * scale * w[tid + 512];
}

// ================= tensor-core GEMM (double-buffered pipeline) =================
#define BM 128
#define BN 128
#define BK 32
#define STA 40
#define STB 136
#define ASZ (BM * STA)                 // bf16 elems
#define BSZ (BK * STB)
#define GBUF (2 * ASZ + 2 * BSZ)       // one stage, bf16 elems
#define GEMM_SMEM (2 * GBUF * 2)       // bytes = 75776

__device__ __forceinline__ void gemm_sts(
    __nv_bfloat16* Ah, __nv_bfloat16* Al, __nv_bfloat16* Bh, __nv_bfloat16* Bl,
    const float4* av, const float4* bv, int tid)
{
    #pragma unroll
    for (int i = 0; i < 4; i++) {
        int idx = tid + i * 256;
        int m = idx >> 3, kq = idx & 7;
        uint2 h, l; split4(av[i], h, l);
        *(uint2*)(Ah + m * STA + kq * 4) = h;
        *(uint2*)(Al + m * STA + kq * 4) = l;
    }
    #pragma unroll
    for (int i = 0; i < 4; i++) {
        int idx = tid + i * 256;
        int kk = idx >> 5, nq = idx & 31;
        uint2 h, l; split4(bv[i], h, l);
        *(uint2*)(Bh + kk * STB + nq * 4) = h;
        *(uint2*)(Bl + kk * STB + nq * 4) = l;
    }
}

__global__ __launch_bounds__(256) void gemm_mma_kernel(
    const float* __restrict__ A, const float* __restrict__ W,
    const float* __restrict__ bias, const float* __restrict__ resid,
    float* __restrict__ C, int M, int N, int K, int do_relu)
{
    extern __shared__ __nv_bfloat16 gsm[];
    const int tid = threadIdx.x, wid = tid >> 5, lane = tid & 31;
    const int warp_m = wid >> 2, warp_n = wid & 3;
    const int m0 = blockIdx.y * BM, n0 = blockIdx.x * BN;

    float acc[4][4][4];
    #pragma unroll
    for (int i = 0; i < 4; i++)
        #pragma unroll
        for (int j = 0; j < 4; j++)
            #pragma unroll
            for (int r = 0; r < 4; r++) acc[i][j][r] = 0.f;

    float4 av[4], bv[4];
    const int ntiles = K / BK;

    // prologue: LDG tile 0 -> regs -> STS buf0
    #pragma unroll
    for (int i = 0; i < 4; i++) {
        int idx = tid + i * 256;
        int m = idx >> 3, kq = idx & 7;
        av[i] = *(const float4*)(A + (size_t)(m0 + m) * K + kq * 4);
    }
    #pragma unroll
    for (int i = 0; i < 4; i++) {
        int idx = tid + i * 256;
        int kk = idx >> 5, nq = idx & 31;
        bv[i] = *(const float4*)(W + (size_t)kk * N + n0 + nq * 4);
    }
    gemm_sts(gsm, gsm + ASZ, gsm + 2 * ASZ, gsm + 2 * ASZ + BSZ, av, bv, tid);

    for (int t = 0; t < ntiles; t++) {
        // issue next tile's LDGs early (latency hides under MMA section)
        if (t + 1 < ntiles) {
            const int k0 = (t + 1) * BK;
            #pragma unroll
            for (int i = 0; i < 4; i++) {
                int idx = tid + i * 256;
                int m = idx >> 3, kq = idx & 7;
                av[i] = *(const float4*)(A + (size_t)(m0 + m) * K + k0 + kq * 4);
            }
            #pragma unroll
            for (int i = 0; i < 4; i++) {
                int idx = tid + i * 256;
                int kk = idx >> 5, nq = idx & 31;
                bv[i] = *(const float4*)(W + (size_t)(k0 + kk) * N + n0 + nq * 4);
            }
        }
        __syncthreads();   // buf[t&1] visible; buf[(t+1)&1] readers (iter t-1) done

        __nv_bfloat16* Ah = gsm + (t & 1) * GBUF;
        __nv_bfloat16* Al = Ah + ASZ;
        __nv_bfloat16* Bh = Al + ASZ;
        __nv_bfloat16* Bl = Bh + BSZ;
        const uint32_t ah_b = sptr(Ah), al_b = sptr(Al);
        const uint32_t bh_b = sptr(Bh), bl_b = sptr(Bl);

        #pragma unroll
        for (int ks = 0; ks < 2; ks++) {
            const int kof = ks * 16;
            uint32_t ah[4][4], al[4][4], bh[4][2], bl[4][2];
            #pragma unroll
            for (int mt = 0; mt < 4; mt++) {
                int row = warp_m * 64 + mt * 16 + (lane & 15);
                int col = kof + ((lane >> 4) << 3);
                uint32_t off = (uint32_t)(row * STA + col) * 2;
                ldsm_x4(ah_b + off, ah[mt]);
                ldsm_x4(al_b + off, al[mt]);
            }
            #pragma unroll
            for (int nt = 0; nt < 4; nt++) {
                int krow = kof + (lane & 15);
                int col = warp_n * 32 + nt * 8;
                uint32_t off = (uint32_t)(krow * STB + col) * 2;
                ldsm_x2t(bh_b + off, bh[nt]);
                ldsm_x2t(bl_b + off, bl[nt]);
            }
            #pragma unroll
            for (int mt = 0; mt < 4; mt++)
                #pragma unroll
                for (int nt = 0; nt < 4; nt++) {
                    mma_bf16(acc[mt][nt], ah[mt], bh[nt]);
                    mma_bf16(acc[mt][nt], ah[mt], bl[nt]);
                    mma_bf16(acc[mt][nt], al[mt], bh[nt]);
                }
        }

        if (t + 1 < ntiles) {
            __nv_bfloat16* nAh = gsm + ((t + 1) & 1) * GBUF;
            gemm_sts(nAh, nAh + ASZ, nAh + 2 * ASZ, nAh + 2 * ASZ + BSZ, av, bv, tid);
        }
    }

    #pragma unroll
    for (int mt = 0; mt < 4; mt++) {
        int r0 = m0 + warp_m * 64 + mt * 16 + (lane >> 2);
        #pragma unroll
        for (int nt = 0; nt < 4; nt++) {
            int c0 = n0 + warp_n * 32 + nt * 8 + (lane & 3) * 2;
            float b0 = bias[c0], b1 = bias[c0 + 1];
            float v0 = acc[mt][nt][0] + b0, v1 = acc[mt][nt][1] + b1;
            float v2 = acc[mt][nt][2] + b0, v3 = acc[mt][nt][3] + b1;
            if (do_relu) {
                v0 = fmaxf(v0, 0.f); v1 = fmaxf(v1, 0.f);
                v2 = fmaxf(v2, 0.f); v3 = fmaxf(v3, 0.f);
            }
            if (resid) {
                const float* rr0 = resid + (size_t)r0 * N + c0;
                const float* rr1 = resid + (size_t)(r0 + 8) * N + c0;
                v0 += rr0[0]; v1 += rr0[1];
                v2 += rr1[0]; v3 += rr1[1];
            }
            *(float2*)(C + (size_t)r0 * N + c0)       = make_float2(v0, v1);
            *(float2*)(C + (size_t)(r0 + 8) * N + c0) = make_float2(v2, v3);
        }
    }
}

// ================= tensor-core squared-ReLU attention (pipelined) =================
#define AQ  128
#define AKT 64
#define AST 72
#define QSZ   (AQ * AST)               // bf16 elems per Q plane
#define KVSZ  (AKT * AST)              // bf16 elems per K/V plane
#define KVBUF (4 * KVSZ)               // Kh,Kl,Vh,Vl one stage
// bytes: Q planes (2*QSZ*2 = 36864) + 2 stages (2*KVBUF*2 = 73728)
#define ATTN_SMEM ((2 * QSZ + 2 * KVBUF) * 2)   // 110592

__global__ __launch_bounds__(256) void attn_mma_kernel(
    const float* __restrict__ qkv, float* __restrict__ ctx)
{
    extern __shared__ __nv_bfloat16 asmem[];
    __nv_bfloat16* Qh = asmem;
    __nv_bfloat16* Ql = asmem + QSZ;
    __nv_bfloat16* kvbase = asmem + 2 * QSZ;

    const int tid = threadIdx.x, wid = tid >> 5, lane = tid & 31;
    const int bh = blockIdx.y;
    const int b = bh / NHEAD, h = bh % NHEAD;
    const int q0 = blockIdx.x * AQ;
    const float* base = qkv + (size_t)b * SEQ * QKVN;
    const int hcol = h * DHEAD;

    // ---- Q tile -> smem (hi/lo) ----
    #pragma unroll
    for (int i = 0; i < 8; i++) {
        int idx = tid + i * 256;
        int m = idx >> 4, dq = idx & 15;
        float4 v = *(const float4*)(base + (size_t)(q0 + m) * QKVN + hcol + dq * 4);
        uint2 hh, ll; split4(v, hh, ll);
        *(uint2*)(Qh + m * AST + dq * 4) = hh;
        *(uint2*)(Ql + m * AST + dq * 4) = ll;
    }

    // ---- KV tile 0 -> regs ----
    float4 kva[4], kvv[4];
    #pragma unroll
    for (int i = 0; i < 4; i++) {
        int idx = tid + i * 256;
        int r = idx >> 4, dq = idx & 15;
        kva[i] = *(const float4*)(base + (size_t)r * QKVN + DMODEL + hcol + dq * 4);
        kvv[i] = *(const float4*)(base + (size_t)r * QKVN + 2 * DMODEL + hcol + dq * 4);
    }
    __syncthreads();   // Q visible

    // ---- hoist Q fragments to registers (invariant over key tiles) ----
    uint32_t qa_h[4][4], qa_l[4][4];
    const uint32_t qh_b = sptr(Qh), ql_b = sptr(Ql);
    #pragma unroll
    for (int ks = 0; ks < 4; ks++) {
        int row = wid * 16 + (lane & 15);
        int col = ks * 16 + ((lane >> 4) << 3);
        uint32_t off = (uint32_t)(row * AST + col) * 2;
        ldsm_x4(qh_b + off, qa_h[ks]);
        ldsm_x4(ql_b + off, qa_l[ks]);
    }

    // ---- STS KV tile 0 -> stage 0 ----
    {
        __nv_bfloat16* Kh = kvbase;
        #pragma unroll
        for (int i = 0; i < 4; i++) {
            int idx = tid + i * 256;
            int r = idx >> 4, dq = idx & 15;
            uint2 hh, ll;
            split4(kva[i], hh, ll);
            *(uint2*)(Kh + r * AST + dq * 4)           = hh;
            *(uint2*)(Kh + KVSZ + r * AST + dq * 4)    = ll;
            split4(kvv[i], hh, ll);
            *(uint2*)(Kh + 2 * KVSZ + r * AST + dq * 4) = hh;
            *(uint2*)(Kh + 3 * KVSZ + r * AST + dq * 4) = ll;
        }
    }

    float out_acc[8][4];
    #pragma unroll
    for (int nt = 0; nt < 8; nt++)
        #pragma unroll
        for (int r = 0; r < 4; r++) out_acc[nt][r] = 0.f;

    const int ntiles = SEQ / AKT;    // 32
    for (int t = 0; t < ntiles; t++) {
        // prefetch next KV tile into regs
        if (t + 1 < ntiles) {
            const int k0 = (t + 1) * AKT;
            #pragma unroll
            for (int i = 0; i < 4; i++) {
                int idx = tid + i * 256;
                int r = idx >> 4, dq = idx & 15;
                kva[i] = *(const float4*)(base + (size_t)(k0 + r) * QKVN + DMODEL + hcol + dq * 4);
                kvv[i] = *(const float4*)(base + (size_t)(k0 + r) * QKVN + 2 * DMODEL + hcol + dq * 4);
            }
        }
        __syncthreads();

        __nv_bfloat16* Kh = kvbase + (t & 1) * KVBUF;
        const uint32_t kh_b = sptr(Kh);
        const uint32_t kl_b = kh_b + KVSZ * 2;
        const uint32_t vh_b = kh_b + 2 * KVSZ * 2;
        const uint32_t vl_b = kh_b + 3 * KVSZ * 2;

        // ---- S = Q K^T ----
        float s_acc[8][4];
        #pragma unroll
        for (int nt = 0; nt < 8; nt++)
            #pragma unroll
            for (int r = 0; r < 4; r++) s_acc[nt][r] = 0.f;

        #pragma unroll
        for (int ks = 0; ks < 4; ks++) {
            const int kof = ks * 16;
            #pragma unroll
            for (int ntp = 0; ntp < 4; ntp++) {
                int n = ntp * 16 + (lane & 15);
                int col = kof + ((lane >> 4) << 3);
                uint32_t off = (uint32_t)(n * AST + col) * 2;
                uint32_t kb_h[4], kb_l[4];
                ldsm_x4(kh_b + off, kb_h);
                ldsm_x4(kl_b + off, kb_l);
                uint32_t b0h[2] = {kb_h[0], kb_h[2]}, b1h[2] = {kb_h[1], kb_h[3]};
                uint32_t b0l[2] = {kb_l[0], kb_l[2]}, b1l[2] = {kb_l[1], kb_l[3]};
                mma_bf16(s_acc[2 * ntp],     qa_h[ks], b0h);
                mma_bf16(s_acc[2 * ntp],     qa_h[ks], b0l);
                mma_bf16(s_acc[2 * ntp],     qa_l[ks], b0h);
                mma_bf16(s_acc[2 * ntp + 1], qa_h[ks], b1h);
                mma_bf16(s_acc[2 * ntp + 1], qa_h[ks], b1l);
                mma_bf16(s_acc[2 * ntp + 1], qa_l[ks], b1h);
            }
        }

        // ---- P = relu(s/8)^2, repack in registers into A-fragments ----
        uint32_t pa_h[4][4], pa_l[4][4];
        #pragma unroll
        for (int nt = 0; nt < 8; nt++) {
            float p[4];
            #pragma unroll
            for (int r = 0; r < 4; r++) {
                float tt = fmaxf(s_acc[nt][r], 0.f);
                p[r] = tt * tt * 0.015625f;
            }
            __nv_bfloat16 h0, l0, h1, l1, h2, l2, h3, l3;
            split1(p[0], h0, l0); split1(p[1], h1, l1);
            split1(p[2], h2, l2); split1(p[3], h3, l3);
            int kt2 = nt >> 1;
            int base_r = (nt & 1) ? 2 : 0;
            pa_h[kt2][base_r]     = pack_bf2(h0, h1);
            pa_h[kt2][base_r + 1] = pack_bf2(h2, h3);
            pa_l[kt2][base_r]     = pack_bf2(l0, l1);
            pa_l[kt2][base_r + 1] = pack_bf2(l2, l3);
        }

        // ---- ctx += P V ----
        #pragma unroll
        for (int kt2 = 0; kt2 < 4; kt2++) {
            int krow = kt2 * 16 + (lane & 15);
            #pragma unroll
            for (int cb = 0; cb < 4; cb++) {
                int col = cb * 16 + ((lane >> 4) << 3);
                uint32_t off = (uint32_t)(krow * AST + col) * 2;
                uint32_t vbh[4], vbl[4];
                ldsm_x4t(vh_b + off, vbh);
                ldsm_x4t(vl_b + off, vbl);
                int nt = cb * 2;
                uint32_t b0h[2] = {vbh[0], vbh[1]}, b1h[2] = {vbh[2], vbh[3]};
                uint32_t b0l[2] = {vbl[0], vbl[1]}, b1l[2] = {vbl[2], vbl[3]};
                mma_bf16(out_acc[nt],     pa_h[kt2], b0h);
                mma_bf16(out_acc[nt],     pa_h[kt2], b0l);
                mma_bf16(out_acc[nt],     pa_l[kt2], b0h);
                mma_bf16(out_acc[nt + 1], pa_h[kt2], b1h);
                mma_bf16(out_acc[nt + 1], pa_h[kt2], b1l);
                mma_bf16(out_acc[nt + 1], pa_l[kt2], b1h);
            }
        }

        // ---- STS next KV tile into other stage ----
        if (t + 1 < ntiles) {
            __nv_bfloat16* nKh = kvbase + ((t + 1) & 1) * KVBUF;
            #pragma unroll
            for (int i = 0; i < 4; i++) {
                int idx = tid + i * 256;
                int r = idx >> 4, dq = idx & 15;
                uint2 hh, ll;
                split4(kva[i], hh, ll);
                *(uint2*)(nKh + r * AST + dq * 4)            = hh;
                *(uint2*)(nKh + KVSZ + r * AST + dq * 4)     = ll;
                split4(kvv[i], hh, ll);
                *(uint2*)(nKh + 2 * KVSZ + r * AST + dq * 4) = hh;
                *(uint2*)(nKh + 3 * KVSZ + r * AST + dq * 4) = ll;
            }
        }
    }

    // ---- epilogue ----
    #pragma unroll
    for (int nt = 0; nt < 8; nt++) {
        int q = q0 + wid * 16 + (lane >> 2);
        int c = hcol + nt * 8 + (lane & 3) * 2;
        *(float2*)(ctx + ((size_t)b * SEQ + q) * DMODEL + c) =
            make_float2(out_acc[nt][0], out_acc[nt][1]);
        *(float2*)(ctx + ((size_t)b * SEQ + q + 8) * DMODEL + c) =
            make_float2(out_acc[nt][2], out_acc[nt][3]);
    }
}

// ================= launch =================
extern "C" void kernel_launch(void* const* d_in, const int* in_sizes, int n_in,
                              void* d_out, int out_size)
{
    const float* x      = (const float*)d_in[0];
    const float* ln1_w  = (const float*)d_in[1];
    const float* W_attn = (const float*)d_in[2];
    const float* b_attn = (const float*)d_in[3];
    const float* W_proj = (const float*)d_in[4];
    const float* b_proj = (const float*)d_in[5];
    const float* ln2_w  = (const float*)d_in[6];
    const float* W_fc1  = (const float*)d_in[7];
    const float* b_fc1  = (const float*)d_in[8];
    const float* W_fc2  = (const float*)d_in[9];
    const float* b_fc2  = (const float*)d_in[10];
    float* out = (float*)d_out;

    float *h, *qkv, *ctx, *x1, *fc1;
    cudaGetSymbolAddress((void**)&h,   g_h);
    cudaGetSymbolAddress((void**)&qkv, g_qkv);
    cudaGetSymbolAddress((void**)&ctx, g_ctx);
    cudaGetSymbolAddress((void**)&x1,  g_x1);
    cudaGetSymbolAddress((void**)&fc1, g_fc1);

    cudaFuncSetAttribute(gemm_mma_kernel, cudaFuncAttributeMaxDynamicSharedMemorySize, GEMM_SMEM);
    cudaFuncSetAttribute(attn_mma_kernel, cudaFuncAttributeMaxDynamicSharedMemorySize, ATTN_SMEM);

    rmsnorm_kernel<<<ROWS, 256>>>(x, ln1_w, h);
    gemm_mma_kernel<<<dim3(QKVN / BN, ROWS / BM), 256, GEMM_SMEM>>>(
        h, W_attn, b_attn, nullptr, qkv, ROWS, QKVN, DMODEL, 0);
    attn_mma_kernel<<<dim3(SEQ / AQ, BATCH * NHEAD), 256, ATTN_SMEM>>>(qkv, ctx);
    gemm_mma_kernel<<<dim3(DMODEL / BN, ROWS / BM), 256, GEMM_SMEM>>>(
        ctx, W_proj, b_proj, x, x1, ROWS, DMODEL, DMODEL, 0);
    rmsnorm_kernel<<<ROWS, 256>>>(x1, ln2_w, h);
    gemm_mma_kernel<<<dim3(HID / BN, ROWS / BM), 256, GEMM_SMEM>>>(
        h, W_fc1, b_fc1, nullptr, fc1, ROWS, HID, DMODEL, 1);
    gemm_mma_kernel<<<dim3(DMODEL / BN, ROWS / BM), 256, GEMM_SMEM>>>(
        fc1, W_fc2, b_fc2, x1, out, ROWS, DMODEL, HID, 0);
}

// round 8
// speedup vs baseline: 2.8736x; 1.1623x over previous
#include <cuda_runtime.h>
#include <cuda_bf16.h>
#include <cstdint>

// Problem constants
#define BATCH 2
#define SEQ   2048
#define DMODEL 768
#define NHEAD 12
#define DHEAD 64
#define HID   1536
#define ROWS  (BATCH * SEQ)          // 4096
#define QKVN  (3 * DMODEL)           // 2304
#define EPS   1e-6f

// ---------------- scratch (__device__ globals; no allocs allowed) ----------------
__device__ alignas(16) __nv_bfloat16 g_wattn_h[DMODEL * QKVN], g_wattn_l[DMODEL * QKVN];
__device__ alignas(16) __nv_bfloat16 g_wproj_h[DMODEL * DMODEL], g_wproj_l[DMODEL * DMODEL];
__device__ alignas(16) __nv_bfloat16 g_wfc1_h[DMODEL * HID], g_wfc1_l[DMODEL * HID];
__device__ alignas(16) __nv_bfloat16 g_wfc2_h[HID * DMODEL], g_wfc2_l[HID * DMODEL];
__device__ alignas(16) __nv_bfloat16 g_hh[ROWS * DMODEL], g_hl[ROWS * DMODEL];
__device__ alignas(16) __nv_bfloat16 g_qh[ROWS * QKVN], g_ql[ROWS * QKVN];
__device__ alignas(16) __nv_bfloat16 g_ch[ROWS * DMODEL], g_cl[ROWS * DMODEL];
__device__ alignas(16) __nv_bfloat16 g_f1h[ROWS * HID], g_f1l[ROWS * HID];
__device__ float g_x1[ROWS * DMODEL];

// ================= helpers =================
__device__ __forceinline__ uint32_t sptr(const void* p) {
    return (uint32_t)__cvta_generic_to_shared(p);
}
__device__ __forceinline__ void ldsm_x4(uint32_t addr, uint32_t* r) {
    asm volatile("ldmatrix.sync.aligned.m8n8.x4.shared.b16 {%0,%1,%2,%3}, [%4];"
                 : "=r"(r[0]), "=r"(r[1]), "=r"(r[2]), "=r"(r[3]) : "r"(addr));
}
__device__ __forceinline__ void ldsm_x4t(uint32_t addr, uint32_t* r) {
    asm volatile("ldmatrix.sync.aligned.m8n8.x4.trans.shared.b16 {%0,%1,%2,%3}, [%4];"
                 : "=r"(r[0]), "=r"(r[1]), "=r"(r[2]), "=r"(r[3]) : "r"(addr));
}
__device__ __forceinline__ void mma_bf16(float* c, const uint32_t* a, const uint32_t* b) {
    asm volatile(
        "mma.sync.aligned.m16n8k16.row.col.f32.bf16.bf16.f32 "
        "{%0,%1,%2,%3}, {%4,%5,%6,%7}, {%8,%9}, {%0,%1,%2,%3};"
        : "+f"(c[0]), "+f"(c[1]), "+f"(c[2]), "+f"(c[3])
        : "r"(a[0]), "r"(a[1]), "r"(a[2]), "r"(a[3]), "r"(b[0]), "r"(b[1]));
}
__device__ __forceinline__ uint32_t pack_bf2(__nv_bfloat16 a, __nv_bfloat16 b) {
    return ((uint32_t)__bfloat16_as_ushort(b) << 16) | (uint32_t)__bfloat16_as_ushort(a);
}
__device__ __forceinline__ void split4(float4 v, uint2& h, uint2& l) {
    __nv_bfloat16 hx = __float2bfloat16_rn(v.x), hy = __float2bfloat16_rn(v.y);
    __nv_bfloat16 hz = __float2bfloat16_rn(v.z), hw = __float2bfloat16_rn(v.w);
    __nv_bfloat16 lx = __float2bfloat16_rn(v.x - __bfloat162float(hx));
    __nv_bfloat16 ly = __float2bfloat16_rn(v.y - __bfloat162float(hy));
    __nv_bfloat16 lz = __float2bfloat16_rn(v.z - __bfloat162float(hz));
    __nv_bfloat16 lw = __float2bfloat16_rn(v.w - __bfloat162float(hw));
    h = make_uint2(pack_bf2(hx, hy), pack_bf2(hz, hw));
    l = make_uint2(pack_bf2(lx, ly), pack_bf2(lz, lw));
}
__device__ __forceinline__ void split1(float v, __nv_bfloat16& h, __nv_bfloat16& l) {
    h = __float2bfloat16_rn(v);
    l = __float2bfloat16_rn(v - __bfloat162float(h));
}

#define CP_ASYNC16(dst, src) \
    asm volatile("cp.async.cg.shared.global [%0], [%1], 16;" :: "r"(dst), "l"(src) : "memory")
#define CP_COMMIT() asm volatile("cp.async.commit_group;" ::: "memory")
#define CP_WAIT(N)  asm volatile("cp.async.wait_group %0;" :: "n"(N) : "memory")

// ================= weight conversion: fp32 -> bf16 hi/lo planes =================
__global__ __launch_bounds__(256) void convert_kernel(
    const float* __restrict__ src, __nv_bfloat16* __restrict__ h,
    __nv_bfloat16* __restrict__ l, int n4)
{
    int i = blockIdx.x * 256 + threadIdx.x;
    if (i < n4) {
        float4 v = ((const float4*)src)[i];
        uint2 hh, ll; split4(v, hh, ll);
        ((uint2*)h)[i] = hh;
        ((uint2*)l)[i] = ll;
    }
}

// ================= RMSNorm: fp32 in, bf16 hi/lo planes out =================
__global__ __launch_bounds__(256) void rmsnorm_kernel(
    const float* __restrict__ x, const float* __restrict__ w,
    __nv_bfloat16* __restrict__ oh, __nv_bfloat16* __restrict__ ol)
{
    const int row = blockIdx.x;
    const int tid = threadIdx.x;
    const float* xr = x + (size_t)row * DMODEL;
    float v0 = xr[tid], v1 = xr[tid + 256], v2 = xr[tid + 512];
    float s = v0 * v0 + v1 * v1 + v2 * v2;
    #pragma unroll
    for (int o = 16; o > 0; o >>= 1) s += __shfl_xor_sync(0xFFFFFFFF, s, o);
    __shared__ float wsum[8];
    if ((tid & 31) == 0) wsum[tid >> 5] = s;
    __syncthreads();
    if (tid < 8) {
        float t = wsum[tid];
        #pragma unroll
        for (int o = 4; o > 0; o >>= 1) t += __shfl_xor_sync(0xFF, t, o);
        if (tid == 0) wsum[0] = t;
    }
    __syncthreads();
    const float scale = rsqrtf(wsum[0] * (1.0f / DMODEL) + EPS);
    size_t base = (size_t)row * DMODEL;
    __nv_bfloat16 h, l;
    split1(v0 * scale * w[tid], h, l);       oh[base + tid] = h;       ol[base + tid] = l;
    split1(v1 * scale * w[tid + 256], h, l); oh[base + tid + 256] = h; ol[base + tid + 256] = l;
    split1(v2 * scale * w[tid + 512], h, l); oh[base + tid + 512] = h; ol[base + tid + 512] = l;
}

// ================= tensor-core GEMM (cp.async 3-stage, bf16 hi/lo planes) =================
// C = A @ W + bias; A,W given as bf16 hi/lo planes. Outputs fp32 (+resid) and/or planes.
#define BM 128
#define BN 128
#define BK 32
#define STA 40
#define STB 136
#define ASZ (BM * STA)                 // 5120 halfs per A plane
#define BSZ (BK * STB)                 // 4352 halfs per B plane
#define STAGE_H (2 * ASZ + 2 * BSZ)    // 18944 halfs
#define GEMM_SMEM (3 * STAGE_H * 2)    // 113664 bytes

__device__ __forceinline__ void gemm_cp_stage(
    uint32_t sb, const __nv_bfloat16* Ah_g, const __nv_bfloat16* Al_g,
    const __nv_bfloat16* Bh_g, const __nv_bfloat16* Bl_g,
    int m0, int n0, int k0, int K, int N, int tid)
{
    #pragma unroll
    for (int i = 0; i < 2; i++) {
        int idx = tid + i * 256;                 // 512 chunks per A plane
        int row = idx >> 2, ch = idx & 3;
        uint32_t d = sb + (uint32_t)(row * STA + ch * 8) * 2;
        size_t o = (size_t)(m0 + row) * K + k0 + ch * 8;
        CP_ASYNC16(d, Ah_g + o);
        CP_ASYNC16(d + ASZ * 2, Al_g + o);
    }
    #pragma unroll
    for (int i = 0; i < 2; i++) {
        int idx = tid + i * 256;                 // 512 chunks per B plane
        int row = idx >> 4, ch = idx & 15;
        uint32_t d = sb + (uint32_t)(2 * ASZ + row * STB + ch * 8) * 2;
        size_t o = (size_t)(k0 + row) * N + n0 + ch * 8;
        CP_ASYNC16(d, Bh_g + o);
        CP_ASYNC16(d + BSZ * 2, Bl_g + o);
    }
}

__global__ __launch_bounds__(256, 2) void gemm_mma_kernel(
    const __nv_bfloat16* __restrict__ Ah_g, const __nv_bfloat16* __restrict__ Al_g,
    const __nv_bfloat16* __restrict__ Bh_g, const __nv_bfloat16* __restrict__ Bl_g,
    const float* __restrict__ bias, const float* __restrict__ resid,
    float* __restrict__ Cf, __nv_bfloat16* __restrict__ Ch, __nv_bfloat16* __restrict__ Cl,
    int M, int N, int K, int do_relu)
{
    extern __shared__ __nv_bfloat16 gsm[];
    const uint32_t smb = sptr(gsm);
    const int tid = threadIdx.x, wid = tid >> 5, lane = tid & 31;
    const int warp_m = wid >> 2, warp_n = wid & 3;
    const int m0 = blockIdx.y * BM, n0 = blockIdx.x * BN;

    float acc[4][4][4];
    #pragma unroll
    for (int i = 0; i < 4; i++)
        #pragma unroll
        for (int j = 0; j < 4; j++)
            #pragma unroll
            for (int r = 0; r < 4; r++) acc[i][j][r] = 0.f;

    const int ntiles = K / BK;   // >= 24

    gemm_cp_stage(smb, Ah_g, Al_g, Bh_g, Bl_g, m0, n0, 0, K, N, tid);
    CP_COMMIT();
    gemm_cp_stage(smb + STAGE_H * 2, Ah_g, Al_g, Bh_g, Bl_g, m0, n0, BK, K, N, tid);
    CP_COMMIT();

    for (int t = 0; t < ntiles; t++) {
        if (t + 2 <= ntiles) { CP_WAIT(1); } else { CP_WAIT(0); }
        __syncthreads();
        if (t + 2 < ntiles) {
            gemm_cp_stage(smb + ((t + 2) % 3) * STAGE_H * 2,
                          Ah_g, Al_g, Bh_g, Bl_g, m0, n0, (t + 2) * BK, K, N, tid);
            CP_COMMIT();
        }

        const uint32_t st = smb + (t % 3) * STAGE_H * 2;
        const uint32_t ah_b = st, al_b = st + ASZ * 2;
        const uint32_t bh_b = st + 2 * ASZ * 2, bl_b = bh_b + BSZ * 2;

        #pragma unroll
        for (int ks = 0; ks < 2; ks++) {
            const int kof = ks * 16;
            uint32_t bh[4][2], bl[4][2];
            #pragma unroll
            for (int cb = 0; cb < 2; cb++) {
                int krow = kof + (lane & 15);
                int col = warp_n * 32 + cb * 16 + ((lane >> 4) << 3);
                uint32_t off = (uint32_t)(krow * STB + col) * 2;
                uint32_t tmp[4];
                ldsm_x4t(bh_b + off, tmp);
                bh[2 * cb][0] = tmp[0]; bh[2 * cb][1] = tmp[1];
                bh[2 * cb + 1][0] = tmp[2]; bh[2 * cb + 1][1] = tmp[3];
                ldsm_x4t(bl_b + off, tmp);
                bl[2 * cb][0] = tmp[0]; bl[2 * cb][1] = tmp[1];
                bl[2 * cb + 1][0] = tmp[2]; bl[2 * cb + 1][1] = tmp[3];
            }
            #pragma unroll
            for (int mt = 0; mt < 4; mt++) {
                int row = warp_m * 64 + mt * 16 + (lane & 15);
                int col = kof + ((lane >> 4) << 3);
                uint32_t off = (uint32_t)(row * STA + col) * 2;
                uint32_t ah[4], al[4];
                ldsm_x4(ah_b + off, ah);
                ldsm_x4(al_b + off, al);
                #pragma unroll
                for (int nt = 0; nt < 4; nt++) {
                    mma_bf16(acc[mt][nt], ah, bh[nt]);
                    mma_bf16(acc[mt][nt], ah, bl[nt]);
                    mma_bf16(acc[mt][nt], al, bh[nt]);
                }
            }
        }
    }

    // ---- epilogue ----
    #pragma unroll
    for (int mt = 0; mt < 4; mt++) {
        int r0 = m0 + warp_m * 64 + mt * 16 + (lane >> 2);
        #pragma unroll
        for (int nt = 0; nt < 4; nt++) {
            int c0 = n0 + warp_n * 32 + nt * 8 + (lane & 3) * 2;
            float b0 = bias[c0], b1 = bias[c0 + 1];
            float v0 = acc[mt][nt][0] + b0, v1 = acc[mt][nt][1] + b1;
            float v2 = acc[mt][nt][2] + b0, v3 = acc[mt][nt][3] + b1;
            if (do_relu) {
                v0 = fmaxf(v0, 0.f); v1 = fmaxf(v1, 0.f);
                v2 = fmaxf(v2, 0.f); v3 = fmaxf(v3, 0.f);
            }
            if (resid) {
                const float* rr0 = resid + (size_t)r0 * N + c0;
                const float* rr1 = resid + (size_t)(r0 + 8) * N + c0;
                v0 += rr0[0]; v1 += rr0[1];
                v2 += rr1[0]; v3 += rr1[1];
            }
            if (Cf) {
                *(float2*)(Cf + (size_t)r0 * N + c0)       = make_float2(v0, v1);
                *(float2*)(Cf + (size_t)(r0 + 8) * N + c0) = make_float2(v2, v3);
            }
            if (Ch) {
                __nv_bfloat16 h0, l0, h1, l1;
                split1(v0, h0, l0); split1(v1, h1, l1);
                *(uint32_t*)(Ch + (size_t)r0 * N + c0) = pack_bf2(h0, h1);
                *(uint32_t*)(Cl + (size_t)r0 * N + c0) = pack_bf2(l0, l1);
                split1(v2, h0, l0); split1(v3, h1, l1);
                *(uint32_t*)(Ch + (size_t)(r0 + 8) * N + c0) = pack_bf2(h0, h1);
                *(uint32_t*)(Cl + (size_t)(r0 + 8) * N + c0) = pack_bf2(l0, l1);
            }
        }
    }
}

// ================= tensor-core squared-ReLU attention (cp.async 3-stage) =================
#define AQ  128
#define AKT 64
#define AST 72
#define QSZ   (AQ * AST)               // 9216 halfs per Q plane
#define KVSZ  (AKT * AST)              // 4608 halfs per K/V plane
#define KVSTG (4 * KVSZ)               // 18432 halfs per stage
#define ATTN_SMEM ((2 * QSZ + 3 * KVSTG) * 2)   // 147456 bytes

__device__ __forceinline__ void attn_cp_kv(
    uint32_t sb, const __nv_bfloat16* qh_g, const __nv_bfloat16* ql_g,
    size_t rowbase, int tid)
{
    #pragma unroll
    for (int i = 0; i < 2; i++) {
        int idx = tid + i * 256;                 // 512 chunks per plane
        int row = idx >> 3, ch = idx & 7;
        size_t ko = rowbase + (size_t)row * QKVN + DMODEL + ch * 8;
        size_t vo = rowbase + (size_t)row * QKVN + 2 * DMODEL + ch * 8;
        uint32_t d = sb + (uint32_t)(row * AST + ch * 8) * 2;
        CP_ASYNC16(d,               qh_g + ko);
        CP_ASYNC16(d + KVSZ * 2,    ql_g + ko);
        CP_ASYNC16(d + 2 * KVSZ * 2, qh_g + vo);
        CP_ASYNC16(d + 3 * KVSZ * 2, ql_g + vo);
    }
}

__global__ __launch_bounds__(256) void attn_mma_kernel(
    const __nv_bfloat16* __restrict__ qh_g, const __nv_bfloat16* __restrict__ ql_g,
    __nv_bfloat16* __restrict__ ch_g, __nv_bfloat16* __restrict__ cl_g)
{
    extern __shared__ __nv_bfloat16 asmem[];
    const uint32_t smb = sptr(asmem);
    const uint32_t kvb = smb + 2 * QSZ * 2;

    const int tid = threadIdx.x, wid = tid >> 5, lane = tid & 31;
    const int bh_i = blockIdx.y;
    const int b = bh_i / NHEAD, h = bh_i % NHEAD;
    const int q0 = blockIdx.x * AQ;
    const int hcol = h * DHEAD;
    const size_t bbase = (size_t)b * SEQ * QKVN + hcol;

    // group 0: Q planes
    #pragma unroll
    for (int i = 0; i < 4; i++) {
        int idx = tid + i * 256;                 // 1024 chunks per plane
        int row = idx >> 3, ch = idx & 7;
        size_t o = bbase + (size_t)(q0 + row) * QKVN + ch * 8;
        uint32_t d = smb + (uint32_t)(row * AST + ch * 8) * 2;
        CP_ASYNC16(d, qh_g + o);
        CP_ASYNC16(d + QSZ * 2, ql_g + o);
    }
    CP_COMMIT();
    // groups 1,2: KV stages 0,1
    attn_cp_kv(kvb,               qh_g, ql_g, bbase, tid);
    CP_COMMIT();
    attn_cp_kv(kvb + KVSTG * 2,   qh_g, ql_g, bbase + (size_t)AKT * QKVN, tid);
    CP_COMMIT();

    CP_WAIT(2);          // Q group done
    __syncthreads();

    // hoist Q fragments
    uint32_t qa_h[4][4], qa_l[4][4];
    #pragma unroll
    for (int ks = 0; ks < 4; ks++) {
        int row = wid * 16 + (lane & 15);
        int col = ks * 16 + ((lane >> 4) << 3);
        uint32_t off = (uint32_t)(row * AST + col) * 2;
        ldsm_x4(smb + off, qa_h[ks]);
        ldsm_x4(smb + QSZ * 2 + off, qa_l[ks]);
    }

    float out_acc[8][4];
    #pragma unroll
    for (int nt = 0; nt < 8; nt++)
        #pragma unroll
        for (int r = 0; r < 4; r++) out_acc[nt][r] = 0.f;

    const int ntiles = SEQ / AKT;    // 32
    for (int t = 0; t < ntiles; t++) {
        if (t + 2 <= ntiles) { CP_WAIT(1); } else { CP_WAIT(0); }
        __syncthreads();
        if (t + 2 < ntiles) {
            attn_cp_kv(kvb + ((t + 2) % 3) * KVSTG * 2,
                       qh_g, ql_g, bbase + (size_t)(t + 2) * AKT * QKVN, tid);
            CP_COMMIT();
        }

        const uint32_t st = kvb + (t % 3) * KVSTG * 2;
        const uint32_t kh_b = st, kl_b = st + KVSZ * 2;
        const uint32_t vh_b = st + 2 * KVSZ * 2, vl_b = st + 3 * KVSZ * 2;

        // ---- S = Q K^T ----
        float s_acc[8][4];
        #pragma unroll
        for (int nt = 0; nt < 8; nt++)
            #pragma unroll
            for (int r = 0; r < 4; r++) s_acc[nt][r] = 0.f;

        #pragma unroll
        for (int ks = 0; ks < 4; ks++) {
            const int kof = ks * 16;
            #pragma unroll
            for (int ntp = 0; ntp < 4; ntp++) {
                int n = ntp * 16 + (lane & 15);
                int col = kof + ((lane >> 4) << 3);
                uint32_t off = (uint32_t)(n * AST + col) * 2;
                uint32_t kb_h[4], kb_l[4];
                ldsm_x4(kh_b + off, kb_h);
                ldsm_x4(kl_b + off, kb_l);
                uint32_t b0h[2] = {kb_h[0], kb_h[2]}, b1h[2] = {kb_h[1], kb_h[3]};
                uint32_t b0l[2] = {kb_l[0], kb_l[2]}, b1l[2] = {kb_l[1], kb_l[3]};
                mma_bf16(s_acc[2 * ntp],     qa_h[ks], b0h);
                mma_bf16(s_acc[2 * ntp],     qa_h[ks], b0l);
                mma_bf16(s_acc[2 * ntp],     qa_l[ks], b0h);
                mma_bf16(s_acc[2 * ntp + 1], qa_h[ks], b1h);
                mma_bf16(s_acc[2 * ntp + 1], qa_h[ks], b1l);
                mma_bf16(s_acc[2 * ntp + 1], qa_l[ks], b1h);
            }
        }

        // ---- P = relu(s/8)^2, repack in registers into A-fragments ----
        uint32_t pa_h[4][4], pa_l[4][4];
        #pragma unroll
        for (int nt = 0; nt < 8; nt++) {
            float p[4];
            #pragma unroll
            for (int r = 0; r < 4; r++) {
                float tt = fmaxf(s_acc[nt][r], 0.f);
                p[r] = tt * tt * 0.015625f;
            }
            __nv_bfloat16 h0, l0, h1, l1, h2, l2, h3, l3;
            split1(p[0], h0, l0); split1(p[1], h1, l1);
            split1(p[2], h2, l2); split1(p[3], h3, l3);
            int kt2 = nt >> 1;
            int base_r = (nt & 1) ? 2 : 0;
            pa_h[kt2][base_r]     = pack_bf2(h0, h1);
            pa_h[kt2][base_r + 1] = pack_bf2(h2, h3);
            pa_l[kt2][base_r]     = pack_bf2(l0, l1);
            pa_l[kt2][base_r + 1] = pack_bf2(l2, l3);
        }

        // ---- ctx += P V ----
        #pragma unroll
        for (int kt2 = 0; kt2 < 4; kt2++) {
            int krow = kt2 * 16 + (lane & 15);
            #pragma unroll
            for (int cb = 0; cb < 4; cb++) {
                int col = cb * 16 + ((lane >> 4) << 3);
                uint32_t off = (uint32_t)(krow * AST + col) * 2;
                uint32_t vbh[4], vbl[4];
                ldsm_x4t(vh_b + off, vbh);
                ldsm_x4t(vl_b + off, vbl);
                int nt = cb * 2;
                uint32_t b0h[2] = {vbh[0], vbh[1]}, b1h[2] = {vbh[2], vbh[3]};
                uint32_t b0l[2] = {vbl[0], vbl[1]}, b1l[2] = {vbl[2], vbl[3]};
                mma_bf16(out_acc[nt],     pa_h[kt2], b0h);
                mma_bf16(out_acc[nt],     pa_h[kt2], b0l);
                mma_bf16(out_acc[nt],     pa_l[kt2], b0h);
                mma_bf16(out_acc[nt + 1], pa_h[kt2], b1h);
                mma_bf16(out_acc[nt + 1], pa_h[kt2], b1l);
                mma_bf16(out_acc[nt + 1], pa_l[kt2], b1h);
            }
        }
    }

    // ---- epilogue: ctx hi/lo planes ----
    #pragma unroll
    for (int nt = 0; nt < 8; nt++) {
        int q = q0 + wid * 16 + (lane >> 2);
        int c = hcol + nt * 8 + (lane & 3) * 2;
        __nv_bfloat16 h0, l0, h1, l1;
        split1(out_acc[nt][0], h0, l0); split1(out_acc[nt][1], h1, l1);
        *(uint32_t*)(ch_g + ((size_t)b * SEQ + q) * DMODEL + c) = pack_bf2(h0, h1);
        *(uint32_t*)(cl_g + ((size_t)b * SEQ + q) * DMODEL + c) = pack_bf2(l0, l1);
        split1(out_acc[nt][2], h0, l0); split1(out_acc[nt][3], h1, l1);
        *(uint32_t*)(ch_g + ((size_t)b * SEQ + q + 8) * DMODEL + c) = pack_bf2(h0, h1);
        *(uint32_t*)(cl_g + ((size_t)b * SEQ + q + 8) * DMODEL + c) = pack_bf2(l0, l1);
    }
}

// ================= launch =================
extern "C" void kernel_launch(void* const* d_in, const int* in_sizes, int n_in,
                              void* d_out, int out_size)
{
    const float* x      = (const float*)d_in[0];
    const float* ln1_w  = (const float*)d_in[1];
    const float* W_attn = (const float*)d_in[2];
    const float* b_attn = (const float*)d_in[3];
    const float* W_proj = (const float*)d_in[4];
    const float* b_proj = (const float*)d_in[5];
    const float* ln2_w  = (const float*)d_in[6];
    const float* W_fc1  = (const float*)d_in[7];
    const float* b_fc1  = (const float*)d_in[8];
    const float* W_fc2  = (const float*)d_in[9];
    const float* b_fc2  = (const float*)d_in[10];
    float* out = (float*)d_out;

    __nv_bfloat16 *wah, *wal, *wph, *wpl, *w1h, *w1l, *w2h, *w2l;
    __nv_bfloat16 *hh, *hl, *qh, *ql, *ch, *cl, *f1h, *f1l;
    float* x1;
    cudaGetSymbolAddress((void**)&wah, g_wattn_h); cudaGetSymbolAddress((void**)&wal, g_wattn_l);
    cudaGetSymbolAddress((void**)&wph, g_wproj_h); cudaGetSymbolAddress((void**)&wpl, g_wproj_l);
    cudaGetSymbolAddress((void**)&w1h, g_wfc1_h);  cudaGetSymbolAddress((void**)&w1l, g_wfc1_l);
    cudaGetSymbolAddress((void**)&w2h, g_wfc2_h);  cudaGetSymbolAddress((void**)&w2l, g_wfc2_l);
    cudaGetSymbolAddress((void**)&hh, g_hh);   cudaGetSymbolAddress((void**)&hl, g_hl);
    cudaGetSymbolAddress((void**)&qh, g_qh);   cudaGetSymbolAddress((void**)&ql, g_ql);
    cudaGetSymbolAddress((void**)&ch, g_ch);   cudaGetSymbolAddress((void**)&cl, g_cl);
    cudaGetSymbolAddress((void**)&f1h, g_f1h); cudaGetSymbolAddress((void**)&f1l, g_f1l);
    cudaGetSymbolAddress((void**)&x1, g_x1);

    cudaFuncSetAttribute(gemm_mma_kernel, cudaFuncAttributeMaxDynamicSharedMemorySize, GEMM_SMEM);
    cudaFuncSetAttribute(attn_mma_kernel, cudaFuncAttributeMaxDynamicSharedMemorySize, ATTN_SMEM);

    // weight conversion (fp32 -> bf16 hi/lo planes)
    {
        int n4;
        n4 = DMODEL * QKVN / 4;  convert_kernel<<<(n4 + 255) / 256, 256>>>(W_attn, wah, wal, n4);
        n4 = DMODEL * DMODEL / 4; convert_kernel<<<(n4 + 255) / 256, 256>>>(W_proj, wph, wpl, n4);
        n4 = DMODEL * HID / 4;   convert_kernel<<<(n4 + 255) / 256, 256>>>(W_fc1, w1h, w1l, n4);
        n4 = HID * DMODEL / 4;   convert_kernel<<<(n4 + 255) / 256, 256>>>(W_fc2, w2h, w2l, n4);
    }

    // h = rmsnorm(x, ln1_w) -> planes
    rmsnorm_kernel<<<ROWS, 256>>>(x, ln1_w, hh, hl);
    // qkv = h @ W_attn + b_attn -> planes
    gemm_mma_kernel<<<dim3(QKVN / BN, ROWS / BM), 256, GEMM_SMEM>>>(
        hh, hl, wah, wal, b_attn, nullptr, nullptr, qh, ql, ROWS, QKVN, DMODEL, 0);
    // ctx = attention(qkv) -> planes
    attn_mma_kernel<<<dim3(SEQ / AQ, BATCH * NHEAD), 256, ATTN_SMEM>>>(qh, ql, ch, cl);
    // x1 = x + ctx @ W_proj + b_proj (fp32)
    gemm_mma_kernel<<<dim3(DMODEL / BN, ROWS / BM), 256, GEMM_SMEM>>>(
        ch, cl, wph, wpl, b_proj, x, x1, nullptr, nullptr, ROWS, DMODEL, DMODEL, 0);
    // h = rmsnorm(x1, ln2_w) -> planes
    rmsnorm_kernel<<<ROWS, 256>>>(x1, ln2_w, hh, hl);
    // fc1 = relu(h @ W_fc1 + b_fc1) -> planes
    gemm_mma_kernel<<<dim3(HID / BN, ROWS / BM), 256, GEMM_SMEM>>>(
        hh, hl, w1h, w1l, b_fc1, nullptr, nullptr, f1h, f1l, ROWS, HID, DMODEL, 1);
    // out = x1 + fc1 @ W_fc2 + b_fc2 (fp32)
    gemm_mma_kernel<<<dim3(DMODEL / BN, ROWS / BM), 256, GEMM_SMEM>>>(
        f1h, f1l, w2h, w2l, b_fc2, x1, out, nullptr, nullptr, ROWS, DMODEL, HID, 0);
}

// round 11
// speedup vs baseline: 2.9731x; 1.0346x over previous
#include <cuda_runtime.h>
#include <cuda_bf16.h>
#include <cstdint>

// Problem constants
#define BATCH 2
#define SEQ   2048
#define DMODEL 768
#define NHEAD 12
#define DHEAD 64
#define HID   1536
#define ROWS  (BATCH * SEQ)          // 4096
#define QKVN  (3 * DMODEL)           // 2304
#define EPS   1e-6f

// ---------------- scratch (__device__ globals; no allocs allowed) ----------------
__device__ alignas(16) __nv_bfloat16 g_wattn_h[DMODEL * QKVN], g_wattn_l[DMODEL * QKVN];
__device__ alignas(16) __nv_bfloat16 g_wproj_h[DMODEL * DMODEL], g_wproj_l[DMODEL * DMODEL];
__device__ alignas(16) __nv_bfloat16 g_wfc1_h[DMODEL * HID], g_wfc1_l[DMODEL * HID];
__device__ alignas(16) __nv_bfloat16 g_wfc2_h[HID * DMODEL], g_wfc2_l[HID * DMODEL];
__device__ alignas(16) __nv_bfloat16 g_hh[ROWS * DMODEL], g_hl[ROWS * DMODEL];
__device__ alignas(16) __nv_bfloat16 g_qh[ROWS * QKVN], g_ql[ROWS * QKVN];
__device__ alignas(16) __nv_bfloat16 g_ch[ROWS * DMODEL], g_cl[ROWS * DMODEL];
__device__ alignas(16) __nv_bfloat16 g_f1h[ROWS * HID], g_f1l[ROWS * HID];
__device__ float g_x1[ROWS * DMODEL];

// ================= helpers =================
__device__ __forceinline__ uint32_t sptr(const void* p) {
    return (uint32_t)__cvta_generic_to_shared(p);
}
__device__ __forceinline__ void ldsm_x4(uint32_t addr, uint32_t* r) {
    asm volatile("ldmatrix.sync.aligned.m8n8.x4.shared.b16 {%0,%1,%2,%3}, [%4];"
                 : "=r"(r[0]), "=r"(r[1]), "=r"(r[2]), "=r"(r[3]) : "r"(addr));
}
__device__ __forceinline__ void ldsm_x4t(uint32_t addr, uint32_t* r) {
    asm volatile("ldmatrix.sync.aligned.m8n8.x4.trans.shared.b16 {%0,%1,%2,%3}, [%4];"
                 : "=r"(r[0]), "=r"(r[1]), "=r"(r[2]), "=r"(r[3]) : "r"(addr));
}
__device__ __forceinline__ void mma_bf16(float* c, const uint32_t* a, const uint32_t* b) {
    asm volatile(
        "mma.sync.aligned.m16n8k16.row.col.f32.bf16.bf16.f32 "
        "{%0,%1,%2,%3}, {%4,%5,%6,%7}, {%8,%9}, {%0,%1,%2,%3};"
        : "+f"(c[0]), "+f"(c[1]), "+f"(c[2]), "+f"(c[3])
        : "r"(a[0]), "r"(a[1]), "r"(a[2]), "r"(a[3]), "r"(b[0]), "r"(b[1]));
}
__device__ __forceinline__ uint32_t pack_bf2(__nv_bfloat16 a, __nv_bfloat16 b) {
    return ((uint32_t)__bfloat16_as_ushort(b) << 16) | (uint32_t)__bfloat16_as_ushort(a);
}
__device__ __forceinline__ void split4(float4 v, uint2& h, uint2& l) {
    __nv_bfloat16 hx = __float2bfloat16_rn(v.x), hy = __float2bfloat16_rn(v.y);
    __nv_bfloat16 hz = __float2bfloat16_rn(v.z), hw = __float2bfloat16_rn(v.w);
    __nv_bfloat16 lx = __float2bfloat16_rn(v.x - __bfloat162float(hx));
    __nv_bfloat16 ly = __float2bfloat16_rn(v.y - __bfloat162float(hy));
    __nv_bfloat16 lz = __float2bfloat16_rn(v.z - __bfloat162float(hz));
    __nv_bfloat16 lw = __float2bfloat16_rn(v.w - __bfloat162float(hw));
    h = make_uint2(pack_bf2(hx, hy), pack_bf2(hz, hw));
    l = make_uint2(pack_bf2(lx, ly), pack_bf2(lz, lw));
}
__device__ __forceinline__ void split1(float v, __nv_bfloat16& h, __nv_bfloat16& l) {
    h = __float2bfloat16_rn(v);
    l = __float2bfloat16_rn(v - __bfloat162float(h));
}

#define CP_ASYNC16(dst, src) \
    asm volatile("cp.async.cg.shared.global [%0], [%1], 16;" :: "r"(dst), "l"(src) : "memory")
#define CP_COMMIT() asm volatile("cp.async.commit_group;" ::: "memory")
#define CP_WAIT(N)  asm volatile("cp.async.wait_group %0;" :: "n"(N) : "memory")

// ================= weight conversion: fp32 -> bf16 hi/lo planes =================
__global__ __launch_bounds__(256) void convert_kernel(
    const float* __restrict__ src, __nv_bfloat16* __restrict__ h,
    __nv_bfloat16* __restrict__ l, int n4)
{
    int i = blockIdx.x * 256 + threadIdx.x;
    if (i < n4) {
        float4 v = ((const float4*)src)[i];
        uint2 hh, ll; split4(v, hh, ll);
        ((uint2*)h)[i] = hh;
        ((uint2*)l)[i] = ll;
    }
}

// ================= RMSNorm: fp32 in, bf16 hi/lo planes out =================
__global__ __launch_bounds__(256) void rmsnorm_kernel(
    const float* __restrict__ x, const float* __restrict__ w,
    __nv_bfloat16* __restrict__ oh, __nv_bfloat16* __restrict__ ol)
{
    const int row = blockIdx.x;
    const int tid = threadIdx.x;
    const float* xr = x + (size_t)row * DMODEL;
    float v0 = xr[tid], v1 = xr[tid + 256], v2 = xr[tid + 512];
    float s = v0 * v0 + v1 * v1 + v2 * v2;
    #pragma unroll
    for (int o = 16; o > 0; o >>= 1) s += __shfl_xor_sync(0xFFFFFFFF, s, o);
    __shared__ float wsum[8];
    if ((tid & 31) == 0) wsum[tid >> 5] = s;
    __syncthreads();
    if (tid < 8) {
        float t = wsum[tid];
        #pragma unroll
        for (int o = 4; o > 0; o >>= 1) t += __shfl_xor_sync(0xFF, t, o);
        if (tid == 0) wsum[0] = t;
    }
    __syncthreads();
    const float scale = rsqrtf(wsum[0] * (1.0f / DMODEL) + EPS);
    size_t base = (size_t)row * DMODEL;
    __nv_bfloat16 h, l;
    split1(v0 * scale * w[tid], h, l);       oh[base + tid] = h;       ol[base + tid] = l;
    split1(v1 * scale * w[tid + 256], h, l); oh[base + tid + 256] = h; ol[base + tid + 256] = l;
    split1(v2 * scale * w[tid + 512], h, l); oh[base + tid + 512] = h; ol[base + tid + 512] = l;
}

// ================= tensor-core GEMM (cp.async 3-stage, bf16 hi/lo planes) =================
// Unchanged from the passing R8 kernel.
#define BM 128
#define BN 128
#define BK 32
#define STA 40
#define STB 136
#define ASZ (BM * STA)                 // 5120 halfs per A plane
#define BSZ (BK * STB)                 // 4352 halfs per B plane
#define STAGE_H (2 * ASZ + 2 * BSZ)    // 18944 halfs
#define GEMM_SMEM (3 * STAGE_H * 2)    // 113664 bytes

__device__ __forceinline__ void gemm_cp_stage(
    uint32_t sb, const __nv_bfloat16* Ah_g, const __nv_bfloat16* Al_g,
    const __nv_bfloat16* Bh_g, const __nv_bfloat16* Bl_g,
    int m0, int n0, int k0, int K, int N, int tid)
{
    #pragma unroll
    for (int i = 0; i < 2; i++) {
        int idx = tid + i * 256;                 // 512 chunks per A plane
        int row = idx >> 2, ch = idx & 3;
        uint32_t d = sb + (uint32_t)(row * STA + ch * 8) * 2;
        size_t o = (size_t)(m0 + row) * K + k0 + ch * 8;
        CP_ASYNC16(d, Ah_g + o);
        CP_ASYNC16(d + ASZ * 2, Al_g + o);
    }
    #pragma unroll
    for (int i = 0; i < 2; i++) {
        int idx = tid + i * 256;                 // 512 chunks per B plane
        int row = idx >> 4, ch = idx & 15;
        uint32_t d = sb + (uint32_t)(2 * ASZ + row * STB + ch * 8) * 2;
        size_t o = (size_t)(k0 + row) * N + n0 + ch * 8;
        CP_ASYNC16(d, Bh_g + o);
        CP_ASYNC16(d + BSZ * 2, Bl_g + o);
    }
}

__global__ __launch_bounds__(256, 2) void gemm_mma_kernel(
    const __nv_bfloat16* __restrict__ Ah_g, const __nv_bfloat16* __restrict__ Al_g,
    const __nv_bfloat16* __restrict__ Bh_g, const __nv_bfloat16* __restrict__ Bl_g,
    const float* __restrict__ bias, const float* __restrict__ resid,
    float* __restrict__ Cf, __nv_bfloat16* __restrict__ Ch, __nv_bfloat16* __restrict__ Cl,
    int M, int N, int K, int do_relu)
{
    extern __shared__ __nv_bfloat16 gsm[];
    const uint32_t smb = sptr(gsm);
    const int tid = threadIdx.x, wid = tid >> 5, lane = tid & 31;
    const int warp_m = wid >> 2, warp_n = wid & 3;
    const int m0 = blockIdx.y * BM, n0 = blockIdx.x * BN;

    float acc[4][4][4];
    #pragma unroll
    for (int i = 0; i < 4; i++)
        #pragma unroll
        for (int j = 0; j < 4; j++)
            #pragma unroll
            for (int r = 0; r < 4; r++) acc[i][j][r] = 0.f;

    const int ntiles = K / BK;

    gemm_cp_stage(smb, Ah_g, Al_g, Bh_g, Bl_g, m0, n0, 0, K, N, tid);
    CP_COMMIT();
    gemm_cp_stage(smb + STAGE_H * 2, Ah_g, Al_g, Bh_g, Bl_g, m0, n0, BK, K, N, tid);
    CP_COMMIT();

    for (int t = 0; t < ntiles; t++) {
        if (t + 2 <= ntiles) { CP_WAIT(1); } else { CP_WAIT(0); }
        __syncthreads();
        if (t + 2 < ntiles) {
            gemm_cp_stage(smb + ((t + 2) % 3) * STAGE_H * 2,
                          Ah_g, Al_g, Bh_g, Bl_g, m0, n0, (t + 2) * BK, K, N, tid);
            CP_COMMIT();
        }

        const uint32_t st = smb + (t % 3) * STAGE_H * 2;
        const uint32_t ah_b = st, al_b = st + ASZ * 2;
        const uint32_t bh_b = st + 2 * ASZ * 2, bl_b = bh_b + BSZ * 2;

        #pragma unroll
        for (int ks = 0; ks < 2; ks++) {
            const int kof = ks * 16;
            uint32_t bh[4][2], bl[4][2];
            #pragma unroll
            for (int cb = 0; cb < 2; cb++) {
                int krow = kof + (lane & 15);
                int col = warp_n * 32 + cb * 16 + ((lane >> 4) << 3);
                uint32_t off = (uint32_t)(krow * STB + col) * 2;
                uint32_t tmp[4];
                ldsm_x4t(bh_b + off, tmp);
                bh[2 * cb][0] = tmp[0]; bh[2 * cb][1] = tmp[1];
                bh[2 * cb + 1][0] = tmp[2]; bh[2 * cb + 1][1] = tmp[3];
                ldsm_x4t(bl_b + off, tmp);
                bl[2 * cb][0] = tmp[0]; bl[2 * cb][1] = tmp[1];
                bl[2 * cb + 1][0] = tmp[2]; bl[2 * cb + 1][1] = tmp[3];
            }
            #pragma unroll
            for (int mt = 0; mt < 4; mt++) {
                int row = warp_m * 64 + mt * 16 + (lane & 15);
                int col = kof + ((lane >> 4) << 3);
                uint32_t off = (uint32_t)(row * STA + col) * 2;
                uint32_t ah[4], al[4];
                ldsm_x4(ah_b + off, ah);
                ldsm_x4(al_b + off, al);
                #pragma unroll
                for (int nt = 0; nt < 4; nt++) {
                    mma_bf16(acc[mt][nt], ah, bh[nt]);
                    mma_bf16(acc[mt][nt], ah, bl[nt]);
                    mma_bf16(acc[mt][nt], al, bh[nt]);
                }
            }
        }
    }

    // ---- epilogue ----
    #pragma unroll
    for (int mt = 0; mt < 4; mt++) {
        int r0 = m0 + warp_m * 64 + mt * 16 + (lane >> 2);
        #pragma unroll
        for (int nt = 0; nt < 4; nt++) {
            int c0 = n0 + warp_n * 32 + nt * 8 + (lane & 3) * 2;
            float b0 = bias[c0], b1 = bias[c0 + 1];
            float v0 = acc[mt][nt][0] + b0, v1 = acc[mt][nt][1] + b1;
            float v2 = acc[mt][nt][2] + b0, v3 = acc[mt][nt][3] + b1;
            if (do_relu) {
                v0 = fmaxf(v0, 0.f); v1 = fmaxf(v1, 0.f);
                v2 = fmaxf(v2, 0.f); v3 = fmaxf(v3, 0.f);
            }
            if (resid) {
                const float* rr0 = resid + (size_t)r0 * N + c0;
                const float* rr1 = resid + (size_t)(r0 + 8) * N + c0;
                v0 += rr0[0]; v1 += rr0[1];
                v2 += rr1[0]; v3 += rr1[1];
            }
            if (Cf) {
                *(float2*)(Cf + (size_t)r0 * N + c0)       = make_float2(v0, v1);
                *(float2*)(Cf + (size_t)(r0 + 8) * N + c0) = make_float2(v2, v3);
            }
            if (Ch) {
                __nv_bfloat16 h0, l0, h1, l1;
                split1(v0, h0, l0); split1(v1, h1, l1);
                *(uint32_t*)(Ch + (size_t)r0 * N + c0) = pack_bf2(h0, h1);
                *(uint32_t*)(Cl + (size_t)r0 * N + c0) = pack_bf2(l0, l1);
                split1(v2, h0, l0); split1(v3, h1, l1);
                *(uint32_t*)(Ch + (size_t)(r0 + 8) * N + c0) = pack_bf2(h0, h1);
                *(uint32_t*)(Cl + (size_t)(r0 + 8) * N + c0) = pack_bf2(l0, l1);
            }
        }
    }
}

// ================= tensor-core squared-ReLU attention =================
// Swizzled 128B rows (no padding), 3-stage cp.async pipeline in the PROVEN
// gemm shape (issue-before-compute, one barrier per tile). AKT=32 so that
// Q(32KB) + 3 stages (48KB) = 80KB -> 2 CTAs/SM.
#define AQ  128
#define AKT 32
#define QPL_B  (AQ * 128)              // 16384 bytes per Q plane
#define KVPL_B (AKT * 128)             // 4096 bytes per K/V plane
#define KVSTG_B (4 * KVPL_B)           // 16384 bytes per stage
#define ATTN_SMEM (2 * QPL_B + 3 * KVSTG_B)   // 81920 bytes

// swizzled byte offset of 16B chunk (row, chunk) within a plane
#define ASWZ(r, ch) ((uint32_t)((r) * 128 + ((((ch) ^ ((r) & 7))) << 4)))

__device__ __forceinline__ void attn_cp_kv(
    uint32_t sb, const __nv_bfloat16* qh_g, const __nv_bfloat16* ql_g,
    size_t rowbase, int tid)
{
    // 256 chunks per plane (32 rows x 8 chunks); 256 threads -> 1 chunk, 4 planes
    int r = tid >> 3, ch = tid & 7;
    size_t ko = rowbase + (size_t)r * QKVN + DMODEL + ch * 8;
    size_t vo = rowbase + (size_t)r * QKVN + 2 * DMODEL + ch * 8;
    uint32_t d = sb + ASWZ(r, ch);
    CP_ASYNC16(d,                qh_g + ko);
    CP_ASYNC16(d + KVPL_B,       ql_g + ko);
    CP_ASYNC16(d + 2 * KVPL_B,   qh_g + vo);
    CP_ASYNC16(d + 3 * KVPL_B,   ql_g + vo);
}

__global__ __launch_bounds__(256, 2) void attn_mma_kernel(
    const __nv_bfloat16* __restrict__ qh_g, const __nv_bfloat16* __restrict__ ql_g,
    __nv_bfloat16* __restrict__ ch_g, __nv_bfloat16* __restrict__ cl_g)
{
    extern __shared__ __nv_bfloat16 asmem[];
    const uint32_t smb = sptr(asmem);
    const uint32_t kvb = smb + 2 * QPL_B;

    const int tid = threadIdx.x, wid = tid >> 5, lane = tid & 31;
    const int bh_i = blockIdx.y;
    const int b = bh_i / NHEAD, h = bh_i % NHEAD;
    const int q0 = blockIdx.x * AQ;
    const int hcol = h * DHEAD;
    const size_t bbase = (size_t)b * SEQ * QKVN + hcol;

    // group 0: Q planes (1024 chunks per plane)
    #pragma unroll
    for (int i = 0; i < 4; i++) {
        int idx = tid + i * 256;
        int r = idx >> 3, ch = idx & 7;
        size_t o = bbase + (size_t)(q0 + r) * QKVN + ch * 8;
        uint32_t d = smb + ASWZ(r, ch);
        CP_ASYNC16(d, qh_g + o);
        CP_ASYNC16(d + QPL_B, ql_g + o);
    }
    CP_COMMIT();
    // groups 1,2: KV stages 0,1
    attn_cp_kv(kvb,            qh_g, ql_g, bbase, tid);
    CP_COMMIT();
    attn_cp_kv(kvb + KVSTG_B,  qh_g, ql_g, bbase + (size_t)AKT * QKVN, tid);
    CP_COMMIT();

    float out_acc[8][4];
    #pragma unroll
    for (int nt = 0; nt < 8; nt++)
        #pragma unroll
        for (int r = 0; r < 4; r++) out_acc[nt][r] = 0.f;

    const int ntiles = SEQ / AKT;    // 64
    for (int t = 0; t < ntiles; t++) {
        // pending before wait: {KV(t), KV(t+1)} (+Q at t=0); wait(1) drains through KV(t)
        if (t + 2 <= ntiles) { CP_WAIT(1); } else { CP_WAIT(0); }
        __syncthreads();
        if (t + 2 < ntiles) {
            attn_cp_kv(kvb + ((t + 2) % 3) * KVSTG_B,
                       qh_g, ql_g, bbase + (size_t)(t + 2) * AKT * QKVN, tid);
            CP_COMMIT();
        }

        const uint32_t st = kvb + (t % 3) * KVSTG_B;
        const uint32_t kh_b = st, kl_b = st + KVPL_B;
        const uint32_t vh_b = st + 2 * KVPL_B, vl_b = st + 3 * KVPL_B;

        // ---- S = Q K^T  (per warp: 16 q-rows x 32 keys) ----
        float s_acc[4][4];
        #pragma unroll
        for (int nt = 0; nt < 4; nt++)
            #pragma unroll
            for (int r = 0; r < 4; r++) s_acc[nt][r] = 0.f;

        #pragma unroll
        for (int ks = 0; ks < 4; ks++) {
            const int colc = 2 * ks + (lane >> 4);   // 16B chunk index of d-col
            uint32_t qa_h[4], qa_l[4];
            {
                int row = wid * 16 + (lane & 15);
                uint32_t off = ASWZ(row, colc);
                ldsm_x4(smb + off, qa_h);
                ldsm_x4(smb + QPL_B + off, qa_l);
            }
            #pragma unroll
            for (int ntp = 0; ntp < 2; ntp++) {      // 32 keys = 2 x4 loads
                int n = ntp * 16 + (lane & 15);
                uint32_t off = ASWZ(n, colc);
                uint32_t kb_h[4], kb_l[4];
                ldsm_x4(kh_b + off, kb_h);
                ldsm_x4(kl_b + off, kb_l);
                uint32_t b0h[2] = {kb_h[0], kb_h[2]}, b1h[2] = {kb_h[1], kb_h[3]};
                uint32_t b0l[2] = {kb_l[0], kb_l[2]}, b1l[2] = {kb_l[1], kb_l[3]};
                mma_bf16(s_acc[2 * ntp],     qa_h, b0h);
                mma_bf16(s_acc[2 * ntp],     qa_h, b0l);
                mma_bf16(s_acc[2 * ntp],     qa_l, b0h);
                mma_bf16(s_acc[2 * ntp + 1], qa_h, b1h);
                mma_bf16(s_acc[2 * ntp + 1], qa_h, b1l);
                mma_bf16(s_acc[2 * ntp + 1], qa_l, b1h);
            }
        }

        // ---- P = relu(s/8)^2, repack in registers into A-fragments ----
        uint32_t pa_h[2][4], pa_l[2][4];
        #pragma unroll
        for (int nt = 0; nt < 4; nt++) {
            float p[4];
            #pragma unroll
            for (int r = 0; r < 4; r++) {
                float tt = fmaxf(s_acc[nt][r], 0.f);
                p[r] = tt * tt * 0.015625f;
            }
            __nv_bfloat16 h0, l0, h1, l1, h2, l2, h3, l3;
            split1(p[0], h0, l0); split1(p[1], h1, l1);
            split1(p[2], h2, l2); split1(p[3], h3, l3);
            int kt2 = nt >> 1;
            int base_r = (nt & 1) ? 2 : 0;
            pa_h[kt2][base_r]     = pack_bf2(h0, h1);
            pa_h[kt2][base_r + 1] = pack_bf2(h2, h3);
            pa_l[kt2][base_r]     = pack_bf2(l0, l1);
            pa_l[kt2][base_r + 1] = pack_bf2(l2, l3);
        }

        // ---- ctx += P V  (32 kpos = 2 k16 groups) ----
        #pragma unroll
        for (int kt2 = 0; kt2 < 2; kt2++) {
            int krow = kt2 * 16 + (lane & 15);
            #pragma unroll
            for (int cb = 0; cb < 4; cb++) {
                int colc = 2 * cb + (lane >> 4);
                uint32_t off = ASWZ(krow, colc);
                uint32_t vbh[4], vbl[4];
                ldsm_x4t(vh_b + off, vbh);
                ldsm_x4t(vl_b + off, vbl);
                int nt = cb * 2;
                uint32_t b0h[2] = {vbh[0], vbh[1]}, b1h[2] = {vbh[2], vbh[3]};
                uint32_t b0l[2] = {vbl[0], vbl[1]}, b1l[2] = {vbl[2], vbl[3]};
                mma_bf16(out_acc[nt],     pa_h[kt2], b0h);
                mma_bf16(out_acc[nt],     pa_h[kt2], b0l);
                mma_bf16(out_acc[nt],     pa_l[kt2], b0h);
                mma_bf16(out_acc[nt + 1], pa_h[kt2], b1h);
                mma_bf16(out_acc[nt + 1], pa_h[kt2], b1l);
                mma_bf16(out_acc[nt + 1], pa_l[kt2], b1h);
            }
        }
    }

    // ---- epilogue: ctx hi/lo planes ----
    #pragma unroll
    for (int nt = 0; nt < 8; nt++) {
        int q = q0 + wid * 16 + (lane >> 2);
        int c = hcol + nt * 8 + (lane & 3) * 2;
        __nv_bfloat16 h0, l0, h1, l1;
        split1(out_acc[nt][0], h0, l0); split1(out_acc[nt][1], h1, l1);
        *(uint32_t*)(ch_g + ((size_t)b * SEQ + q) * DMODEL + c) = pack_bf2(h0, h1);
        *(uint32_t*)(cl_g + ((size_t)b * SEQ + q) * DMODEL + c) = pack_bf2(l0, l1);
        split1(out_acc[nt][2], h0, l0); split1(out_acc[nt][3], h1, l1);
        *(uint32_t*)(ch_g + ((size_t)b * SEQ + q + 8) * DMODEL + c) = pack_bf2(h0, h1);
        *(uint32_t*)(cl_g + ((size_t)b * SEQ + q + 8) * DMODEL + c) = pack_bf2(l0, l1);
    }
}

// ================= launch =================
extern "C" void kernel_launch(void* const* d_in, const int* in_sizes, int n_in,
                              void* d_out, int out_size)
{
    const float* x      = (const float*)d_in[0];
    const float* ln1_w  = (const float*)d_in[1];
    const float* W_attn = (const float*)d_in[2];
    const float* b_attn = (const float*)d_in[3];
    const float* W_proj = (const float*)d_in[4];
    const float* b_proj = (const float*)d_in[5];
    const float* ln2_w  = (const float*)d_in[6];
    const float* W_fc1  = (const float*)d_in[7];
    const float* b_fc1  = (const float*)d_in[8];
    const float* W_fc2  = (const float*)d_in[9];
    const float* b_fc2  = (const float*)d_in[10];
    float* out = (float*)d_out;

    __nv_bfloat16 *wah, *wal, *wph, *wpl, *w1h, *w1l, *w2h, *w2l;
    __nv_bfloat16 *hh, *hl, *qh, *ql, *ch, *cl, *f1h, *f1l;
    float* x1;
    cudaGetSymbolAddress((void**)&wah, g_wattn_h); cudaGetSymbolAddress((void**)&wal, g_wattn_l);
    cudaGetSymbolAddress((void**)&wph, g_wproj_h); cudaGetSymbolAddress((void**)&wpl, g_wproj_l);
    cudaGetSymbolAddress((void**)&w1h, g_wfc1_h);  cudaGetSymbolAddress((void**)&w1l, g_wfc1_l);
    cudaGetSymbolAddress((void**)&w2h, g_wfc2_h);  cudaGetSymbolAddress((void**)&w2l, g_wfc2_l);
    cudaGetSymbolAddress((void**)&hh, g_hh);   cudaGetSymbolAddress((void**)&hl, g_hl);
    cudaGetSymbolAddress((void**)&qh, g_qh);   cudaGetSymbolAddress((void**)&ql, g_ql);
    cudaGetSymbolAddress((void**)&ch, g_ch);   cudaGetSymbolAddress((void**)&cl, g_cl);
    cudaGetSymbolAddress((void**)&f1h, g_f1h); cudaGetSymbolAddress((void**)&f1l, g_f1l);
    cudaGetSymbolAddress((void**)&x1, g_x1);

    cudaFuncSetAttribute(gemm_mma_kernel, cudaFuncAttributeMaxDynamicSharedMemorySize, GEMM_SMEM);
    cudaFuncSetAttribute(attn_mma_kernel, cudaFuncAttributeMaxDynamicSharedMemorySize, ATTN_SMEM);

    // weight conversion (fp32 -> bf16 hi/lo planes)
    {
        int n4;
        n4 = DMODEL * QKVN / 4;  convert_kernel<<<(n4 + 255) / 256, 256>>>(W_attn, wah, wal, n4);
        n4 = DMODEL * DMODEL / 4; convert_kernel<<<(n4 + 255) / 256, 256>>>(W_proj, wph, wpl, n4);
        n4 = DMODEL * HID / 4;   convert_kernel<<<(n4 + 255) / 256, 256>>>(W_fc1, w1h, w1l, n4);
        n4 = HID * DMODEL / 4;   convert_kernel<<<(n4 + 255) / 256, 256>>>(W_fc2, w2h, w2l, n4);
    }

    // h = rmsnorm(x, ln1_w) -> planes
    rmsnorm_kernel<<<ROWS, 256>>>(x, ln1_w, hh, hl);
    // qkv = h @ W_attn + b_attn -> planes
    gemm_mma_kernel<<<dim3(QKVN / BN, ROWS / BM), 256, GEMM_SMEM>>>(
        hh, hl, wah, wal, b_attn, nullptr, nullptr, qh, ql, ROWS, QKVN, DMODEL, 0);
    // ctx = attention(qkv) -> planes
    attn_mma_kernel<<<dim3(SEQ / AQ, BATCH * NHEAD), 256, ATTN_SMEM>>>(qh, ql, ch, cl);
    // x1 = x + ctx @ W_proj + b_proj (fp32)
    gemm_mma_kernel<<<dim3(DMODEL / BN, ROWS / BM), 256, GEMM_SMEM>>>(
        ch, cl, wph, wpl, b_proj, x, x1, nullptr, nullptr, ROWS, DMODEL, DMODEL, 0);
    // h = rmsnorm(x1, ln2_w) -> planes
    rmsnorm_kernel<<<ROWS, 256>>>(x1, ln2_w, hh, hl);
    // fc1 = relu(h @ W_fc1 + b_fc1) -> planes
    gemm_mma_kernel<<<dim3(HID / BN, ROWS / BM), 256, GEMM_SMEM>>>(
        hh, hl, w1h, w1l, b_fc1, nullptr, nullptr, f1h, f1l, ROWS, HID, DMODEL, 1);
    // out = x1 + fc1 @ W_fc2 + b_fc2 (fp32)
    gemm_mma_kernel<<<dim3(DMODEL / BN, ROWS / BM), 256, GEMM_SMEM>>>(
        f1h, f1l, w2h, w2l, b_fc2, x1, out, nullptr, nullptr, ROWS, DMODEL, HID, 0);
}

// round 12
// speedup vs baseline: 3.0504x; 1.0260x over previous
#include <cuda_runtime.h>
#include <cuda_bf16.h>
#include <cstdint>

// Problem constants
#define BATCH 2
#define SEQ   2048
#define DMODEL 768
#define NHEAD 12
#define DHEAD 64
#define HID   1536
#define ROWS  (BATCH * SEQ)          // 4096
#define QKVN  (3 * DMODEL)           // 2304
#define EPS   1e-6f
#define PGRID 296                    // 2 CTAs x 148 SMs

// ---------------- scratch (__device__ globals; no allocs allowed) ----------------
__device__ alignas(16) __nv_bfloat16 g_wattn_h[DMODEL * QKVN], g_wattn_l[DMODEL * QKVN];
__device__ alignas(16) __nv_bfloat16 g_wproj_h[DMODEL * DMODEL], g_wproj_l[DMODEL * DMODEL];
__device__ alignas(16) __nv_bfloat16 g_wfc1_h[DMODEL * HID], g_wfc1_l[DMODEL * HID];
__device__ alignas(16) __nv_bfloat16 g_wfc2_h[HID * DMODEL], g_wfc2_l[HID * DMODEL];
__device__ alignas(16) __nv_bfloat16 g_hh[ROWS * DMODEL], g_hl[ROWS * DMODEL];
__device__ alignas(16) __nv_bfloat16 g_qh[ROWS * QKVN], g_ql[ROWS * QKVN];
__device__ alignas(16) __nv_bfloat16 g_ch[ROWS * DMODEL], g_cl[ROWS * DMODEL];
__device__ alignas(16) __nv_bfloat16 g_f1h[ROWS * HID], g_f1l[ROWS * HID];
__device__ float g_x1[ROWS * DMODEL];

// ================= helpers =================
__device__ __forceinline__ uint32_t sptr(const void* p) {
    return (uint32_t)__cvta_generic_to_shared(p);
}
__device__ __forceinline__ void ldsm_x4(uint32_t addr, uint32_t* r) {
    asm volatile("ldmatrix.sync.aligned.m8n8.x4.shared.b16 {%0,%1,%2,%3}, [%4];"
                 : "=r"(r[0]), "=r"(r[1]), "=r"(r[2]), "=r"(r[3]) : "r"(addr));
}
__device__ __forceinline__ void ldsm_x4t(uint32_t addr, uint32_t* r) {
    asm volatile("ldmatrix.sync.aligned.m8n8.x4.trans.shared.b16 {%0,%1,%2,%3}, [%4];"
                 : "=r"(r[0]), "=r"(r[1]), "=r"(r[2]), "=r"(r[3]) : "r"(addr));
}
__device__ __forceinline__ void mma_bf16(float* c, const uint32_t* a, const uint32_t* b) {
    asm volatile(
        "mma.sync.aligned.m16n8k16.row.col.f32.bf16.bf16.f32 "
        "{%0,%1,%2,%3}, {%4,%5,%6,%7}, {%8,%9}, {%0,%1,%2,%3};"
        : "+f"(c[0]), "+f"(c[1]), "+f"(c[2]), "+f"(c[3])
        : "r"(a[0]), "r"(a[1]), "r"(a[2]), "r"(a[3]), "r"(b[0]), "r"(b[1]));
}
__device__ __forceinline__ uint32_t pack_bf2(__nv_bfloat16 a, __nv_bfloat16 b) {
    return ((uint32_t)__bfloat16_as_ushort(b) << 16) | (uint32_t)__bfloat16_as_ushort(a);
}
__device__ __forceinline__ void split4(float4 v, uint2& h, uint2& l) {
    __nv_bfloat16 hx = __float2bfloat16_rn(v.x), hy = __float2bfloat16_rn(v.y);
    __nv_bfloat16 hz = __float2bfloat16_rn(v.z), hw = __float2bfloat16_rn(v.w);
    __nv_bfloat16 lx = __float2bfloat16_rn(v.x - __bfloat162float(hx));
    __nv_bfloat16 ly = __float2bfloat16_rn(v.y - __bfloat162float(hy));
    __nv_bfloat16 lz = __float2bfloat16_rn(v.z - __bfloat162float(hz));
    __nv_bfloat16 lw = __float2bfloat16_rn(v.w - __bfloat162float(hw));
    h = make_uint2(pack_bf2(hx, hy), pack_bf2(hz, hw));
    l = make_uint2(pack_bf2(lx, ly), pack_bf2(lz, lw));
}
__device__ __forceinline__ void split1(float v, __nv_bfloat16& h, __nv_bfloat16& l) {
    h = __float2bfloat16_rn(v);
    l = __float2bfloat16_rn(v - __bfloat162float(h));
}

#define CP_ASYNC16(dst, src) \
    asm volatile("cp.async.cg.shared.global [%0], [%1], 16;" :: "r"(dst), "l"(src) : "memory")
#define CP_COMMIT() asm volatile("cp.async.commit_group;" ::: "memory")
#define CP_WAIT(N)  asm volatile("cp.async.wait_group %0;" :: "n"(N) : "memory")

// ================= merged weight conversion: fp32 -> bf16 hi/lo planes =================
#define CV_N0 (DMODEL * QKVN / 4)      // 442368
#define CV_N1 (DMODEL * DMODEL / 4)    // 147456
#define CV_N2 (DMODEL * HID / 4)       // 294912
#define CV_N3 (HID * DMODEL / 4)       // 294912
#define CV_TOT (CV_N0 + CV_N1 + CV_N2 + CV_N3)

__global__ __launch_bounds__(256) void convert_all_kernel(
    const float* __restrict__ s0, __nv_bfloat16* __restrict__ h0, __nv_bfloat16* __restrict__ l0,
    const float* __restrict__ s1, __nv_bfloat16* __restrict__ h1, __nv_bfloat16* __restrict__ l1,
    const float* __restrict__ s2, __nv_bfloat16* __restrict__ h2, __nv_bfloat16* __restrict__ l2,
    const float* __restrict__ s3, __nv_bfloat16* __restrict__ h3, __nv_bfloat16* __restrict__ l3)
{
    int i = blockIdx.x * 256 + threadIdx.x;
    const float* s; __nv_bfloat16* h; __nv_bfloat16* l;
    if (i < CV_N0)                    { s = s0; h = h0; l = l0; }
    else if (i < CV_N0 + CV_N1)       { s = s1; h = h1; l = l1; i -= CV_N0; }
    else if (i < CV_N0 + CV_N1 + CV_N2){ s = s2; h = h2; l = l2; i -= CV_N0 + CV_N1; }
    else if (i < CV_TOT)              { s = s3; h = h3; l = l3; i -= CV_N0 + CV_N1 + CV_N2; }
    else return;
    float4 v = ((const float4*)s)[i];
    uint2 hh, ll; split4(v, hh, ll);
    ((uint2*)h)[i] = hh;
    ((uint2*)l)[i] = ll;
}

// ================= RMSNorm: fp32 in, bf16 hi/lo planes out =================
__global__ __launch_bounds__(256) void rmsnorm_kernel(
    const float* __restrict__ x, const float* __restrict__ w,
    __nv_bfloat16* __restrict__ oh, __nv_bfloat16* __restrict__ ol)
{
    const int row = blockIdx.x;
    const int tid = threadIdx.x;
    const float* xr = x + (size_t)row * DMODEL;
    float v0 = xr[tid], v1 = xr[tid + 256], v2 = xr[tid + 512];
    float s = v0 * v0 + v1 * v1 + v2 * v2;
    #pragma unroll
    for (int o = 16; o > 0; o >>= 1) s += __shfl_xor_sync(0xFFFFFFFF, s, o);
    __shared__ float wsum[8];
    if ((tid & 31) == 0) wsum[tid >> 5] = s;
    __syncthreads();
    if (tid < 8) {
        float t = wsum[tid];
        #pragma unroll
        for (int o = 4; o > 0; o >>= 1) t += __shfl_xor_sync(0xFF, t, o);
        if (tid == 0) wsum[0] = t;
    }
    __syncthreads();
    const float scale = rsqrtf(wsum[0] * (1.0f / DMODEL) + EPS);
    size_t base = (size_t)row * DMODEL;
    __nv_bfloat16 h, l;
    split1(v0 * scale * w[tid], h, l);       oh[base + tid] = h;       ol[base + tid] = l;
    split1(v1 * scale * w[tid + 256], h, l); oh[base + tid + 256] = h; ol[base + tid + 256] = l;
    split1(v2 * scale * w[tid + 512], h, l); oh[base + tid + 512] = h; ol[base + tid + 512] = l;
}

// ================= persistent tensor-core GEMM (cp.async 3-stage) =================
#define BM 128
#define BN 128
#define BK 32
#define STA 40
#define STB 136
#define ASZ (BM * STA)                 // 5120 halfs per A plane
#define BSZ (BK * STB)                 // 4352 halfs per B plane
#define STAGE_H (2 * ASZ + 2 * BSZ)    // 18944 halfs
#define GEMM_SMEM (3 * STAGE_H * 2)    // 113664 bytes

__device__ __forceinline__ void gemm_cp_stage(
    uint32_t sb, const __nv_bfloat16* Ah_g, const __nv_bfloat16* Al_g,
    const __nv_bfloat16* Bh_g, const __nv_bfloat16* Bl_g,
    int m0, int n0, int k0, int K, int N, int tid)
{
    #pragma unroll
    for (int i = 0; i < 2; i++) {
        int idx = tid + i * 256;                 // 512 chunks per A plane
        int row = idx >> 2, ch = idx & 3;
        uint32_t d = sb + (uint32_t)(row * STA + ch * 8) * 2;
        size_t o = (size_t)(m0 + row) * K + k0 + ch * 8;
        CP_ASYNC16(d, Ah_g + o);
        CP_ASYNC16(d + ASZ * 2, Al_g + o);
    }
    #pragma unroll
    for (int i = 0; i < 2; i++) {
        int idx = tid + i * 256;                 // 512 chunks per B plane
        int row = idx >> 4, ch = idx & 15;
        uint32_t d = sb + (uint32_t)(2 * ASZ + row * STB + ch * 8) * 2;
        size_t o = (size_t)(k0 + row) * N + n0 + ch * 8;
        CP_ASYNC16(d, Bh_g + o);
        CP_ASYNC16(d + BSZ * 2, Bl_g + o);
    }
}

__global__ __launch_bounds__(256, 2) void gemm_mma_kernel(
    const __nv_bfloat16* __restrict__ Ah_g, const __nv_bfloat16* __restrict__ Al_g,
    const __nv_bfloat16* __restrict__ Bh_g, const __nv_bfloat16* __restrict__ Bl_g,
    const float* __restrict__ bias, const float* __restrict__ resid,
    float* __restrict__ Cf, __nv_bfloat16* __restrict__ Ch, __nv_bfloat16* __restrict__ Cl,
    int M, int N, int K, int do_relu)
{
    extern __shared__ __nv_bfloat16 gsm[];
    const uint32_t smb = sptr(gsm);
    const int tid = threadIdx.x, wid = tid >> 5, lane = tid & 31;
    const int warp_m = wid >> 2, warp_n = wid & 3;
    const int nxt = N / BN;
    const int ntot = (M / BM) * nxt;
    const int ntiles = K / BK;

    for (int tile = blockIdx.x; tile < ntot; tile += gridDim.x) {
        const int m0 = (tile / nxt) * BM, n0 = (tile % nxt) * BN;

        float acc[4][4][4];
        #pragma unroll
        for (int i = 0; i < 4; i++)
            #pragma unroll
            for (int j = 0; j < 4; j++)
                #pragma unroll
                for (int r = 0; r < 4; r++) acc[i][j][r] = 0.f;

        gemm_cp_stage(smb, Ah_g, Al_g, Bh_g, Bl_g, m0, n0, 0, K, N, tid);
        CP_COMMIT();
        gemm_cp_stage(smb + STAGE_H * 2, Ah_g, Al_g, Bh_g, Bl_g, m0, n0, BK, K, N, tid);
        CP_COMMIT();

        for (int t = 0; t < ntiles; t++) {
            if (t + 2 <= ntiles) { CP_WAIT(1); } else { CP_WAIT(0); }
            __syncthreads();
            if (t + 2 < ntiles) {
                gemm_cp_stage(smb + ((t + 2) % 3) * STAGE_H * 2,
                              Ah_g, Al_g, Bh_g, Bl_g, m0, n0, (t + 2) * BK, K, N, tid);
                CP_COMMIT();
            }

            const uint32_t st = smb + (t % 3) * STAGE_H * 2;
            const uint32_t ah_b = st, al_b = st + ASZ * 2;
            const uint32_t bh_b = st + 2 * ASZ * 2, bl_b = bh_b + BSZ * 2;

            #pragma unroll
            for (int ks = 0; ks < 2; ks++) {
                const int kof = ks * 16;
                uint32_t bh[4][2], bl[4][2];
                #pragma unroll
                for (int cb = 0; cb < 2; cb++) {
                    int krow = kof + (lane & 15);
                    int col = warp_n * 32 + cb * 16 + ((lane >> 4) << 3);
                    uint32_t off = (uint32_t)(krow * STB + col) * 2;
                    uint32_t tmp[4];
                    ldsm_x4t(bh_b + off, tmp);
                    bh[2 * cb][0] = tmp[0]; bh[2 * cb][1] = tmp[1];
                    bh[2 * cb + 1][0] = tmp[2]; bh[2 * cb + 1][1] = tmp[3];
                    ldsm_x4t(bl_b + off, tmp);
                    bl[2 * cb][0] = tmp[0]; bl[2 * cb][1] = tmp[1];
                    bl[2 * cb + 1][0] = tmp[2]; bl[2 * cb + 1][1] = tmp[3];
                }
                #pragma unroll
                for (int mt = 0; mt < 4; mt++) {
                    int row = warp_m * 64 + mt * 16 + (lane & 15);
                    int col = kof + ((lane >> 4) << 3);
                    uint32_t off = (uint32_t)(row * STA + col) * 2;
                    uint32_t ah[4], al[4];
                    ldsm_x4(ah_b + off, ah);
                    ldsm_x4(al_b + off, al);
                    #pragma unroll
                    for (int nt = 0; nt < 4; nt++) {
                        mma_bf16(acc[mt][nt], ah, bh[nt]);
                        mma_bf16(acc[mt][nt], ah, bl[nt]);
                        mma_bf16(acc[mt][nt], al, bh[nt]);
                    }
                }
            }
        }

        // ---- epilogue ----
        #pragma unroll
        for (int mt = 0; mt < 4; mt++) {
            int r0 = m0 + warp_m * 64 + mt * 16 + (lane >> 2);
            #pragma unroll
            for (int nt = 0; nt < 4; nt++) {
                int c0 = n0 + warp_n * 32 + nt * 8 + (lane & 3) * 2;
                float b0 = bias[c0], b1 = bias[c0 + 1];
                float v0 = acc[mt][nt][0] + b0, v1 = acc[mt][nt][1] + b1;
                float v2 = acc[mt][nt][2] + b0, v3 = acc[mt][nt][3] + b1;
                if (do_relu) {
                    v0 = fmaxf(v0, 0.f); v1 = fmaxf(v1, 0.f);
                    v2 = fmaxf(v2, 0.f); v3 = fmaxf(v3, 0.f);
                }
                if (resid) {
                    const float* rr0 = resid + (size_t)r0 * N + c0;
                    const float* rr1 = resid + (size_t)(r0 + 8) * N + c0;
                    v0 += rr0[0]; v1 += rr0[1];
                    v2 += rr1[0]; v3 += rr1[1];
                }
                if (Cf) {
                    *(float2*)(Cf + (size_t)r0 * N + c0)       = make_float2(v0, v1);
                    *(float2*)(Cf + (size_t)(r0 + 8) * N + c0) = make_float2(v2, v3);
                }
                if (Ch) {
                    __nv_bfloat16 h0, l0, h1, l1;
                    split1(v0, h0, l0); split1(v1, h1, l1);
                    *(uint32_t*)(Ch + (size_t)r0 * N + c0) = pack_bf2(h0, h1);
                    *(uint32_t*)(Cl + (size_t)r0 * N + c0) = pack_bf2(l0, l1);
                    split1(v2, h0, l0); split1(v3, h1, l1);
                    *(uint32_t*)(Ch + (size_t)(r0 + 8) * N + c0) = pack_bf2(h0, h1);
                    *(uint32_t*)(Cl + (size_t)(r0 + 8) * N + c0) = pack_bf2(l0, l1);
                }
            }
        }
        __syncthreads();   // protect smem stages before next tile's prologue
    }
}

// ================= persistent tensor-core squared-ReLU attention =================
#define AQ  128
#define AKT 32
#define QPL_B  (AQ * 128)              // 16384 bytes per Q plane
#define KVPL_B (AKT * 128)             // 4096 bytes per K/V plane
#define KVSTG_B (4 * KVPL_B)           // 16384 bytes per stage
#define ATTN_SMEM (2 * QPL_B + 3 * KVSTG_B)   // 81920 bytes

#define ASWZ(r, ch) ((uint32_t)((r) * 128 + ((((ch) ^ ((r) & 7))) << 4)))

__device__ __forceinline__ void attn_cp_kv(
    uint32_t sb, const __nv_bfloat16* qh_g, const __nv_bfloat16* ql_g,
    size_t rowbase, int tid)
{
    int r = tid >> 3, ch = tid & 7;
    size_t ko = rowbase + (size_t)r * QKVN + DMODEL + ch * 8;
    size_t vo = rowbase + (size_t)r * QKVN + 2 * DMODEL + ch * 8;
    uint32_t d = sb + ASWZ(r, ch);
    CP_ASYNC16(d,                qh_g + ko);
    CP_ASYNC16(d + KVPL_B,       ql_g + ko);
    CP_ASYNC16(d + 2 * KVPL_B,   qh_g + vo);
    CP_ASYNC16(d + 3 * KVPL_B,   ql_g + vo);
}

__global__ __launch_bounds__(256, 2) void attn_mma_kernel(
    const __nv_bfloat16* __restrict__ qh_g, const __nv_bfloat16* __restrict__ ql_g,
    __nv_bfloat16* __restrict__ ch_g, __nv_bfloat16* __restrict__ cl_g)
{
    extern __shared__ __nv_bfloat16 asmem[];
    const uint32_t smb = sptr(asmem);
    const uint32_t kvb = smb + 2 * QPL_B;

    const int tid = threadIdx.x, wid = tid >> 5, lane = tid & 31;
    const int nwi = (SEQ / AQ) * BATCH * NHEAD;   // 16 * 24 = 384

    for (int wi = blockIdx.x; wi < nwi; wi += gridDim.x) {
        const int q0 = (wi & 15) * AQ;
        const int bh_i = wi >> 4;
        const int b = bh_i / NHEAD, h = bh_i % NHEAD;
        const int hcol = h * DHEAD;
        const size_t bbase = (size_t)b * SEQ * QKVN + hcol;

        // group 0: Q planes
        #pragma unroll
        for (int i = 0; i < 4; i++) {
            int idx = tid + i * 256;
            int r = idx >> 3, ch = idx & 7;
            size_t o = bbase + (size_t)(q0 + r) * QKVN + ch * 8;
            uint32_t d = smb + ASWZ(r, ch);
            CP_ASYNC16(d, qh_g + o);
            CP_ASYNC16(d + QPL_B, ql_g + o);
        }
        CP_COMMIT();
        // groups 1,2: KV stages 0,1
        attn_cp_kv(kvb,            qh_g, ql_g, bbase, tid);
        CP_COMMIT();
        attn_cp_kv(kvb + KVSTG_B,  qh_g, ql_g, bbase + (size_t)AKT * QKVN, tid);
        CP_COMMIT();

        float out_acc[8][4];
        #pragma unroll
        for (int nt = 0; nt < 8; nt++)
            #pragma unroll
            for (int r = 0; r < 4; r++) out_acc[nt][r] = 0.f;

        const int ntiles = SEQ / AKT;    // 64
        for (int t = 0; t < ntiles; t++) {
            if (t + 2 <= ntiles) { CP_WAIT(1); } else { CP_WAIT(0); }
            __syncthreads();
            if (t + 2 < ntiles) {
                attn_cp_kv(kvb + ((t + 2) % 3) * KVSTG_B,
                           qh_g, ql_g, bbase + (size_t)(t + 2) * AKT * QKVN, tid);
                CP_COMMIT();
            }

            const uint32_t st = kvb + (t % 3) * KVSTG_B;
            const uint32_t kh_b = st, kl_b = st + KVPL_B;
            const uint32_t vh_b = st + 2 * KVPL_B, vl_b = st + 3 * KVPL_B;

            // ---- S = Q K^T ----
            float s_acc[4][4];
            #pragma unroll
            for (int nt = 0; nt < 4; nt++)
                #pragma unroll
                for (int r = 0; r < 4; r++) s_acc[nt][r] = 0.f;

            #pragma unroll
            for (int ks = 0; ks < 4; ks++) {
                const int colc = 2 * ks + (lane >> 4);
                uint32_t qa_h[4], qa_l[4];
                {
                    int row = wid * 16 + (lane & 15);
                    uint32_t off = ASWZ(row, colc);
                    ldsm_x4(smb + off, qa_h);
                    ldsm_x4(smb + QPL_B + off, qa_l);
                }
                #pragma unroll
                for (int ntp = 0; ntp < 2; ntp++) {
                    int n = ntp * 16 + (lane & 15);
                    uint32_t off = ASWZ(n, colc);
                    uint32_t kb_h[4], kb_l[4];
                    ldsm_x4(kh_b + off, kb_h);
                    ldsm_x4(kl_b + off, kb_l);
                    uint32_t b0h[2] = {kb_h[0], kb_h[2]}, b1h[2] = {kb_h[1], kb_h[3]};
                    uint32_t b0l[2] = {kb_l[0], kb_l[2]}, b1l[2] = {kb_l[1], kb_l[3]};
                    mma_bf16(s_acc[2 * ntp],     qa_h, b0h);
                    mma_bf16(s_acc[2 * ntp],     qa_h, b0l);
                    mma_bf16(s_acc[2 * ntp],     qa_l, b0h);
                    mma_bf16(s_acc[2 * ntp + 1], qa_h, b1h);
                    mma_bf16(s_acc[2 * ntp + 1], qa_h, b1l);
                    mma_bf16(s_acc[2 * ntp + 1], qa_l, b1h);
                }
            }

            // ---- P = relu(s/8)^2, repack into A-fragments ----
            uint32_t pa_h[2][4], pa_l[2][4];
            #pragma unroll
            for (int nt = 0; nt < 4; nt++) {
                float p[4];
                #pragma unroll
                for (int r = 0; r < 4; r++) {
                    float tt = fmaxf(s_acc[nt][r], 0.f);
                    p[r] = tt * tt * 0.015625f;
                }
                __nv_bfloat16 h0, l0, h1, l1, h2, l2, h3, l3;
                split1(p[0], h0, l0); split1(p[1], h1, l1);
                split1(p[2], h2, l2); split1(p[3], h3, l3);
                int kt2 = nt >> 1;
                int base_r = (nt & 1) ? 2 : 0;
                pa_h[kt2][base_r]     = pack_bf2(h0, h1);
                pa_h[kt2][base_r + 1] = pack_bf2(h2, h3);
                pa_l[kt2][base_r]     = pack_bf2(l0, l1);
                pa_l[kt2][base_r + 1] = pack_bf2(l2, l3);
            }

            // ---- ctx += P V ----
            #pragma unroll
            for (int kt2 = 0; kt2 < 2; kt2++) {
                int krow = kt2 * 16 + (lane & 15);
                #pragma unroll
                for (int cb = 0; cb < 4; cb++) {
                    int colc = 2 * cb + (lane >> 4);
                    uint32_t off = ASWZ(krow, colc);
                    uint32_t vbh[4], vbl[4];
                    ldsm_x4t(vh_b + off, vbh);
                    ldsm_x4t(vl_b + off, vbl);
                    int nt = cb * 2;
                    uint32_t b0h[2] = {vbh[0], vbh[1]}, b1h[2] = {vbh[2], vbh[3]};
                    uint32_t b0l[2] = {vbl[0], vbl[1]}, b1l[2] = {vbl[2], vbl[3]};
                    mma_bf16(out_acc[nt],     pa_h[kt2], b0h);
                    mma_bf16(out_acc[nt],     pa_h[kt2], b0l);
                    mma_bf16(out_acc[nt],     pa_l[kt2], b0h);
                    mma_bf16(out_acc[nt + 1], pa_h[kt2], b1h);
                    mma_bf16(out_acc[nt + 1], pa_h[kt2], b1l);
                    mma_bf16(out_acc[nt + 1], pa_l[kt2], b1h);
                }
            }
        }

        // ---- epilogue: ctx hi/lo planes ----
        #pragma unroll
        for (int nt = 0; nt < 8; nt++) {
            int q = q0 + wid * 16 + (lane >> 2);
            int c = hcol + nt * 8 + (lane & 3) * 2;
            __nv_bfloat16 h0, l0, h1, l1;
            split1(out_acc[nt][0], h0, l0); split1(out_acc[nt][1], h1, l1);
            *(uint32_t*)(ch_g + ((size_t)b * SEQ + q) * DMODEL + c) = pack_bf2(h0, h1);
            *(uint32_t*)(cl_g + ((size_t)b * SEQ + q) * DMODEL + c) = pack_bf2(l0, l1);
            split1(out_acc[nt][2], h0, l0); split1(out_acc[nt][3], h1, l1);
            *(uint32_t*)(ch_g + ((size_t)b * SEQ + q + 8) * DMODEL + c) = pack_bf2(h0, h1);
            *(uint32_t*)(cl_g + ((size_t)b * SEQ + q + 8) * DMODEL + c) = pack_bf2(l0, l1);
        }
        __syncthreads();   // REQUIRED: next item's Q load must not race final S reads
    }
}

// ================= launch =================
extern "C" void kernel_launch(void* const* d_in, const int* in_sizes, int n_in,
                              void* d_out, int out_size)
{
    const float* x      = (const float*)d_in[0];
    const float* ln1_w  = (const float*)d_in[1];
    const float* W_attn = (const float*)d_in[2];
    const float* b_attn = (const float*)d_in[3];
    const float* W_proj = (const float*)d_in[4];
    const float* b_proj = (const float*)d_in[5];
    const float* ln2_w  = (const float*)d_in[6];
    const float* W_fc1  = (const float*)d_in[7];
    const float* b_fc1  = (const float*)d_in[8];
    const float* W_fc2  = (const float*)d_in[9];
    const float* b_fc2  = (const float*)d_in[10];
    float* out = (float*)d_out;

    __nv_bfloat16 *wah, *wal, *wph, *wpl, *w1h, *w1l, *w2h, *w2l;
    __nv_bfloat16 *hh, *hl, *qh, *ql, *ch, *cl, *f1h, *f1l;
    float* x1;
    cudaGetSymbolAddress((void**)&wah, g_wattn_h); cudaGetSymbolAddress((void**)&wal, g_wattn_l);
    cudaGetSymbolAddress((void**)&wph, g_wproj_h); cudaGetSymbolAddress((void**)&wpl, g_wproj_l);
    cudaGetSymbolAddress((void**)&w1h, g_wfc1_h);  cudaGetSymbolAddress((void**)&w1l, g_wfc1_l);
    cudaGetSymbolAddress((void**)&w2h, g_wfc2_h);  cudaGetSymbolAddress((void**)&w2l, g_wfc2_l);
    cudaGetSymbolAddress((void**)&hh, g_hh);   cudaGetSymbolAddress((void**)&hl, g_hl);
    cudaGetSymbolAddress((void**)&qh, g_qh);   cudaGetSymbolAddress((void**)&ql, g_ql);
    cudaGetSymbolAddress((void**)&ch, g_ch);   cudaGetSymbolAddress((void**)&cl, g_cl);
    cudaGetSymbolAddress((void**)&f1h, g_f1h); cudaGetSymbolAddress((void**)&f1l, g_f1l);
    cudaGetSymbolAddress((void**)&x1, g_x1);

    cudaFuncSetAttribute(gemm_mma_kernel, cudaFuncAttributeMaxDynamicSharedMemorySize, GEMM_SMEM);
    cudaFuncSetAttribute(attn_mma_kernel, cudaFuncAttributeMaxDynamicSharedMemorySize, ATTN_SMEM);

    // merged weight conversion (fp32 -> bf16 hi/lo planes)
    convert_all_kernel<<<(CV_TOT + 255) / 256, 256>>>(
        W_attn, wah, wal, W_proj, wph, wpl, W_fc1, w1h, w1l, W_fc2, w2h, w2l);

    // h = rmsnorm(x, ln1_w) -> planes
    rmsnorm_kernel<<<ROWS, 256>>>(x, ln1_w, hh, hl);
    // qkv = h @ W_attn + b_attn -> planes
    gemm_mma_kernel<<<PGRID, 256, GEMM_SMEM>>>(
        hh, hl, wah, wal, b_attn, nullptr, nullptr, qh, ql, ROWS, QKVN, DMODEL, 0);
    // ctx = attention(qkv) -> planes
    attn_mma_kernel<<<PGRID, 256, ATTN_SMEM>>>(qh, ql, ch, cl);
    // x1 = x + ctx @ W_proj + b_proj (fp32)
    gemm_mma_kernel<<<PGRID, 256, GEMM_SMEM>>>(
        ch, cl, wph, wpl, b_proj, x, x1, nullptr, nullptr, ROWS, DMODEL, DMODEL, 0);
    // h = rmsnorm(x1, ln2_w) -> planes
    rmsnorm_kernel<<<ROWS, 256>>>(x1, ln2_w, hh, hl);
    // fc1 = relu(h @ W_fc1 + b_fc1) -> planes
    gemm_mma_kernel<<<PGRID, 256, GEMM_SMEM>>>(
        hh, hl, w1h, w1l, b_fc1, nullptr, nullptr, f1h, f1l, ROWS, HID, DMODEL, 1);
    // out = x1 + fc1 @ W_fc2 + b_fc2 (fp32)
    gemm_mma_kernel<<<PGRID, 256, GEMM_SMEM>>>(
        f1h, f1l, w2h, w2l, b_fc2, x1, out, nullptr, nullptr, ROWS, DMODEL, HID, 0);
}

// round 13
// speedup vs baseline: 3.1947x; 1.0473x over previous
#include <cuda_runtime.h>
#include <cuda_bf16.h>
#include <cuda_fp16.h>
#include <cstdint>

// Problem constants
#define BATCH 2
#define SEQ   2048
#define DMODEL 768
#define NHEAD 12
#define DHEAD 64
#define HID   1536
#define ROWS  (BATCH * SEQ)          // 4096
#define QKVN  (3 * DMODEL)           // 2304
#define EPS   1e-6f
#define PGRID 296                    // 2 CTAs x 148 SMs

// ---------------- scratch (__device__ globals; no allocs allowed) ----------------
__device__ alignas(16) __nv_bfloat16 g_wattn_h[DMODEL * QKVN], g_wattn_l[DMODEL * QKVN];
__device__ alignas(16) __nv_bfloat16 g_wproj_h[DMODEL * DMODEL], g_wproj_l[DMODEL * DMODEL];
__device__ alignas(16) __nv_bfloat16 g_wfc1_h[DMODEL * HID], g_wfc1_l[DMODEL * HID];
__device__ alignas(16) __nv_bfloat16 g_wfc2_h[HID * DMODEL], g_wfc2_l[HID * DMODEL];
__device__ alignas(16) __nv_bfloat16 g_hh[ROWS * DMODEL], g_hl[ROWS * DMODEL];
__device__ alignas(16) __nv_bfloat16 g_qh[ROWS * QKVN], g_ql[ROWS * QKVN];   // V third holds fp16
__device__ alignas(16) __nv_bfloat16 g_ch[ROWS * DMODEL], g_cl[ROWS * DMODEL];
__device__ alignas(16) __nv_bfloat16 g_f1h[ROWS * HID], g_f1l[ROWS * HID];
__device__ float g_x1[ROWS * DMODEL];

// ================= helpers =================
__device__ __forceinline__ uint32_t sptr(const void* p) {
    return (uint32_t)__cvta_generic_to_shared(p);
}
__device__ __forceinline__ void ldsm_x4(uint32_t addr, uint32_t* r) {
    asm volatile("ldmatrix.sync.aligned.m8n8.x4.shared.b16 {%0,%1,%2,%3}, [%4];"
                 : "=r"(r[0]), "=r"(r[1]), "=r"(r[2]), "=r"(r[3]) : "r"(addr));
}
__device__ __forceinline__ void ldsm_x4t(uint32_t addr, uint32_t* r) {
    asm volatile("ldmatrix.sync.aligned.m8n8.x4.trans.shared.b16 {%0,%1,%2,%3}, [%4];"
                 : "=r"(r[0]), "=r"(r[1]), "=r"(r[2]), "=r"(r[3]) : "r"(addr));
}
__device__ __forceinline__ void mma_bf16(float* c, const uint32_t* a, const uint32_t* b) {
    asm volatile(
        "mma.sync.aligned.m16n8k16.row.col.f32.bf16.bf16.f32 "
        "{%0,%1,%2,%3}, {%4,%5,%6,%7}, {%8,%9}, {%0,%1,%2,%3};"
        : "+f"(c[0]), "+f"(c[1]), "+f"(c[2]), "+f"(c[3])
        : "r"(a[0]), "r"(a[1]), "r"(a[2]), "r"(a[3]), "r"(b[0]), "r"(b[1]));
}
__device__ __forceinline__ void mma_f16(float* c, const uint32_t* a, const uint32_t* b) {
    asm volatile(
        "mma.sync.aligned.m16n8k16.row.col.f32.f16.f16.f32 "
        "{%0,%1,%2,%3}, {%4,%5,%6,%7}, {%8,%9}, {%0,%1,%2,%3};"
        : "+f"(c[0]), "+f"(c[1]), "+f"(c[2]), "+f"(c[3])
        : "r"(a[0]), "r"(a[1]), "r"(a[2]), "r"(a[3]), "r"(b[0]), "r"(b[1]));
}
__device__ __forceinline__ uint32_t pack_bf2(__nv_bfloat16 a, __nv_bfloat16 b) {
    return ((uint32_t)__bfloat16_as_ushort(b) << 16) | (uint32_t)__bfloat16_as_ushort(a);
}
__device__ __forceinline__ uint32_t pack_h2(__half a, __half b) {
    return ((uint32_t)__half_as_ushort(b) << 16) | (uint32_t)__half_as_ushort(a);
}
__device__ __forceinline__ void split4(float4 v, uint2& h, uint2& l) {
    __nv_bfloat16 hx = __float2bfloat16_rn(v.x), hy = __float2bfloat16_rn(v.y);
    __nv_bfloat16 hz = __float2bfloat16_rn(v.z), hw = __float2bfloat16_rn(v.w);
    __nv_bfloat16 lx = __float2bfloat16_rn(v.x - __bfloat162float(hx));
    __nv_bfloat16 ly = __float2bfloat16_rn(v.y - __bfloat162float(hy));
    __nv_bfloat16 lz = __float2bfloat16_rn(v.z - __bfloat162float(hz));
    __nv_bfloat16 lw = __float2bfloat16_rn(v.w - __bfloat162float(hw));
    h = make_uint2(pack_bf2(hx, hy), pack_bf2(hz, hw));
    l = make_uint2(pack_bf2(lx, ly), pack_bf2(lz, lw));
}
__device__ __forceinline__ void split1(float v, __nv_bfloat16& h, __nv_bfloat16& l) {
    h = __float2bfloat16_rn(v);
    l = __float2bfloat16_rn(v - __bfloat162float(h));
}
__device__ __forceinline__ void split1h(float v, __half& h, __half& l) {
    h = __float2half_rn(v);
    l = __float2half_rn(v - __half2float(h));
}

#define CP_ASYNC16(dst, src) \
    asm volatile("cp.async.cg.shared.global [%0], [%1], 16;" :: "r"(dst), "l"(src) : "memory")
#define CP_COMMIT() asm volatile("cp.async.commit_group;" ::: "memory")
#define CP_WAIT(N)  asm volatile("cp.async.wait_group %0;" :: "n"(N) : "memory")

// ================= merged weight conversion: fp32 -> bf16 hi/lo planes =================
#define CV_N0 (DMODEL * QKVN / 4)
#define CV_N1 (DMODEL * DMODEL / 4)
#define CV_N2 (DMODEL * HID / 4)
#define CV_N3 (HID * DMODEL / 4)
#define CV_TOT (CV_N0 + CV_N1 + CV_N2 + CV_N3)

__global__ __launch_bounds__(256) void convert_all_kernel(
    const float* __restrict__ s0, __nv_bfloat16* __restrict__ h0, __nv_bfloat16* __restrict__ l0,
    const float* __restrict__ s1, __nv_bfloat16* __restrict__ h1, __nv_bfloat16* __restrict__ l1,
    const float* __restrict__ s2, __nv_bfloat16* __restrict__ h2, __nv_bfloat16* __restrict__ l2,
    const float* __restrict__ s3, __nv_bfloat16* __restrict__ h3, __nv_bfloat16* __restrict__ l3)
{
    int i = blockIdx.x * 256 + threadIdx.x;
    const float* s; __nv_bfloat16* h; __nv_bfloat16* l;
    if (i < CV_N0)                    { s = s0; h = h0; l = l0; }
    else if (i < CV_N0 + CV_N1)       { s = s1; h = h1; l = l1; i -= CV_N0; }
    else if (i < CV_N0 + CV_N1 + CV_N2){ s = s2; h = h2; l = l2; i -= CV_N0 + CV_N1; }
    else if (i < CV_TOT)              { s = s3; h = h3; l = l3; i -= CV_N0 + CV_N1 + CV_N2; }
    else return;
    float4 v = ((const float4*)s)[i];
    uint2 hh, ll; split4(v, hh, ll);
    ((uint2*)h)[i] = hh;
    ((uint2*)l)[i] = ll;
}

// ================= RMSNorm: fp32 in, bf16 hi/lo planes out =================
__global__ __launch_bounds__(256) void rmsnorm_kernel(
    const float* __restrict__ x, const float* __restrict__ w,
    __nv_bfloat16* __restrict__ oh, __nv_bfloat16* __restrict__ ol)
{
    const int row = blockIdx.x;
    const int tid = threadIdx.x;
    const float* xr = x + (size_t)row * DMODEL;
    float v0 = xr[tid], v1 = xr[tid + 256], v2 = xr[tid + 512];
    float s = v0 * v0 + v1 * v1 + v2 * v2;
    #pragma unroll
    for (int o = 16; o > 0; o >>= 1) s += __shfl_xor_sync(0xFFFFFFFF, s, o);
    __shared__ float wsum[8];
    if ((tid & 31) == 0) wsum[tid >> 5] = s;
    __syncthreads();
    if (tid < 8) {
        float t = wsum[tid];
        #pragma unroll
        for (int o = 4; o > 0; o >>= 1) t += __shfl_xor_sync(0xFF, t, o);
        if (tid == 0) wsum[0] = t;
    }
    __syncthreads();
    const float scale = rsqrtf(wsum[0] * (1.0f / DMODEL) + EPS);
    size_t base = (size_t)row * DMODEL;
    __nv_bfloat16 h, l;
    split1(v0 * scale * w[tid], h, l);       oh[base + tid] = h;       ol[base + tid] = l;
    split1(v1 * scale * w[tid + 256], h, l); oh[base + tid + 256] = h; ol[base + tid + 256] = l;
    split1(v2 * scale * w[tid + 512], h, l); oh[base + tid + 512] = h; ol[base + tid + 512] = l;
}

// ================= persistent tensor-core GEMM (cp.async 3-stage) =================
#define BM 128
#define BN 128
#define BK 32
#define STA 40
#define STB 136
#define ASZ (BM * STA)
#define BSZ (BK * STB)
#define STAGE_H (2 * ASZ + 2 * BSZ)
#define GEMM_SMEM (3 * STAGE_H * 2)    // 113664 bytes

__device__ __forceinline__ void gemm_cp_stage(
    uint32_t sb, const __nv_bfloat16* Ah_g, const __nv_bfloat16* Al_g,
    const __nv_bfloat16* Bh_g, const __nv_bfloat16* Bl_g,
    int m0, int n0, int k0, int K, int N, int tid)
{
    #pragma unroll
    for (int i = 0; i < 2; i++) {
        int idx = tid + i * 256;
        int row = idx >> 2, ch = idx & 3;
        uint32_t d = sb + (uint32_t)(row * STA + ch * 8) * 2;
        size_t o = (size_t)(m0 + row) * K + k0 + ch * 8;
        CP_ASYNC16(d, Ah_g + o);
        CP_ASYNC16(d + ASZ * 2, Al_g + o);
    }
    #pragma unroll
    for (int i = 0; i < 2; i++) {
        int idx = tid + i * 256;
        int row = idx >> 4, ch = idx & 15;
        uint32_t d = sb + (uint32_t)(2 * ASZ + row * STB + ch * 8) * 2;
        size_t o = (size_t)(k0 + row) * N + n0 + ch * 8;
        CP_ASYNC16(d, Bh_g + o);
        CP_ASYNC16(d + BSZ * 2, Bl_g + o);
    }
}

__global__ __launch_bounds__(256, 2) void gemm_mma_kernel(
    const __nv_bfloat16* __restrict__ Ah_g, const __nv_bfloat16* __restrict__ Al_g,
    const __nv_bfloat16* __restrict__ Bh_g, const __nv_bfloat16* __restrict__ Bl_g,
    const float* __restrict__ bias, const float* __restrict__ resid,
    float* __restrict__ Cf, __nv_bfloat16* __restrict__ Ch, __nv_bfloat16* __restrict__ Cl,
    int M, int N, int K, int do_relu, int fp16col)
{
    extern __shared__ __nv_bfloat16 gsm[];
    const uint32_t smb = sptr(gsm);
    const int tid = threadIdx.x, wid = tid >> 5, lane = tid & 31;
    const int warp_m = wid >> 2, warp_n = wid & 3;
    const int nxt = N / BN;
    const int ntot = (M / BM) * nxt;
    const int ntiles = K / BK;

    for (int tile = blockIdx.x; tile < ntot; tile += gridDim.x) {
        const int m0 = (tile / nxt) * BM, n0 = (tile % nxt) * BN;

        float acc[4][4][4];
        #pragma unroll
        for (int i = 0; i < 4; i++)
            #pragma unroll
            for (int j = 0; j < 4; j++)
                #pragma unroll
                for (int r = 0; r < 4; r++) acc[i][j][r] = 0.f;

        gemm_cp_stage(smb, Ah_g, Al_g, Bh_g, Bl_g, m0, n0, 0, K, N, tid);
        CP_COMMIT();
        gemm_cp_stage(smb + STAGE_H * 2, Ah_g, Al_g, Bh_g, Bl_g, m0, n0, BK, K, N, tid);
        CP_COMMIT();

        for (int t = 0; t < ntiles; t++) {
            if (t + 2 <= ntiles) { CP_WAIT(1); } else { CP_WAIT(0); }
            __syncthreads();
            if (t + 2 < ntiles) {
                gemm_cp_stage(smb + ((t + 2) % 3) * STAGE_H * 2,
                              Ah_g, Al_g, Bh_g, Bl_g, m0, n0, (t + 2) * BK, K, N, tid);
                CP_COMMIT();
            }

            const uint32_t st = smb + (t % 3) * STAGE_H * 2;
            const uint32_t ah_b = st, al_b = st + ASZ * 2;
            const uint32_t bh_b = st + 2 * ASZ * 2, bl_b = bh_b + BSZ * 2;

            #pragma unroll
            for (int ks = 0; ks < 2; ks++) {
                const int kof = ks * 16;
                uint32_t bh[4][2], bl[4][2];
                #pragma unroll
                for (int cb = 0; cb < 2; cb++) {
                    int krow = kof + (lane & 15);
                    int col = warp_n * 32 + cb * 16 + ((lane >> 4) << 3);
                    uint32_t off = (uint32_t)(krow * STB + col) * 2;
                    uint32_t tmp[4];
                    ldsm_x4t(bh_b + off, tmp);
                    bh[2 * cb][0] = tmp[0]; bh[2 * cb][1] = tmp[1];
                    bh[2 * cb + 1][0] = tmp[2]; bh[2 * cb + 1][1] = tmp[3];
                    ldsm_x4t(bl_b + off, tmp);
                    bl[2 * cb][0] = tmp[0]; bl[2 * cb][1] = tmp[1];
                    bl[2 * cb + 1][0] = tmp[2]; bl[2 * cb + 1][1] = tmp[3];
                }
                #pragma unroll
                for (int mt = 0; mt < 4; mt++) {
                    int row = warp_m * 64 + mt * 16 + (lane & 15);
                    int col = kof + ((lane >> 4) << 3);
                    uint32_t off = (uint32_t)(row * STA + col) * 2;
                    uint32_t ah[4], al[4];
                    ldsm_x4(ah_b + off, ah);
                    ldsm_x4(al_b + off, al);
                    #pragma unroll
                    for (int nt = 0; nt < 4; nt++) {
                        mma_bf16(acc[mt][nt], ah, bh[nt]);
                        mma_bf16(acc[mt][nt], ah, bl[nt]);
                        mma_bf16(acc[mt][nt], al, bh[nt]);
                    }
                }
            }
        }

        // ---- epilogue ----
        #pragma unroll
        for (int mt = 0; mt < 4; mt++) {
            int r0 = m0 + warp_m * 64 + mt * 16 + (lane >> 2);
            #pragma unroll
            for (int nt = 0; nt < 4; nt++) {
                int c0 = n0 + warp_n * 32 + nt * 8 + (lane & 3) * 2;
                float b0 = bias[c0], b1 = bias[c0 + 1];
                float v0 = acc[mt][nt][0] + b0, v1 = acc[mt][nt][1] + b1;
                float v2 = acc[mt][nt][2] + b0, v3 = acc[mt][nt][3] + b1;
                if (do_relu) {
                    v0 = fmaxf(v0, 0.f); v1 = fmaxf(v1, 0.f);
                    v2 = fmaxf(v2, 0.f); v3 = fmaxf(v3, 0.f);
                }
                if (resid) {
                    const float* rr0 = resid + (size_t)r0 * N + c0;
                    const float* rr1 = resid + (size_t)(r0 + 8) * N + c0;
                    v0 += rr0[0]; v1 += rr0[1];
                    v2 += rr1[0]; v3 += rr1[1];
                }
                if (Cf) {
                    *(float2*)(Cf + (size_t)r0 * N + c0)       = make_float2(v0, v1);
                    *(float2*)(Cf + (size_t)(r0 + 8) * N + c0) = make_float2(v2, v3);
                }
                if (Ch) {
                    if (c0 >= fp16col) {     // V third of qkv -> fp16 hi/lo planes
                        __half h0, l0, h1, l1;
                        split1h(v0, h0, l0); split1h(v1, h1, l1);
                        *(uint32_t*)(Ch + (size_t)r0 * N + c0) = pack_h2(h0, h1);
                        *(uint32_t*)(Cl + (size_t)r0 * N + c0) = pack_h2(l0, l1);
                        split1h(v2, h0, l0); split1h(v3, h1, l1);
                        *(uint32_t*)(Ch + (size_t)(r0 + 8) * N + c0) = pack_h2(h0, h1);
                        *(uint32_t*)(Cl + (size_t)(r0 + 8) * N + c0) = pack_h2(l0, l1);
                    } else {
                        __nv_bfloat16 h0, l0, h1, l1;
                        split1(v0, h0, l0); split1(v1, h1, l1);
                        *(uint32_t*)(Ch + (size_t)r0 * N + c0) = pack_bf2(h0, h1);
                        *(uint32_t*)(Cl + (size_t)r0 * N + c0) = pack_bf2(l0, l1);
                        split1(v2, h0, l0); split1(v3, h1, l1);
                        *(uint32_t*)(Ch + (size_t)(r0 + 8) * N + c0) = pack_bf2(h0, h1);
                        *(uint32_t*)(Cl + (size_t)(r0 + 8) * N + c0) = pack_bf2(l0, l1);
                    }
                }
            }
        }
        __syncthreads();
    }
}

// ================= persistent tensor-core squared-ReLU attention =================
// S path bf16 hi/lo (3 passes). PV path: P as single fp16, V fp16 hi/lo (2 passes).
#define AQ  128
#define AKT 32
#define QPL_B  (AQ * 128)
#define KVPL_B (AKT * 128)
#define KVSTG_B (4 * KVPL_B)
#define ATTN_SMEM (2 * QPL_B + 3 * KVSTG_B)   // 81920 bytes

#define ASWZ(r, ch) ((uint32_t)((r) * 128 + ((((ch) ^ ((r) & 7))) << 4)))

__device__ __forceinline__ void attn_cp_kv(
    uint32_t sb, const __nv_bfloat16* qh_g, const __nv_bfloat16* ql_g,
    size_t rowbase, int tid)
{
    int r = tid >> 3, ch = tid & 7;
    size_t ko = rowbase + (size_t)r * QKVN + DMODEL + ch * 8;
    size_t vo = rowbase + (size_t)r * QKVN + 2 * DMODEL + ch * 8;
    uint32_t d = sb + ASWZ(r, ch);
    CP_ASYNC16(d,                qh_g + ko);
    CP_ASYNC16(d + KVPL_B,       ql_g + ko);
    CP_ASYNC16(d + 2 * KVPL_B,   qh_g + vo);
    CP_ASYNC16(d + 3 * KVPL_B,   ql_g + vo);
}

__global__ __launch_bounds__(256, 2) void attn_mma_kernel(
    const __nv_bfloat16* __restrict__ qh_g, const __nv_bfloat16* __restrict__ ql_g,
    __nv_bfloat16* __restrict__ ch_g, __nv_bfloat16* __restrict__ cl_g)
{
    extern __shared__ __nv_bfloat16 asmem[];
    const uint32_t smb = sptr(asmem);
    const uint32_t kvb = smb + 2 * QPL_B;

    const int tid = threadIdx.x, wid = tid >> 5, lane = tid & 31;
    const int nwi = (SEQ / AQ) * BATCH * NHEAD;   // 384

    for (int wi = blockIdx.x; wi < nwi; wi += gridDim.x) {
        const int q0 = (wi & 15) * AQ;
        const int bh_i = wi >> 4;
        const int b = bh_i / NHEAD, h = bh_i % NHEAD;
        const int hcol = h * DHEAD;
        const size_t bbase = (size_t)b * SEQ * QKVN + hcol;

        // group 0: Q planes
        #pragma unroll
        for (int i = 0; i < 4; i++) {
            int idx = tid + i * 256;
            int r = idx >> 3, ch = idx & 7;
            size_t o = bbase + (size_t)(q0 + r) * QKVN + ch * 8;
            uint32_t d = smb + ASWZ(r, ch);
            CP_ASYNC16(d, qh_g + o);
            CP_ASYNC16(d + QPL_B, ql_g + o);
        }
        CP_COMMIT();
        attn_cp_kv(kvb,            qh_g, ql_g, bbase, tid);
        CP_COMMIT();
        attn_cp_kv(kvb + KVSTG_B,  qh_g, ql_g, bbase + (size_t)AKT * QKVN, tid);
        CP_COMMIT();

        float out_acc[8][4];
        #pragma unroll
        for (int nt = 0; nt < 8; nt++)
            #pragma unroll
            for (int r = 0; r < 4; r++) out_acc[nt][r] = 0.f;

        const int ntiles = SEQ / AKT;    // 64
        for (int t = 0; t < ntiles; t++) {
            if (t + 2 <= ntiles) { CP_WAIT(1); } else { CP_WAIT(0); }
            __syncthreads();
            if (t + 2 < ntiles) {
                attn_cp_kv(kvb + ((t + 2) % 3) * KVSTG_B,
                           qh_g, ql_g, bbase + (size_t)(t + 2) * AKT * QKVN, tid);
                CP_COMMIT();
            }

            const uint32_t st = kvb + (t % 3) * KVSTG_B;
            const uint32_t kh_b = st, kl_b = st + KVPL_B;
            const uint32_t vh_b = st + 2 * KVPL_B, vl_b = st + 3 * KVPL_B;

            // ---- S = Q K^T (bf16 hi/lo, 3 passes) ----
            float s_acc[4][4];
            #pragma unroll
            for (int nt = 0; nt < 4; nt++)
                #pragma unroll
                for (int r = 0; r < 4; r++) s_acc[nt][r] = 0.f;

            #pragma unroll
            for (int ks = 0; ks < 4; ks++) {
                const int colc = 2 * ks + (lane >> 4);
                uint32_t qa_h[4], qa_l[4];
                {
                    int row = wid * 16 + (lane & 15);
                    uint32_t off = ASWZ(row, colc);
                    ldsm_x4(smb + off, qa_h);
                    ldsm_x4(smb + QPL_B + off, qa_l);
                }
                #pragma unroll
                for (int ntp = 0; ntp < 2; ntp++) {
                    int n = ntp * 16 + (lane & 15);
                    uint32_t off = ASWZ(n, colc);
                    uint32_t kb_h[4], kb_l[4];
                    ldsm_x4(kh_b + off, kb_h);
                    ldsm_x4(kl_b + off, kb_l);
                    uint32_t b0h[2] = {kb_h[0], kb_h[2]}, b1h[2] = {kb_h[1], kb_h[3]};
                    uint32_t b0l[2] = {kb_l[0], kb_l[2]}, b1l[2] = {kb_l[1], kb_l[3]};
                    mma_bf16(s_acc[2 * ntp],     qa_h, b0h);
                    mma_bf16(s_acc[2 * ntp],     qa_h, b0l);
                    mma_bf16(s_acc[2 * ntp],     qa_l, b0h);
                    mma_bf16(s_acc[2 * ntp + 1], qa_h, b1h);
                    mma_bf16(s_acc[2 * ntp + 1], qa_h, b1l);
                    mma_bf16(s_acc[2 * ntp + 1], qa_l, b1h);
                }
            }

            // ---- P = relu(s/8)^2 -> single fp16 A-fragments ----
            uint32_t pa[2][4];
            #pragma unroll
            for (int nt = 0; nt < 4; nt++) {
                float p[4];
                #pragma unroll
                for (int r = 0; r < 4; r++) {
                    float tt = fmaxf(s_acc[nt][r], 0.f);
                    p[r] = tt * tt * 0.015625f;
                }
                __half h0 = __float2half_rn(p[0]), h1 = __float2half_rn(p[1]);
                __half h2 = __float2half_rn(p[2]), h3 = __float2half_rn(p[3]);
                int kt2 = nt >> 1;
                int base_r = (nt & 1) ? 2 : 0;
                pa[kt2][base_r]     = pack_h2(h0, h1);
                pa[kt2][base_r + 1] = pack_h2(h2, h3);
            }

            // ---- ctx += P V (fp16, 2 passes) ----
            #pragma unroll
            for (int kt2 = 0; kt2 < 2; kt2++) {
                int krow = kt2 * 16 + (lane & 15);
                #pragma unroll
                for (int cb = 0; cb < 4; cb++) {
                    int colc = 2 * cb + (lane >> 4);
                    uint32_t off = ASWZ(krow, colc);
                    uint32_t vbh[4], vbl[4];
                    ldsm_x4t(vh_b + off, vbh);
                    ldsm_x4t(vl_b + off, vbl);
                    int nt = cb * 2;
                    uint32_t b0h[2] = {vbh[0], vbh[1]}, b1h[2] = {vbh[2], vbh[3]};
                    uint32_t b0l[2] = {vbl[0], vbl[1]}, b1l[2] = {vbl[2], vbl[3]};
                    mma_f16(out_acc[nt],     pa[kt2], b0h);
                    mma_f16(out_acc[nt],     pa[kt2], b0l);
                    mma_f16(out_acc[nt + 1], pa[kt2], b1h);
                    mma_f16(out_acc[nt + 1], pa[kt2], b1l);
                }
            }
        }

        // ---- epilogue: ctx hi/lo planes (bf16) ----
        #pragma unroll
        for (int nt = 0; nt < 8; nt++) {
            int q = q0 + wid * 16 + (lane >> 2);
            int c = hcol + nt * 8 + (lane & 3) * 2;
            __nv_bfloat16 h0, l0, h1, l1;
            split1(out_acc[nt][0], h0, l0); split1(out_acc[nt][1], h1, l1);
            *(uint32_t*)(ch_g + ((size_t)b * SEQ + q) * DMODEL + c) = pack_bf2(h0, h1);
            *(uint32_t*)(cl_g + ((size_t)b * SEQ + q) * DMODEL + c) = pack_bf2(l0, l1);
            split1(out_acc[nt][2], h0, l0); split1(out_acc[nt][3], h1, l1);
            *(uint32_t*)(ch_g + ((size_t)b * SEQ + q + 8) * DMODEL + c) = pack_bf2(h0, h1);
            *(uint32_t*)(cl_g + ((size_t)b * SEQ + q + 8) * DMODEL + c) = pack_bf2(l0, l1);
        }
        __syncthreads();   // next item's Q load must not race final S reads
    }
}

// ================= launch =================
extern "C" void kernel_launch(void* const* d_in, const int* in_sizes, int n_in,
                              void* d_out, int out_size)
{
    const float* x      = (const float*)d_in[0];
    const float* ln1_w  = (const float*)d_in[1];
    const float* W_attn = (const float*)d_in[2];
    const float* b_attn = (const float*)d_in[3];
    const float* W_proj = (const float*)d_in[4];
    const float* b_proj = (const float*)d_in[5];
    const float* ln2_w  = (const float*)d_in[6];
    const float* W_fc1  = (const float*)d_in[7];
    const float* b_fc1  = (const float*)d_in[8];
    const float* W_fc2  = (const float*)d_in[9];
    const float* b_fc2  = (const float*)d_in[10];
    float* out = (float*)d_out;

    __nv_bfloat16 *wah, *wal, *wph, *wpl, *w1h, *w1l, *w2h, *w2l;
    __nv_bfloat16 *hh, *hl, *qh, *ql, *ch, *cl, *f1h, *f1l;
    float* x1;
    cudaGetSymbolAddress((void**)&wah, g_wattn_h); cudaGetSymbolAddress((void**)&wal, g_wattn_l);
    cudaGetSymbolAddress((void**)&wph, g_wproj_h); cudaGetSymbolAddress((void**)&wpl, g_wproj_l);
    cudaGetSymbolAddress((void**)&w1h, g_wfc1_h);  cudaGetSymbolAddress((void**)&w1l, g_wfc1_l);
    cudaGetSymbolAddress((void**)&w2h, g_wfc2_h);  cudaGetSymbolAddress((void**)&w2l, g_wfc2_l);
    cudaGetSymbolAddress((void**)&hh, g_hh);   cudaGetSymbolAddress((void**)&hl, g_hl);
    cudaGetSymbolAddress((void**)&qh, g_qh);   cudaGetSymbolAddress((void**)&ql, g_ql);
    cudaGetSymbolAddress((void**)&ch, g_ch);   cudaGetSymbolAddress((void**)&cl, g_cl);
    cudaGetSymbolAddress((void**)&f1h, g_f1h); cudaGetSymbolAddress((void**)&f1l, g_f1l);
    cudaGetSymbolAddress((void**)&x1, g_x1);

    cudaFuncSetAttribute(gemm_mma_kernel, cudaFuncAttributeMaxDynamicSharedMemorySize, GEMM_SMEM);
    cudaFuncSetAttribute(attn_mma_kernel, cudaFuncAttributeMaxDynamicSharedMemorySize, ATTN_SMEM);

    convert_all_kernel<<<(CV_TOT + 255) / 256, 256>>>(
        W_attn, wah, wal, W_proj, wph, wpl, W_fc1, w1h, w1l, W_fc2, w2h, w2l);

    const int NOFP16 = 1 << 30;

    // h = rmsnorm(x, ln1_w) -> planes
    rmsnorm_kernel<<<ROWS, 256>>>(x, ln1_w, hh, hl);
    // qkv = h @ W_attn + b_attn -> planes (V third as fp16 hi/lo)
    gemm_mma_kernel<<<PGRID, 256, GEMM_SMEM>>>(
        hh, hl, wah, wal, b_attn, nullptr, nullptr, qh, ql, ROWS, QKVN, DMODEL, 0, 2 * DMODEL);
    // ctx = attention(qkv) -> planes
    attn_mma_kernel<<<PGRID, 256, ATTN_SMEM>>>(qh, ql, ch, cl);
    // x1 = x + ctx @ W_proj + b_proj (fp32)
    gemm_mma_kernel<<<PGRID, 256, GEMM_SMEM>>>(
        ch, cl, wph, wpl, b_proj, x, x1, nullptr, nullptr, ROWS, DMODEL, DMODEL, 0, NOFP16);
    // h = rmsnorm(x1, ln2_w) -> planes
    rmsnorm_kernel<<<ROWS, 256>>>(x1, ln2_w, hh, hl);
    // fc1 = relu(h @ W_fc1 + b_fc1) -> planes
    gemm_mma_kernel<<<PGRID, 256, GEMM_SMEM>>>(
        hh, hl, w1h, w1l, b_fc1, nullptr, nullptr, f1h, f1l, ROWS, HID, DMODEL, 1, NOFP16);
    // out = x1 + fc1 @ W_fc2 + b_fc2 (fp32)
    gemm_mma_kernel<<<PGRID, 256, GEMM_SMEM>>>(
        f1h, f1l, w2h, w2l, b_fc2, x1, out, nullptr, nullptr, ROWS, DMODEL, HID, 0, NOFP16);
}

// round 14
// speedup vs baseline: 3.8966x; 1.2197x over previous
#include <cuda_runtime.h>
#include <cuda_bf16.h>
#include <cuda_fp16.h>
#include <cstdint>

// Problem constants
#define BATCH 2
#define SEQ   2048
#define DMODEL 768
#define NHEAD 12
#define DHEAD 64
#define HID   1536
#define ROWS  (BATCH * SEQ)          // 4096
#define QKVN  (3 * DMODEL)           // 2304
#define EPS   1e-6f
#define PGRID 296                    // 2 CTAs x 148 SMs

// ---------------- scratch (__device__ globals; no allocs allowed) ----------------
__device__ alignas(16) __half g_wattn[DMODEL * QKVN];
__device__ alignas(16) __half g_wproj[DMODEL * DMODEL];
__device__ alignas(16) __half g_wfc1[DMODEL * HID];
__device__ alignas(16) __half g_wfc2[HID * DMODEL];
__device__ alignas(16) __half g_hh[ROWS * DMODEL], g_hl[ROWS * DMODEL];
__device__ alignas(16) __half g_qh[ROWS * QKVN], g_ql[ROWS * QKVN];
__device__ alignas(16) __half g_ch[ROWS * DMODEL], g_cl[ROWS * DMODEL];
__device__ alignas(16) __half g_f1h[ROWS * HID], g_f1l[ROWS * HID];
__device__ float g_x1[ROWS * DMODEL];

// ================= helpers =================
__device__ __forceinline__ uint32_t sptr(const void* p) {
    return (uint32_t)__cvta_generic_to_shared(p);
}
__device__ __forceinline__ void ldsm_x4(uint32_t addr, uint32_t* r) {
    asm volatile("ldmatrix.sync.aligned.m8n8.x4.shared.b16 {%0,%1,%2,%3}, [%4];"
                 : "=r"(r[0]), "=r"(r[1]), "=r"(r[2]), "=r"(r[3]) : "r"(addr));
}
__device__ __forceinline__ void ldsm_x4t(uint32_t addr, uint32_t* r) {
    asm volatile("ldmatrix.sync.aligned.m8n8.x4.trans.shared.b16 {%0,%1,%2,%3}, [%4];"
                 : "=r"(r[0]), "=r"(r[1]), "=r"(r[2]), "=r"(r[3]) : "r"(addr));
}
__device__ __forceinline__ void mma_f16(float* c, const uint32_t* a, const uint32_t* b) {
    asm volatile(
        "mma.sync.aligned.m16n8k16.row.col.f32.f16.f16.f32 "
        "{%0,%1,%2,%3}, {%4,%5,%6,%7}, {%8,%9}, {%0,%1,%2,%3};"
        : "+f"(c[0]), "+f"(c[1]), "+f"(c[2]), "+f"(c[3])
        : "r"(a[0]), "r"(a[1]), "r"(a[2]), "r"(a[3]), "r"(b[0]), "r"(b[1]));
}
__device__ __forceinline__ uint32_t pack_h2(__half a, __half b) {
    return ((uint32_t)__half_as_ushort(b) << 16) | (uint32_t)__half_as_ushort(a);
}
__device__ __forceinline__ void split1h(float v, __half& h, __half& l) {
    h = __float2half_rn(v);
    l = __float2half_rn(v - __half2float(h));
}
__device__ __forceinline__ void split4h(float4 v, uint2& h, uint2& l) {
    __half hx, lx, hy, ly, hz, lz, hw, lw;
    split1h(v.x, hx, lx); split1h(v.y, hy, ly);
    split1h(v.z, hz, lz); split1h(v.w, hw, lw);
    h = make_uint2(pack_h2(hx, hy), pack_h2(hz, hw));
    l = make_uint2(pack_h2(lx, ly), pack_h2(lz, lw));
}

#define CP_ASYNC16(dst, src) \
    asm volatile("cp.async.cg.shared.global [%0], [%1], 16;" :: "r"(dst), "l"(src) : "memory")
#define CP_COMMIT() asm volatile("cp.async.commit_group;" ::: "memory")
#define CP_WAIT(N)  asm volatile("cp.async.wait_group %0;" :: "n"(N) : "memory")

// ================= merged weight conversion: fp32 -> single fp16 =================
#define CV_N0 (DMODEL * QKVN / 4)
#define CV_N1 (DMODEL * DMODEL / 4)
#define CV_N2 (DMODEL * HID / 4)
#define CV_N3 (HID * DMODEL / 4)
#define CV_TOT (CV_N0 + CV_N1 + CV_N2 + CV_N3)

__global__ __launch_bounds__(256) void convert_all_kernel(
    const float* __restrict__ s0, __half* __restrict__ h0,
    const float* __restrict__ s1, __half* __restrict__ h1,
    const float* __restrict__ s2, __half* __restrict__ h2,
    const float* __restrict__ s3, __half* __restrict__ h3)
{
    int i = blockIdx.x * 256 + threadIdx.x;
    const float* s; __half* h;
    if (i < CV_N0)                     { s = s0; h = h0; }
    else if (i < CV_N0 + CV_N1)        { s = s1; h = h1; i -= CV_N0; }
    else if (i < CV_N0 + CV_N1 + CV_N2){ s = s2; h = h2; i -= CV_N0 + CV_N1; }
    else if (i < CV_TOT)               { s = s3; h = h3; i -= CV_N0 + CV_N1 + CV_N2; }
    else return;
    float4 v = ((const float4*)s)[i];
    uint2 o;
    o.x = pack_h2(__float2half_rn(v.x), __float2half_rn(v.y));
    o.y = pack_h2(__float2half_rn(v.z), __float2half_rn(v.w));
    ((uint2*)h)[i] = o;
}

// ================= RMSNorm: fp32 in, fp16 hi/lo planes out =================
__global__ __launch_bounds__(256) void rmsnorm_kernel(
    const float* __restrict__ x, const float* __restrict__ w,
    __half* __restrict__ oh, __half* __restrict__ ol)
{
    const int row = blockIdx.x;
    const int tid = threadIdx.x;
    const float* xr = x + (size_t)row * DMODEL;
    float v0 = xr[tid], v1 = xr[tid + 256], v2 = xr[tid + 512];
    float s = v0 * v0 + v1 * v1 + v2 * v2;
    #pragma unroll
    for (int o = 16; o > 0; o >>= 1) s += __shfl_xor_sync(0xFFFFFFFF, s, o);
    __shared__ float wsum[8];
    if ((tid & 31) == 0) wsum[tid >> 5] = s;
    __syncthreads();
    if (tid < 8) {
        float t = wsum[tid];
        #pragma unroll
        for (int o = 4; o > 0; o >>= 1) t += __shfl_xor_sync(0xFF, t, o);
        if (tid == 0) wsum[0] = t;
    }
    __syncthreads();
    const float scale = rsqrtf(wsum[0] * (1.0f / DMODEL) + EPS);
    size_t base = (size_t)row * DMODEL;
    __half h, l;
    split1h(v0 * scale * w[tid], h, l);       oh[base + tid] = h;       ol[base + tid] = l;
    split1h(v1 * scale * w[tid + 256], h, l); oh[base + tid + 256] = h; ol[base + tid + 256] = l;
    split1h(v2 * scale * w[tid + 512], h, l); oh[base + tid + 512] = h; ol[base + tid + 512] = l;
}

// ================= persistent tensor-core GEMM (cp.async 3-stage, fp16) =================
// A fp16 hi/lo planes, W single fp16; 2 MMA passes per fragment pair.
#define BM 128
#define BN 128
#define BK 32
#define STA 40
#define STB 136
#define ASZ (BM * STA)                 // 5120 halfs per A plane
#define BSZ (BK * STB)                 // 4352 halfs (single B plane)
#define STAGE_H (2 * ASZ + BSZ)        // 14592 halfs
#define GEMM_SMEM (3 * STAGE_H * 2)    // 87552 bytes

__device__ __forceinline__ void gemm_cp_stage(
    uint32_t sb, const __half* Ah_g, const __half* Al_g, const __half* B_g,
    int m0, int n0, int k0, int K, int N, int tid)
{
    #pragma unroll
    for (int i = 0; i < 2; i++) {
        int idx = tid + i * 256;                 // 512 chunks per A plane
        int row = idx >> 2, ch = idx & 3;
        uint32_t d = sb + (uint32_t)(row * STA + ch * 8) * 2;
        size_t o = (size_t)(m0 + row) * K + k0 + ch * 8;
        CP_ASYNC16(d, Ah_g + o);
        CP_ASYNC16(d + ASZ * 2, Al_g + o);
    }
    #pragma unroll
    for (int i = 0; i < 2; i++) {
        int idx = tid + i * 256;                 // 512 chunks for B plane
        int row = idx >> 4, ch = idx & 15;
        uint32_t d = sb + (uint32_t)(2 * ASZ + row * STB + ch * 8) * 2;
        size_t o = (size_t)(k0 + row) * N + n0 + ch * 8;
        CP_ASYNC16(d, B_g + o);
    }
}

__global__ __launch_bounds__(256, 2) void gemm_mma_kernel(
    const __half* __restrict__ Ah_g, const __half* __restrict__ Al_g,
    const __half* __restrict__ B_g,
    const float* __restrict__ bias, const float* __restrict__ resid,
    float* __restrict__ Cf, __half* __restrict__ Ch, __half* __restrict__ Cl,
    int M, int N, int K, int do_relu)
{
    extern __shared__ __half gsm[];
    const uint32_t smb = sptr(gsm);
    const int tid = threadIdx.x, wid = tid >> 5, lane = tid & 31;
    const int warp_m = wid >> 2, warp_n = wid & 3;
    const int nxt = N / BN;
    const int ntot = (M / BM) * nxt;
    const int ntiles = K / BK;

    for (int tile = blockIdx.x; tile < ntot; tile += gridDim.x) {
        const int m0 = (tile / nxt) * BM, n0 = (tile % nxt) * BN;

        float acc[4][4][4];
        #pragma unroll
        for (int i = 0; i < 4; i++)
            #pragma unroll
            for (int j = 0; j < 4; j++)
                #pragma unroll
                for (int r = 0; r < 4; r++) acc[i][j][r] = 0.f;

        gemm_cp_stage(smb, Ah_g, Al_g, B_g, m0, n0, 0, K, N, tid);
        CP_COMMIT();
        gemm_cp_stage(smb + STAGE_H * 2, Ah_g, Al_g, B_g, m0, n0, BK, K, N, tid);
        CP_COMMIT();

        for (int t = 0; t < ntiles; t++) {
            if (t + 2 <= ntiles) { CP_WAIT(1); } else { CP_WAIT(0); }
            __syncthreads();
            if (t + 2 < ntiles) {
                gemm_cp_stage(smb + ((t + 2) % 3) * STAGE_H * 2,
                              Ah_g, Al_g, B_g, m0, n0, (t + 2) * BK, K, N, tid);
                CP_COMMIT();
            }

            const uint32_t st = smb + (t % 3) * STAGE_H * 2;
            const uint32_t ah_b = st, al_b = st + ASZ * 2;
            const uint32_t b_b = st + 2 * ASZ * 2;

            #pragma unroll
            for (int ks = 0; ks < 2; ks++) {
                const int kof = ks * 16;
                uint32_t bfr[4][2];
                #pragma unroll
                for (int cb = 0; cb < 2; cb++) {
                    int krow = kof + (lane & 15);
                    int col = warp_n * 32 + cb * 16 + ((lane >> 4) << 3);
                    uint32_t off = (uint32_t)(krow * STB + col) * 2;
                    uint32_t tmp[4];
                    ldsm_x4t(b_b + off, tmp);
                    bfr[2 * cb][0] = tmp[0]; bfr[2 * cb][1] = tmp[1];
                    bfr[2 * cb + 1][0] = tmp[2]; bfr[2 * cb + 1][1] = tmp[3];
                }
                #pragma unroll
                for (int mt = 0; mt < 4; mt++) {
                    int row = warp_m * 64 + mt * 16 + (lane & 15);
                    int col = kof + ((lane >> 4) << 3);
                    uint32_t off = (uint32_t)(row * STA + col) * 2;
                    uint32_t ah[4], al[4];
                    ldsm_x4(ah_b + off, ah);
                    ldsm_x4(al_b + off, al);
                    #pragma unroll
                    for (int nt = 0; nt < 4; nt++) {
                        mma_f16(acc[mt][nt], ah, bfr[nt]);
                        mma_f16(acc[mt][nt], al, bfr[nt]);
                    }
                }
            }
        }

        // ---- epilogue ----
        #pragma unroll
        for (int mt = 0; mt < 4; mt++) {
            int r0 = m0 + warp_m * 64 + mt * 16 + (lane >> 2);
            #pragma unroll
            for (int nt = 0; nt < 4; nt++) {
                int c0 = n0 + warp_n * 32 + nt * 8 + (lane & 3) * 2;
                float b0 = bias[c0], b1 = bias[c0 + 1];
                float v0 = acc[mt][nt][0] + b0, v1 = acc[mt][nt][1] + b1;
                float v2 = acc[mt][nt][2] + b0, v3 = acc[mt][nt][3] + b1;
                if (do_relu) {
                    v0 = fmaxf(v0, 0.f); v1 = fmaxf(v1, 0.f);
                    v2 = fmaxf(v2, 0.f); v3 = fmaxf(v3, 0.f);
                }
                if (resid) {
                    const float* rr0 = resid + (size_t)r0 * N + c0;
                    const float* rr1 = resid + (size_t)(r0 + 8) * N + c0;
                    v0 += rr0[0]; v1 += rr0[1];
                    v2 += rr1[0]; v3 += rr1[1];
                }
                if (Cf) {
                    *(float2*)(Cf + (size_t)r0 * N + c0)       = make_float2(v0, v1);
                    *(float2*)(Cf + (size_t)(r0 + 8) * N + c0) = make_float2(v2, v3);
                }
                if (Ch) {
                    __half h0, l0, h1, l1;
                    split1h(v0, h0, l0); split1h(v1, h1, l1);
                    *(uint32_t*)(Ch + (size_t)r0 * N + c0) = pack_h2(h0, h1);
                    *(uint32_t*)(Cl + (size_t)r0 * N + c0) = pack_h2(l0, l1);
                    split1h(v2, h0, l0); split1h(v3, h1, l1);
                    *(uint32_t*)(Ch + (size_t)(r0 + 8) * N + c0) = pack_h2(h0, h1);
                    *(uint32_t*)(Cl + (size_t)(r0 + 8) * N + c0) = pack_h2(l0, l1);
                }
            }
        }
        __syncthreads();
    }
}

// ================= persistent tensor-core squared-ReLU attention (fp16) =================
// S: Q/K fp16 hi/lo (3 passes). PV: P single fp16, V fp16 hi/lo (2 passes).
#define AQ  128
#define AKT 32
#define QPL_B  (AQ * 128)
#define KVPL_B (AKT * 128)
#define KVSTG_B (4 * KVPL_B)
#define ATTN_SMEM (2 * QPL_B + 3 * KVSTG_B)   // 81920 bytes

#define ASWZ(r, ch) ((uint32_t)((r) * 128 + ((((ch) ^ ((r) & 7))) << 4)))

__device__ __forceinline__ void attn_cp_kv(
    uint32_t sb, const __half* qh_g, const __half* ql_g,
    size_t rowbase, int tid)
{
    int r = tid >> 3, ch = tid & 7;
    size_t ko = rowbase + (size_t)r * QKVN + DMODEL + ch * 8;
    size_t vo = rowbase + (size_t)r * QKVN + 2 * DMODEL + ch * 8;
    uint32_t d = sb + ASWZ(r, ch);
    CP_ASYNC16(d,                qh_g + ko);
    CP_ASYNC16(d + KVPL_B,       ql_g + ko);
    CP_ASYNC16(d + 2 * KVPL_B,   qh_g + vo);
    CP_ASYNC16(d + 3 * KVPL_B,   ql_g + vo);
}

__global__ __launch_bounds__(256, 2) void attn_mma_kernel(
    const __half* __restrict__ qh_g, const __half* __restrict__ ql_g,
    __half* __restrict__ ch_g, __half* __restrict__ cl_g)
{
    extern __shared__ __half asmem[];
    const uint32_t smb = sptr(asmem);
    const uint32_t kvb = smb + 2 * QPL_B;

    const int tid = threadIdx.x, wid = tid >> 5, lane = tid & 31;
    const int nwi = (SEQ / AQ) * BATCH * NHEAD;   // 384

    for (int wi = blockIdx.x; wi < nwi; wi += gridDim.x) {
        const int q0 = (wi & 15) * AQ;
        const int bh_i = wi >> 4;
        const int b = bh_i / NHEAD, h = bh_i % NHEAD;
        const int hcol = h * DHEAD;
        const size_t bbase = (size_t)b * SEQ * QKVN + hcol;

        // group 0: Q planes
        #pragma unroll
        for (int i = 0; i < 4; i++) {
            int idx = tid + i * 256;
            int r = idx >> 3, ch = idx & 7;
            size_t o = bbase + (size_t)(q0 + r) * QKVN + ch * 8;
            uint32_t d = smb + ASWZ(r, ch);
            CP_ASYNC16(d, qh_g + o);
            CP_ASYNC16(d + QPL_B, ql_g + o);
        }
        CP_COMMIT();
        attn_cp_kv(kvb,            qh_g, ql_g, bbase, tid);
        CP_COMMIT();
        attn_cp_kv(kvb + KVSTG_B,  qh_g, ql_g, bbase + (size_t)AKT * QKVN, tid);
        CP_COMMIT();

        float out_acc[8][4];
        #pragma unroll
        for (int nt = 0; nt < 8; nt++)
            #pragma unroll
            for (int r = 0; r < 4; r++) out_acc[nt][r] = 0.f;

        const int ntiles = SEQ / AKT;    // 64
        for (int t = 0; t < ntiles; t++) {
            if (t + 2 <= ntiles) { CP_WAIT(1); } else { CP_WAIT(0); }
            __syncthreads();
            if (t + 2 < ntiles) {
                attn_cp_kv(kvb + ((t + 2) % 3) * KVSTG_B,
                           qh_g, ql_g, bbase + (size_t)(t + 2) * AKT * QKVN, tid);
                CP_COMMIT();
            }

            const uint32_t st = kvb + (t % 3) * KVSTG_B;
            const uint32_t kh_b = st, kl_b = st + KVPL_B;
            const uint32_t vh_b = st + 2 * KVPL_B, vl_b = st + 3 * KVPL_B;

            // ---- S = Q K^T (fp16 hi/lo, 3 passes) ----
            float s_acc[4][4];
            #pragma unroll
            for (int nt = 0; nt < 4; nt++)
                #pragma unroll
                for (int r = 0; r < 4; r++) s_acc[nt][r] = 0.f;

            #pragma unroll
            for (int ks = 0; ks < 4; ks++) {
                const int colc = 2 * ks + (lane >> 4);
                uint32_t qa_h[4], qa_l[4];
                {
                    int row = wid * 16 + (lane & 15);
                    uint32_t off = ASWZ(row, colc);
                    ldsm_x4(smb + off, qa_h);
                    ldsm_x4(smb + QPL_B + off, qa_l);
                }
                #pragma unroll
                for (int ntp = 0; ntp < 2; ntp++) {
                    int n = ntp * 16 + (lane & 15);
                    uint32_t off = ASWZ(n, colc);
                    uint32_t kb_h[4], kb_l[4];
                    ldsm_x4(kh_b + off, kb_h);
                    ldsm_x4(kl_b + off, kb_l);
                    uint32_t b0h[2] = {kb_h[0], kb_h[2]}, b1h[2] = {kb_h[1], kb_h[3]};
                    uint32_t b0l[2] = {kb_l[0], kb_l[2]}, b1l[2] = {kb_l[1], kb_l[3]};
                    mma_f16(s_acc[2 * ntp],     qa_h, b0h);
                    mma_f16(s_acc[2 * ntp],     qa_h, b0l);
                    mma_f16(s_acc[2 * ntp],     qa_l, b0h);
                    mma_f16(s_acc[2 * ntp + 1], qa_h, b1h);
                    mma_f16(s_acc[2 * ntp + 1], qa_h, b1l);
                    mma_f16(s_acc[2 * ntp + 1], qa_l, b1h);
                }
            }

            // ---- P = relu(s/8)^2 -> single fp16 A-fragments ----
            uint32_t pa[2][4];
            #pragma unroll
            for (int nt = 0; nt < 4; nt++) {
                float p[4];
                #pragma unroll
                for (int r = 0; r < 4; r++) {
                    float tt = fmaxf(s_acc[nt][r], 0.f);
                    p[r] = tt * tt * 0.015625f;
                }
                __half h0 = __float2half_rn(p[0]), h1 = __float2half_rn(p[1]);
                __half h2 = __float2half_rn(p[2]), h3 = __float2half_rn(p[3]);
                int kt2 = nt >> 1;
                int base_r = (nt & 1) ? 2 : 0;
                pa[kt2][base_r]     = pack_h2(h0, h1);
                pa[kt2][base_r + 1] = pack_h2(h2, h3);
            }

            // ---- ctx += P V (fp16, 2 passes) ----
            #pragma unroll
            for (int kt2 = 0; kt2 < 2; kt2++) {
                int krow = kt2 * 16 + (lane & 15);
                #pragma unroll
                for (int cb = 0; cb < 4; cb++) {
                    int colc = 2 * cb + (lane >> 4);
                    uint32_t off = ASWZ(krow, colc);
                    uint32_t vbh[4], vbl[4];
                    ldsm_x4t(vh_b + off, vbh);
                    ldsm_x4t(vl_b + off, vbl);
                    int nt = cb * 2;
                    uint32_t b0h[2] = {vbh[0], vbh[1]}, b1h[2] = {vbh[2], vbh[3]};
                    uint32_t b0l[2] = {vbl[0], vbl[1]}, b1l[2] = {vbl[2], vbl[3]};
                    mma_f16(out_acc[nt],     pa[kt2], b0h);
                    mma_f16(out_acc[nt],     pa[kt2], b0l);
                    mma_f16(out_acc[nt + 1], pa[kt2], b1h);
                    mma_f16(out_acc[nt + 1], pa[kt2], b1l);
                }
            }
        }

        // ---- epilogue: ctx fp16 hi/lo planes ----
        #pragma unroll
        for (int nt = 0; nt < 8; nt++) {
            int q = q0 + wid * 16 + (lane >> 2);
            int c = hcol + nt * 8 + (lane & 3) * 2;
            __half h0, l0, h1, l1;
            split1h(out_acc[nt][0], h0, l0); split1h(out_acc[nt][1], h1, l1);
            *(uint32_t*)(ch_g + ((size_t)b * SEQ + q) * DMODEL + c) = pack_h2(h0, h1);
            *(uint32_t*)(cl_g + ((size_t)b * SEQ + q) * DMODEL + c) = pack_h2(l0, l1);
            split1h(out_acc[nt][2], h0, l0); split1h(out_acc[nt][3], h1, l1);
            *(uint32_t*)(ch_g + ((size_t)b * SEQ + q + 8) * DMODEL + c) = pack_h2(h0, h1);
            *(uint32_t*)(cl_g + ((size_t)b * SEQ + q + 8) * DMODEL + c) = pack_h2(l0, l1);
        }
        __syncthreads();   // next item's Q load must not race final S reads
    }
}

// ================= launch =================
extern "C" void kernel_launch(void* const* d_in, const int* in_sizes, int n_in,
                              void* d_out, int out_size)
{
    const float* x      = (const float*)d_in[0];
    const float* ln1_w  = (const float*)d_in[1];
    const float* W_attn = (const float*)d_in[2];
    const float* b_attn = (const float*)d_in[3];
    const float* W_proj = (const float*)d_in[4];
    const float* b_proj = (const float*)d_in[5];
    const float* ln2_w  = (const float*)d_in[6];
    const float* W_fc1  = (const float*)d_in[7];
    const float* b_fc1  = (const float*)d_in[8];
    const float* W_fc2  = (const float*)d_in[9];
    const float* b_fc2  = (const float*)d_in[10];
    float* out = (float*)d_out;

    __half *wa, *wp, *w1, *w2;
    __half *hh, *hl, *qh, *ql, *ch, *cl, *f1h, *f1l;
    float* x1;
    cudaGetSymbolAddress((void**)&wa, g_wattn);
    cudaGetSymbolAddress((void**)&wp, g_wproj);
    cudaGetSymbolAddress((void**)&w1, g_wfc1);
    cudaGetSymbolAddress((void**)&w2, g_wfc2);
    cudaGetSymbolAddress((void**)&hh, g_hh);   cudaGetSymbolAddress((void**)&hl, g_hl);
    cudaGetSymbolAddress((void**)&qh, g_qh);   cudaGetSymbolAddress((void**)&ql, g_ql);
    cudaGetSymbolAddress((void**)&ch, g_ch);   cudaGetSymbolAddress((void**)&cl, g_cl);
    cudaGetSymbolAddress((void**)&f1h, g_f1h); cudaGetSymbolAddress((void**)&f1l, g_f1l);
    cudaGetSymbolAddress((void**)&x1, g_x1);

    cudaFuncSetAttribute(gemm_mma_kernel, cudaFuncAttributeMaxDynamicSharedMemorySize, GEMM_SMEM);
    cudaFuncSetAttribute(attn_mma_kernel, cudaFuncAttributeMaxDynamicSharedMemorySize, ATTN_SMEM);

    convert_all_kernel<<<(CV_TOT + 255) / 256, 256>>>(
        W_attn, wa, W_proj, wp, W_fc1, w1, W_fc2, w2);

    // h = rmsnorm(x, ln1_w) -> planes
    rmsnorm_kernel<<<ROWS, 256>>>(x, ln1_w, hh, hl);
    // qkv = h @ W_attn + b_attn -> planes
    gemm_mma_kernel<<<PGRID, 256, GEMM_SMEM>>>(
        hh, hl, wa, b_attn, nullptr, nullptr, qh, ql, ROWS, QKVN, DMODEL, 0);
    // ctx = attention(qkv) -> planes
    attn_mma_kernel<<<PGRID, 256, ATTN_SMEM>>>(qh, ql, ch, cl);
    // x1 = x + ctx @ W_proj + b_proj (fp32)
    gemm_mma_kernel<<<PGRID, 256, GEMM_SMEM>>>(
        ch, cl, wp, b_proj, x, x1, nullptr, nullptr, ROWS, DMODEL, DMODEL, 0);
    // h = rmsnorm(x1, ln2_w) -> planes
    rmsnorm_kernel<<<ROWS, 256>>>(x1, ln2_w, hh, hl);
    // fc1 = relu(h @ W_fc1 + b_fc1) -> planes
    gemm_mma_kernel<<<PGRID, 256, GEMM_SMEM>>>(
        hh, hl, w1, b_fc1, nullptr, nullptr, f1h, f1l, ROWS, HID, DMODEL, 1);
    // out = x1 + fc1 @ W_fc2 + b_fc2 (fp32)
    gemm_mma_kernel<<<PGRID, 256, GEMM_SMEM>>>(
        f1h, f1l, w2, b_fc2, x1, out, nullptr, nullptr, ROWS, DMODEL, HID, 0);
}

// round 16
// speedup vs baseline: 4.1988x; 1.0776x over previous
#include <cuda_runtime.h>
#include <cuda_bf16.h>
#include <cuda_fp16.h>
#include <cstdint>

// Problem constants
#define BATCH 2
#define SEQ   2048
#define DMODEL 768
#define NHEAD 12
#define DHEAD 64
#define HID   1536
#define ROWS  (BATCH * SEQ)          // 4096
#define QKVN  (3 * DMODEL)           // 2304
#define EPS   1e-6f
#define PGRID 296                    // 2 CTAs x 148 SMs

// ---------------- scratch (__device__ globals; no allocs allowed) ----------------
__device__ alignas(16) __half g_wattn[DMODEL * QKVN];
__device__ alignas(16) __half g_wproj[DMODEL * DMODEL];
__device__ alignas(16) __half g_wfc1[DMODEL * HID];
__device__ alignas(16) __half g_wfc2[HID * DMODEL];
__device__ alignas(16) __half g_hh[ROWS * DMODEL], g_hl[ROWS * DMODEL];
__device__ alignas(16) __half g_qh[ROWS * QKVN], g_ql[ROWS * QKVN];
__device__ alignas(16) __half g_ch[ROWS * DMODEL], g_cl[ROWS * DMODEL];
__device__ alignas(16) __half g_f1h[ROWS * HID], g_f1l[ROWS * HID];
__device__ float g_x1[ROWS * DMODEL];

// ================= helpers =================
__device__ __forceinline__ uint32_t sptr(const void* p) {
    return (uint32_t)__cvta_generic_to_shared(p);
}
__device__ __forceinline__ void ldsm_x4(uint32_t addr, uint32_t* r) {
    asm volatile("ldmatrix.sync.aligned.m8n8.x4.shared.b16 {%0,%1,%2,%3}, [%4];"
                 : "=r"(r[0]), "=r"(r[1]), "=r"(r[2]), "=r"(r[3]) : "r"(addr));
}
__device__ __forceinline__ void ldsm_x4t(uint32_t addr, uint32_t* r) {
    asm volatile("ldmatrix.sync.aligned.m8n8.x4.trans.shared.b16 {%0,%1,%2,%3}, [%4];"
                 : "=r"(r[0]), "=r"(r[1]), "=r"(r[2]), "=r"(r[3]) : "r"(addr));
}
__device__ __forceinline__ void mma_f16(float* c, const uint32_t* a, const uint32_t* b) {
    asm volatile(
        "mma.sync.aligned.m16n8k16.row.col.f32.f16.f16.f32 "
        "{%0,%1,%2,%3}, {%4,%5,%6,%7}, {%8,%9}, {%0,%1,%2,%3};"
        : "+f"(c[0]), "+f"(c[1]), "+f"(c[2]), "+f"(c[3])
        : "r"(a[0]), "r"(a[1]), "r"(a[2]), "r"(a[3]), "r"(b[0]), "r"(b[1]));
}
__device__ __forceinline__ uint32_t pack_h2(__half a, __half b) {
    return ((uint32_t)__half_as_ushort(b) << 16) | (uint32_t)__half_as_ushort(a);
}
__device__ __forceinline__ void split1h(float v, __half& h, __half& l) {
    h = __float2half_rn(v);
    l = __float2half_rn(v - __half2float(h));
}

#define CP_ASYNC16(dst, src) \
    asm volatile("cp.async.cg.shared.global [%0], [%1], 16;" :: "r"(dst), "l"(src) : "memory")
#define CP_COMMIT() asm volatile("cp.async.commit_group;" ::: "memory")
#define CP_WAIT(N)  asm volatile("cp.async.wait_group %0;" :: "n"(N) : "memory")

// ================= merged weight conversion: fp32 -> single fp16 =================
#define CV_N0 (DMODEL * QKVN / 4)
#define CV_N1 (DMODEL * DMODEL / 4)
#define CV_N2 (DMODEL * HID / 4)
#define CV_N3 (HID * DMODEL / 4)
#define CV_TOT (CV_N0 + CV_N1 + CV_N2 + CV_N3)

__global__ __launch_bounds__(256) void convert_all_kernel(
    const float* __restrict__ s0, __half* __restrict__ h0,
    const float* __restrict__ s1, __half* __restrict__ h1,
    const float* __restrict__ s2, __half* __restrict__ h2,
    const float* __restrict__ s3, __half* __restrict__ h3)
{
    int i = blockIdx.x * 256 + threadIdx.x;
    const float* s; __half* h;
    if (i < CV_N0)                     { s = s0; h = h0; }
    else if (i < CV_N0 + CV_N1)        { s = s1; h = h1; i -= CV_N0; }
    else if (i < CV_N0 + CV_N1 + CV_N2){ s = s2; h = h2; i -= CV_N0 + CV_N1; }
    else if (i < CV_TOT)               { s = s3; h = h3; i -= CV_N0 + CV_N1 + CV_N2; }
    else return;
    float4 v = ((const float4*)s)[i];
    uint2 o;
    o.x = pack_h2(__float2half_rn(v.x), __float2half_rn(v.y));
    o.y = pack_h2(__float2half_rn(v.z), __float2half_rn(v.w));
    ((uint2*)h)[i] = o;
}

// ================= RMSNorm: fp32 in, fp16 hi/lo planes out =================
__global__ __launch_bounds__(256) void rmsnorm_kernel(
    const float* __restrict__ x, const float* __restrict__ w,
    __half* __restrict__ oh, __half* __restrict__ ol)
{
    const int row = blockIdx.x;
    const int tid = threadIdx.x;
    const float* xr = x + (size_t)row * DMODEL;
    float v0 = xr[tid], v1 = xr[tid + 256], v2 = xr[tid + 512];
    float s = v0 * v0 + v1 * v1 + v2 * v2;
    #pragma unroll
    for (int o = 16; o > 0; o >>= 1) s += __shfl_xor_sync(0xFFFFFFFF, s, o);
    __shared__ float wsum[8];
    if ((tid & 31) == 0) wsum[tid >> 5] = s;
    __syncthreads();
    if (tid < 8) {
        float t = wsum[tid];
        #pragma unroll
        for (int o = 4; o > 0; o >>= 1) t += __shfl_xor_sync(0xFF, t, o);
        if (tid == 0) wsum[0] = t;
    }
    __syncthreads();
    const float scale = rsqrtf(wsum[0] * (1.0f / DMODEL) + EPS);
    size_t base = (size_t)row * DMODEL;
    __half h, l;
    split1h(v0 * scale * w[tid], h, l);       oh[base + tid] = h;       ol[base + tid] = l;
    split1h(v1 * scale * w[tid + 256], h, l); oh[base + tid + 256] = h; ol[base + tid + 256] = l;
    split1h(v2 * scale * w[tid + 512], h, l); oh[base + tid + 512] = h; ol[base + tid + 512] = l;
}

// ================= persistent tensor-core GEMM (cp.async 3-stage, fp16) =================
#define BM 128
#define BN 128
#define BK 32
#define STA 40
#define STB 136
#define ASZ (BM * STA)
#define BSZ (BK * STB)
#define STAGE_H (2 * ASZ + BSZ)
#define GEMM_SMEM (3 * STAGE_H * 2)    // 87552 bytes

__device__ __forceinline__ void gemm_cp_stage(
    uint32_t sb, const __half* Ah_g, const __half* Al_g, const __half* B_g,
    int m0, int n0, int k0, int K, int N, int tid)
{
    #pragma unroll
    for (int i = 0; i < 2; i++) {
        int idx = tid + i * 256;
        int row = idx >> 2, ch = idx & 3;
        uint32_t d = sb + (uint32_t)(row * STA + ch * 8) * 2;
        size_t o = (size_t)(m0 + row) * K + k0 + ch * 8;
        CP_ASYNC16(d, Ah_g + o);
        CP_ASYNC16(d + ASZ * 2, Al_g + o);
    }
    #pragma unroll
    for (int i = 0; i < 2; i++) {
        int idx = tid + i * 256;
        int row = idx >> 4, ch = idx & 15;
        uint32_t d = sb + (uint32_t)(2 * ASZ + row * STB + ch * 8) * 2;
        size_t o = (size_t)(k0 + row) * N + n0 + ch * 8;
        CP_ASYNC16(d, B_g + o);
    }
}

__global__ __launch_bounds__(256, 2) void gemm_mma_kernel(
    const __half* __restrict__ Ah_g, const __half* __restrict__ Al_g,
    const __half* __restrict__ B_g,
    const float* __restrict__ bias, const float* __restrict__ resid,
    float* __restrict__ Cf, __half* __restrict__ Ch, __half* __restrict__ Cl,
    int M, int N, int K, int do_relu)
{
    extern __shared__ __half gsm[];
    const uint32_t smb = sptr(gsm);
    const int tid = threadIdx.x, wid = tid >> 5, lane = tid & 31;
    const int warp_m = wid >> 2, warp_n = wid & 3;
    const int nxt = N / BN;
    const int ntot = (M / BM) * nxt;
    const int ntiles = K / BK;

    for (int tile = blockIdx.x; tile < ntot; tile += gridDim.x) {
        const int m0 = (tile / nxt) * BM, n0 = (tile % nxt) * BN;

        float acc[4][4][4];
        #pragma unroll
        for (int i = 0; i < 4; i++)
            #pragma unroll
            for (int j = 0; j < 4; j++)
                #pragma unroll
                for (int r = 0; r < 4; r++) acc[i][j][r] = 0.f;

        gemm_cp_stage(smb, Ah_g, Al_g, B_g, m0, n0, 0, K, N, tid);
        CP_COMMIT();
        gemm_cp_stage(smb + STAGE_H * 2, Ah_g, Al_g, B_g, m0, n0, BK, K, N, tid);
        CP_COMMIT();

        for (int t = 0; t < ntiles; t++) {
            if (t + 2 <= ntiles) { CP_WAIT(1); } else { CP_WAIT(0); }
            __syncthreads();
            if (t + 2 < ntiles) {
                gemm_cp_stage(smb + ((t + 2) % 3) * STAGE_H * 2,
                              Ah_g, Al_g, B_g, m0, n0, (t + 2) * BK, K, N, tid);
                CP_COMMIT();
            }

            const uint32_t st = smb + (t % 3) * STAGE_H * 2;
            const uint32_t ah_b = st, al_b = st + ASZ * 2;
            const uint32_t b_b = st + 2 * ASZ * 2;

            #pragma unroll
            for (int ks = 0; ks < 2; ks++) {
                const int kof = ks * 16;
                uint32_t bfr[4][2];
                #pragma unroll
                for (int cb = 0; cb < 2; cb++) {
                    int krow = kof + (lane & 15);
                    int col = warp_n * 32 + cb * 16 + ((lane >> 4) << 3);
                    uint32_t off = (uint32_t)(krow * STB + col) * 2;
                    uint32_t tmp[4];
                    ldsm_x4t(b_b + off, tmp);
                    bfr[2 * cb][0] = tmp[0]; bfr[2 * cb][1] = tmp[1];
                    bfr[2 * cb + 1][0] = tmp[2]; bfr[2 * cb + 1][1] = tmp[3];
                }
                #pragma unroll
                for (int mt = 0; mt < 4; mt++) {
                    int row = warp_m * 64 + mt * 16 + (lane & 15);
                    int col = kof + ((lane >> 4) << 3);
                    uint32_t off = (uint32_t)(row * STA + col) * 2;
                    uint32_t ah[4], al[4];
                    ldsm_x4(ah_b + off, ah);
                    ldsm_x4(al_b + off, al);
                    #pragma unroll
                    for (int nt = 0; nt < 4; nt++) {
                        mma_f16(acc[mt][nt], ah, bfr[nt]);
                        mma_f16(acc[mt][nt], al, bfr[nt]);
                    }
                }
            }
        }

        // ---- epilogue ----
        #pragma unroll
        for (int mt = 0; mt < 4; mt++) {
            int r0 = m0 + warp_m * 64 + mt * 16 + (lane >> 2);
            #pragma unroll
            for (int nt = 0; nt < 4; nt++) {
                int c0 = n0 + warp_n * 32 + nt * 8 + (lane & 3) * 2;
                float b0 = bias[c0], b1 = bias[c0 + 1];
                float v0 = acc[mt][nt][0] + b0, v1 = acc[mt][nt][1] + b1;
                float v2 = acc[mt][nt][2] + b0, v3 = acc[mt][nt][3] + b1;
                if (do_relu) {
                    v0 = fmaxf(v0, 0.f); v1 = fmaxf(v1, 0.f);
                    v2 = fmaxf(v2, 0.f); v3 = fmaxf(v3, 0.f);
                }
                if (resid) {
                    const float* rr0 = resid + (size_t)r0 * N + c0;
                    const float* rr1 = resid + (size_t)(r0 + 8) * N + c0;
                    v0 += rr0[0]; v1 += rr0[1];
                    v2 += rr1[0]; v3 += rr1[1];
                }
                if (Cf) {
                    *(float2*)(Cf + (size_t)r0 * N + c0)       = make_float2(v0, v1);
                    *(float2*)(Cf + (size_t)(r0 + 8) * N + c0) = make_float2(v2, v3);
                }
                if (Ch) {
                    __half h0, l0, h1, l1;
                    split1h(v0, h0, l0); split1h(v1, h1, l1);
                    *(uint32_t*)(Ch + (size_t)r0 * N + c0) = pack_h2(h0, h1);
                    *(uint32_t*)(Cl + (size_t)r0 * N + c0) = pack_h2(l0, l1);
                    split1h(v2, h0, l0); split1h(v3, h1, l1);
                    *(uint32_t*)(Ch + (size_t)(r0 + 8) * N + c0) = pack_h2(h0, h1);
                    *(uint32_t*)(Cl + (size_t)(r0 + 8) * N + c0) = pack_h2(l0, l1);
                }
            }
        }
        __syncthreads();
    }
}

// ================= persistent tensor-core squared-ReLU attention (fp16) =================
// S: Q fp16 hi/lo x K single fp16 (2 passes). PV: P single fp16, V fp16 hi/lo (2 passes).
// KV stage: 3 planes (K, Vh, Vl).
#define AQ  128
#define AKT 32
#define QPL_B  (AQ * 128)              // 16384 bytes per Q plane
#define KVPL_B (AKT * 128)             // 4096 bytes per plane
#define KVSTG_B (3 * KVPL_B)           // 12288 bytes per stage
#define ATTN_SMEM (2 * QPL_B + 3 * KVSTG_B)   // 69632 bytes

#define ASWZ(r, ch) ((uint32_t)((r) * 128 + ((((ch) ^ ((r) & 7))) << 4)))

__device__ __forceinline__ void attn_cp_kv(
    uint32_t sb, const __half* qh_g, const __half* ql_g,
    size_t rowbase, int tid)
{
    int r = tid >> 3, ch = tid & 7;
    size_t ko = rowbase + (size_t)r * QKVN + DMODEL + ch * 8;
    size_t vo = rowbase + (size_t)r * QKVN + 2 * DMODEL + ch * 8;
    uint32_t d = sb + ASWZ(r, ch);
    CP_ASYNC16(d,                qh_g + ko);   // K (single)
    CP_ASYNC16(d + KVPL_B,       qh_g + vo);   // V hi
    CP_ASYNC16(d + 2 * KVPL_B,   ql_g + vo);   // V lo
}

__global__ __launch_bounds__(256, 2) void attn_mma_kernel(
    const __half* __restrict__ qh_g, const __half* __restrict__ ql_g,
    __half* __restrict__ ch_g, __half* __restrict__ cl_g)
{
    extern __shared__ __half asmem[];
    const uint32_t smb = sptr(asmem);
    const uint32_t kvb = smb + 2 * QPL_B;

    const int tid = threadIdx.x, wid = tid >> 5, lane = tid & 31;
    const int nwi = (SEQ / AQ) * BATCH * NHEAD;   // 384

    for (int wi = blockIdx.x; wi < nwi; wi += gridDim.x) {
        const int q0 = (wi & 15) * AQ;
        const int bh_i = wi >> 4;
        const int b = bh_i / NHEAD, h = bh_i % NHEAD;
        const int hcol = h * DHEAD;
        const size_t bbase = (size_t)b * SEQ * QKVN + hcol;

        // group 0: Q planes
        #pragma unroll
        for (int i = 0; i < 4; i++) {
            int idx = tid + i * 256;
            int r = idx >> 3, ch = idx & 7;
            size_t o = bbase + (size_t)(q0 + r) * QKVN + ch * 8;
            uint32_t d = smb + ASWZ(r, ch);
            CP_ASYNC16(d, qh_g + o);
            CP_ASYNC16(d + QPL_B, ql_g + o);
        }
        CP_COMMIT();
        attn_cp_kv(kvb,            qh_g, ql_g, bbase, tid);
        CP_COMMIT();
        attn_cp_kv(kvb + KVSTG_B,  qh_g, ql_g, bbase + (size_t)AKT * QKVN, tid);
        CP_COMMIT();

        float out_acc[8][4];
        #pragma unroll
        for (int nt = 0; nt < 8; nt++)
            #pragma unroll
            for (int r = 0; r < 4; r++) out_acc[nt][r] = 0.f;

        const int ntiles = SEQ / AKT;    // 64
        for (int t = 0; t < ntiles; t++) {
            if (t + 2 <= ntiles) { CP_WAIT(1); } else { CP_WAIT(0); }
            __syncthreads();
            if (t + 2 < ntiles) {
                attn_cp_kv(kvb + ((t + 2) % 3) * KVSTG_B,
                           qh_g, ql_g, bbase + (size_t)(t + 2) * AKT * QKVN, tid);
                CP_COMMIT();
            }

            const uint32_t st = kvb + (t % 3) * KVSTG_B;
            const uint32_t k_b = st;
            const uint32_t vh_b = st + KVPL_B, vl_b = st + 2 * KVPL_B;

            // ---- S = Q K^T (Q hi/lo x K single, 2 passes) ----
            float s_acc[4][4];
            #pragma unroll
            for (int nt = 0; nt < 4; nt++)
                #pragma unroll
                for (int r = 0; r < 4; r++) s_acc[nt][r] = 0.f;

            #pragma unroll
            for (int ks = 0; ks < 4; ks++) {
                const int colc = 2 * ks + (lane >> 4);
                uint32_t qa_h[4], qa_l[4];
                {
                    int row = wid * 16 + (lane & 15);
                    uint32_t off = ASWZ(row, colc);
                    ldsm_x4(smb + off, qa_h);
                    ldsm_x4(smb + QPL_B + off, qa_l);
                }
                #pragma unroll
                for (int ntp = 0; ntp < 2; ntp++) {
                    int n = ntp * 16 + (lane & 15);
                    uint32_t off = ASWZ(n, colc);
                    uint32_t kb[4];
                    ldsm_x4(k_b + off, kb);
                    uint32_t b0[2] = {kb[0], kb[2]}, b1[2] = {kb[1], kb[3]};
                    mma_f16(s_acc[2 * ntp],     qa_h, b0);
                    mma_f16(s_acc[2 * ntp],     qa_l, b0);
                    mma_f16(s_acc[2 * ntp + 1], qa_h, b1);
                    mma_f16(s_acc[2 * ntp + 1], qa_l, b1);
                }
            }

            // ---- P = relu(s/8)^2 -> single fp16 A-fragments ----
            uint32_t pa[2][4];
            #pragma unroll
            for (int nt = 0; nt < 4; nt++) {
                float p[4];
                #pragma unroll
                for (int r = 0; r < 4; r++) {
                    float tt = fmaxf(s_acc[nt][r], 0.f);
                    p[r] = tt * tt * 0.015625f;
                }
                __half h0 = __float2half_rn(p[0]), h1 = __float2half_rn(p[1]);
                __half h2 = __float2half_rn(p[2]), h3 = __float2half_rn(p[3]);
                int kt2 = nt >> 1;
                int base_r = (nt & 1) ? 2 : 0;
                pa[kt2][base_r]     = pack_h2(h0, h1);
                pa[kt2][base_r + 1] = pack_h2(h2, h3);
            }

            // ---- ctx += P V (fp16, 2 passes) ----
            #pragma unroll
            for (int kt2 = 0; kt2 < 2; kt2++) {
                int krow = kt2 * 16 + (lane & 15);
                #pragma unroll
                for (int cb = 0; cb < 4; cb++) {
                    int colc = 2 * cb + (lane >> 4);
                    uint32_t off = ASWZ(krow, colc);
                    uint32_t vbh[4], vbl[4];
                    ldsm_x4t(vh_b + off, vbh);
                    ldsm_x4t(vl_b + off, vbl);
                    int nt = cb * 2;
                    uint32_t b0h[2] = {vbh[0], vbh[1]}, b1h[2] = {vbh[2], vbh[3]};
                    uint32_t b0l[2] = {vbl[0], vbl[1]}, b1l[2] = {vbl[2], vbl[3]};
                    mma_f16(out_acc[nt],     pa[kt2], b0h);
                    mma_f16(out_acc[nt],     pa[kt2], b0l);
                    mma_f16(out_acc[nt + 1], pa[kt2], b1h);
                    mma_f16(out_acc[nt + 1], pa[kt2], b1l);
                }
            }
        }

        // ---- epilogue: ctx fp16 hi/lo planes ----
        #pragma unroll
        for (int nt = 0; nt < 8; nt++) {
            int q = q0 + wid * 16 + (lane >> 2);
            int c = hcol + nt * 8 + (lane & 3) * 2;
            __half h0, l0, h1, l1;
            split1h(out_acc[nt][0], h0, l0); split1h(out_acc[nt][1], h1, l1);
            *(uint32_t*)(ch_g + ((size_t)b * SEQ + q) * DMODEL + c) = pack_h2(h0, h1);
            *(uint32_t*)(cl_g + ((size_t)b * SEQ + q) * DMODEL + c) = pack_h2(l0, l1);
            split1h(out_acc[nt][2], h0, l0); split1h(out_acc[nt][3], h1, l1);
            *(uint32_t*)(ch_g + ((size_t)b * SEQ + q + 8) * DMODEL + c) = pack_h2(h0, h1);
            *(uint32_t*)(cl_g + ((size_t)b * SEQ + q + 8) * DMODEL + c) = pack_h2(l0, l1);
        }
        __syncthreads();   // next item's Q load must not race final S reads
    }
}

// ================= launch =================
extern "C" void kernel_launch(void* const* d_in, const int* in_sizes, int n_in,
                              void* d_out, int out_size)
{
    const float* x      = (const float*)d_in[0];
    const float* ln1_w  = (const float*)d_in[1];
    const float* W_attn = (const float*)d_in[2];
    const float* b_attn = (const float*)d_in[3];
    const float* W_proj = (const float*)d_in[4];
    const float* b_proj = (const float*)d_in[5];
    const float* ln2_w  = (const float*)d_in[6];
    const float* W_fc1  = (const float*)d_in[7];
    const float* b_fc1  = (const float*)d_in[8];
    const float* W_fc2  = (const float*)d_in[9];
    const float* b_fc2  = (const float*)d_in[10];
    float* out = (float*)d_out;

    __half *wa, *wp, *w1, *w2;
    __half *hh, *hl, *qh, *ql, *ch, *cl, *f1h, *f1l;
    float* x1;
    cudaGetSymbolAddress((void**)&wa, g_wattn);
    cudaGetSymbolAddress((void**)&wp, g_wproj);
    cudaGetSymbolAddress((void**)&w1, g_wfc1);
    cudaGetSymbolAddress((void**)&w2, g_wfc2);
    cudaGetSymbolAddress((void**)&hh, g_hh);   cudaGetSymbolAddress((void**)&hl, g_hl);
    cudaGetSymbolAddress((void**)&qh, g_qh);   cudaGetSymbolAddress((void**)&ql, g_ql);
    cudaGetSymbolAddress((void**)&ch, g_ch);   cudaGetSymbolAddress((void**)&cl, g_cl);
    cudaGetSymbolAddress((void**)&f1h, g_f1h); cudaGetSymbolAddress((void**)&f1l, g_f1l);
    cudaGetSymbolAddress((void**)&x1, g_x1);

    cudaFuncSetAttribute(gemm_mma_kernel, cudaFuncAttributeMaxDynamicSharedMemorySize, GEMM_SMEM);
    cudaFuncSetAttribute(attn_mma_kernel, cudaFuncAttributeMaxDynamicSharedMemorySize, ATTN_SMEM);

    convert_all_kernel<<<(CV_TOT + 255) / 256, 256>>>(
        W_attn, wa, W_proj, wp, W_fc1, w1, W_fc2, w2);

    // h = rmsnorm(x, ln1_w) -> planes
    rmsnorm_kernel<<<ROWS, 256>>>(x, ln1_w, hh, hl);
    // qkv = h @ W_attn + b_attn -> planes
    gemm_mma_kernel<<<PGRID, 256, GEMM_SMEM>>>(
        hh, hl, wa, b_attn, nullptr, nullptr, qh, ql, ROWS, QKVN, DMODEL, 0);
    // ctx = attention(qkv) -> planes
    attn_mma_kernel<<<PGRID, 256, ATTN_SMEM>>>(qh, ql, ch, cl);
    // x1 = x + ctx @ W_proj + b_proj (fp32)
    gemm_mma_kernel<<<PGRID, 256, GEMM_SMEM>>>(
        ch, cl, wp, b_proj, x, x1, nullptr, nullptr, ROWS, DMODEL, DMODEL, 0);
    // h = rmsnorm(x1, ln2_w) -> planes
    rmsnorm_kernel<<<ROWS, 256>>>(x1, ln2_w, hh, hl);
    // fc1 = relu(h @ W_fc1 + b_fc1) -> planes
    gemm_mma_kernel<<<PGRID, 256, GEMM_SMEM>>>(
        hh, hl, w1, b_fc1, nullptr, nullptr, f1h, f1l, ROWS, HID, DMODEL, 1);
    // out = x1 + fc1 @ W_fc2 + b_fc2 (fp32)
    gemm_mma_kernel<<<PGRID, 256, GEMM_SMEM>>>(
        f1h, f1l, w2, b_fc2, x1, out, nullptr, nullptr, ROWS, DMODEL, HID, 0);
}